// round 2
// baseline (speedup 1.0000x reference)
#include <cuda_runtime.h>
#include <cstdint>

// Problem constants (guarded against actual sizes at launch)
#define NMAX 50000
#define EMAX 800000

// ---------------- scratch (device globals; no allocation allowed) ----------
__device__ float g_q [NMAX * 512];
__device__ float g_k [NMAX * 512];
__device__ float g_v [NMAX * 512];
__device__ float g_h0[NMAX * 512];
__device__ float g_h1[NMAX * 512];
__device__ int   g_rowptr[NMAX + 1];
__device__ int   g_cnt[NMAX];
__device__ int   g_cur[NMAX];
__device__ int   g_srcs[EMAX];
__device__ int   g_is64;

// ---------------- edge dtype detection (int32 vs int64) ----------------
// Values are < 50000 < 2^31. If the buffer is int64, every odd 32-bit word is 0.
// If it's int32, odd words are random edge values (all-zero prob ~ (1/N)^128).
__global__ void detect_kernel(const int* __restrict__ w) {
    int odd_nonzero = 0;
    for (int i = 0; i < 128; i++) odd_nonzero += (w[2 * i + 1] != 0);
    g_is64 = (odd_nonzero == 0) ? 1 : 0;
}

__device__ __forceinline__ int edge_at(const void* ei, long long idx, int is64) {
    return is64 ? (int)((const long long*)ei)[idx] : ((const int*)ei)[idx];
}

// ---------------- CSR build ----------------
__global__ void zero_int_kernel(int* __restrict__ p, int n) {
    int i = blockIdx.x * blockDim.x + threadIdx.x;
    if (i < n) p[i] = 0;
}

__global__ void hist_kernel(const void* __restrict__ ei, int* __restrict__ cnt, int E) {
    int e = blockIdx.x * blockDim.x + threadIdx.x;
    if (e < E) {
        int d = edge_at(ei, (long long)E + e, g_is64);   // dst row
        atomicAdd(&cnt[d], 1);
    }
}

__global__ void scan_kernel(const int* __restrict__ cnt, int* __restrict__ rowptr,
                            int* __restrict__ cur, int n) {
    __shared__ int part[1024];
    const int t = threadIdx.x;
    const int chunk = (n + 1023) >> 10;
    int b = t * chunk; if (b > n) b = n;
    int e = b + chunk; if (e > n) e = n;
    int s = 0;
    for (int i = b; i < e; i++) s += cnt[i];
    part[t] = s;
    __syncthreads();
    if (t == 0) {
        int a = 0;
        for (int i = 0; i < 1024; i++) { int v = part[i]; part[i] = a; a += v; }
    }
    __syncthreads();
    int off = part[t];
    for (int i = b; i < e; i++) { rowptr[i] = off; cur[i] = off; off += cnt[i]; }
    if (t == 1023) rowptr[n] = off;   // == E
}

__global__ void scatter_kernel(const void* __restrict__ ei, int* __restrict__ cur,
                               int* __restrict__ srcs, int E) {
    int e = blockIdx.x * blockDim.x + threadIdx.x;
    if (e < E) {
        const int is64 = g_is64;
        int d = edge_at(ei, (long long)E + e, is64);     // dst row
        int p = atomicAdd(&cur[d], 1);
        srcs[p] = edge_at(ei, e, is64);                  // src row
    }
}

// ---------------- SGEMM + bias: C[N,M] = A[N,K] @ W[K,M] + b ----------------
template<int BM, int BN, int BK, int TM, int TN>
__global__ void __launch_bounds__(256)
sgemm_bias_kernel(const float* __restrict__ A, const float* __restrict__ W,
                  const float* __restrict__ bias, float* __restrict__ C,
                  int N, int K, int M)
{
    __shared__ float As[BK][BM + 4];
    __shared__ float Bs[BK][BN];
    const int tid  = threadIdx.x;
    const int brow = blockIdx.y * BM;
    const int bcol = blockIdx.x * BN;
    constexpr int TCOLS = BN / TN;
    const int ty = tid / TCOLS;
    const int tx = tid % TCOLS;

    float acc[TM][TN];
#pragma unroll
    for (int i = 0; i < TM; i++)
#pragma unroll
        for (int j = 0; j < TN; j++) acc[i][j] = 0.f;

    constexpr int A4 = BM * BK / 4;
    constexpr int B4 = BK * BN / 4;

    for (int k0 = 0; k0 < K; k0 += BK) {
        // A tile -> As (transposed), vectorized over K (K % 8 == 0 here)
        for (int idx = tid; idx < A4; idx += 256) {
            int r  = idx / (BK / 4);
            int c4 = (idx % (BK / 4)) * 4;
            float4 av = make_float4(0.f, 0.f, 0.f, 0.f);
            int gr = brow + r;
            if (gr < N) av = *reinterpret_cast<const float4*>(A + (size_t)gr * K + k0 + c4);
            As[c4 + 0][r] = av.x; As[c4 + 1][r] = av.y;
            As[c4 + 2][r] = av.z; As[c4 + 3][r] = av.w;
        }
        // W tile -> Bs
        for (int idx = tid; idx < B4; idx += 256) {
            int r  = idx / (BN / 4);
            int c4 = (idx % (BN / 4)) * 4;
            float4 bv = make_float4(0.f, 0.f, 0.f, 0.f);
            int gc = bcol + c4;
            if (gc < M) bv = *reinterpret_cast<const float4*>(W + (size_t)(k0 + r) * M + gc);
            *reinterpret_cast<float4*>(&Bs[r][c4]) = bv;
        }
        __syncthreads();
#pragma unroll
        for (int kk = 0; kk < BK; kk++) {
            float a[TM], b[TN];
#pragma unroll
            for (int i = 0; i < TM; i += 4) {
                float4 t = *reinterpret_cast<const float4*>(&As[kk][ty * TM + i]);
                a[i] = t.x; a[i + 1] = t.y; a[i + 2] = t.z; a[i + 3] = t.w;
            }
#pragma unroll
            for (int j = 0; j < TN; j += 4) {
                float4 t = *reinterpret_cast<const float4*>(&Bs[kk][tx * TN + j]);
                b[j] = t.x; b[j + 1] = t.y; b[j + 2] = t.z; b[j + 3] = t.w;
            }
#pragma unroll
            for (int i = 0; i < TM; i++)
#pragma unroll
                for (int j = 0; j < TN; j++)
                    acc[i][j] = fmaf(a[i], b[j], acc[i][j]);
        }
        __syncthreads();
    }

#pragma unroll
    for (int i = 0; i < TM; i++) {
        int gr = brow + ty * TM + i;
        if (gr >= N) continue;
#pragma unroll
        for (int j = 0; j < TN; j += 4) {
            int gc = bcol + tx * TN + j;
            if (gc >= M) continue;      // M is a multiple of 64 -> whole float4 in/out
            float4 o;
            o.x = acc[i][j + 0] + bias[gc + 0];
            o.y = acc[i][j + 1] + bias[gc + 1];
            o.z = acc[i][j + 2] + bias[gc + 2];
            o.w = acc[i][j + 3] + bias[gc + 3];
            *reinterpret_cast<float4*>(C + (size_t)gr * M + gc) = o;
        }
    }
}

// ---------------- per-node attention aggregation (warp / node) -------------
template<int PER>
__device__ __forceinline__ void vload(float* r, const float* __restrict__ p) {
    if constexpr ((PER & 3) == 0) {
#pragma unroll
        for (int i = 0; i < PER / 4; i++) {
            float4 t = reinterpret_cast<const float4*>(p)[i];
            r[4 * i + 0] = t.x; r[4 * i + 1] = t.y;
            r[4 * i + 2] = t.z; r[4 * i + 3] = t.w;
        }
    } else {
#pragma unroll
        for (int i = 0; i < PER / 2; i++) {
            float2 t = reinterpret_cast<const float2*>(p)[i];
            r[2 * i + 0] = t.x; r[2 * i + 1] = t.y;
        }
    }
}

// One warp per destination node. Lane l owns channels [l*PER, (l+1)*PER) of the
// H*C concatenated feature; each lane's channels lie in exactly one head, and a
// head spans RW = C/PER contiguous lanes -> shfl-xor reduction for the QK dot.
// Online softmax over the node's incoming edges (CSR), no atomics.
template<int HEADS, int CH, bool RELU>
__global__ void __launch_bounds__(256)
gat_agg_kernel(const float* __restrict__ Q, const float* __restrict__ Kf,
               const float* __restrict__ V,
               const int* __restrict__ rowptr, const int* __restrict__ srcs,
               float* __restrict__ out, int n)
{
    constexpr int NCH = HEADS * CH;
    constexpr int PER = NCH / 32;
    constexpr int RW  = CH / PER;        // lanes per head
    const int lane = threadIdx.x & 31;
    const int node = blockIdx.x * (blockDim.x >> 5) + (threadIdx.x >> 5);
    if (node >= n) return;

    const float scale = rsqrtf((float)CH);
    const size_t base = (size_t)node * NCH + lane * PER;

    float qv[PER], acc[PER];
    vload<PER>(qv, Q + base);
#pragma unroll
    for (int i = 0; i < PER; i++) acc[i] = 0.f;

    float m = __int_as_float(0xff800000);   // -inf
    float s = 0.f;

    const int e0 = rowptr[node];
    const int e1 = rowptr[node + 1];
    for (int e = e0; e < e1; e++) {
        const int sn = srcs[e];
        const size_t sb = (size_t)sn * NCH + lane * PER;
        float kv[PER], vv[PER];
        vload<PER>(kv, Kf + sb);
        vload<PER>(vv, V  + sb);

        float part = 0.f;
#pragma unroll
        for (int i = 0; i < PER; i++) part = fmaf(qv[i], kv[i], part);
#pragma unroll
        for (int off = RW >> 1; off > 0; off >>= 1)
            part += __shfl_xor_sync(0xffffffffu, part, off);

        const float alpha = part * scale;
        const float mn    = fmaxf(m, alpha);
        const float corr  = __expf(m - mn);      // exp(-inf)=0 on first edge
        const float w     = __expf(alpha - mn);
        s = s * corr + w;
#pragma unroll
        for (int i = 0; i < PER; i++) acc[i] = fmaf(acc[i], corr, w * vv[i]);
        m = mn;
    }

    const float inv = 1.f / (s + 1e-16f);
#pragma unroll
    for (int i = 0; i < PER; i++) {
        float o = out[base + i] + acc[i] * inv;   // skip connection already stored
        if (RELU) o = fmaxf(o, 0.f);
        out[base + i] = o;
    }
}

// ---------------- host orchestration ----------------
static inline void run_gemm(const float* A, const float* W, const float* b,
                            float* C, int n, int K, int M)
{
    if (M % 128 == 0) {
        dim3 g(M / 128, (n + 127) / 128);
        sgemm_bias_kernel<128, 128, 8, 8, 8><<<g, 256>>>(A, W, b, C, n, K, M);
    } else {
        dim3 g((M + 63) / 64, (n + 127) / 128);
        sgemm_bias_kernel<128, 64, 8, 8, 4><<<g, 256>>>(A, W, b, C, n, K, M);
    }
}

extern "C" void kernel_launch(void* const* d_in, const int* in_sizes, int n_in,
                              void* d_out, int out_size)
{
    const float* x  = (const float*)d_in[0];
    const void*  ei = d_in[1];                  // int32 or int64, detected on device
    const int N = in_sizes[0] / 128;
    const int E = in_sizes[1] / 2;

    const float* P[24];
    for (int i = 0; i < 24; i++) P[i] = (const float*)d_in[2 + i];
    // P layout per layer L (stride 8): Wq,bq, Wk,bk, Wv,bv, Ws,bs

    float *q, *k, *v, *h0, *h1;
    int *rowptr, *cnt, *cur, *srcs;
    cudaGetSymbolAddress((void**)&q,  g_q);
    cudaGetSymbolAddress((void**)&k,  g_k);
    cudaGetSymbolAddress((void**)&v,  g_v);
    cudaGetSymbolAddress((void**)&h0, g_h0);
    cudaGetSymbolAddress((void**)&h1, g_h1);
    cudaGetSymbolAddress((void**)&rowptr, g_rowptr);
    cudaGetSymbolAddress((void**)&cnt, g_cnt);
    cudaGetSymbolAddress((void**)&cur, g_cur);
    cudaGetSymbolAddress((void**)&srcs, g_srcs);

    const int TB = 256;

    // Build CSR (dst-sorted edge list) every launch — graph-capturable, ~100us
    detect_kernel<<<1, 1>>>((const int*)ei);
    zero_int_kernel<<<(N + TB - 1) / TB, TB>>>(cnt, N);
    hist_kernel<<<(E + TB - 1) / TB, TB>>>(ei, cnt, E);
    scan_kernel<<<1, 1024>>>(cnt, rowptr, cur, N);
    scatter_kernel<<<(E + TB - 1) / TB, TB>>>(ei, cur, srcs, E);

    const int aggBlocks = (N + 7) / 8;

    // ---- layer 0: 128 -> 8*64 (concat) + relu ----
    run_gemm(x, P[0], P[1], q,  N, 128, 512);
    run_gemm(x, P[2], P[3], k,  N, 128, 512);
    run_gemm(x, P[4], P[5], v,  N, 128, 512);
    run_gemm(x, P[6], P[7], h0, N, 128, 512);   // skip connection into h0
    gat_agg_kernel<8, 64, true><<<aggBlocks, 256>>>(q, k, v, rowptr, srcs, h0, N);

    // ---- layer 1: 512 -> 8*64 (concat) + relu ----
    run_gemm(h0, P[8],  P[9],  q,  N, 512, 512);
    run_gemm(h0, P[10], P[11], k,  N, 512, 512);
    run_gemm(h0, P[12], P[13], v,  N, 512, 512);
    run_gemm(h0, P[14], P[15], h1, N, 512, 512);
    gat_agg_kernel<8, 64, true><<<aggBlocks, 256>>>(q, k, v, rowptr, srcs, h1, N);

    // ---- layer 2: 512 -> 64 (heads=1, mean == identity), no relu ----
    float* out = (float*)d_out;
    run_gemm(h1, P[16], P[17], q,   N, 512, 64);
    run_gemm(h1, P[18], P[19], k,   N, 512, 64);
    run_gemm(h1, P[20], P[21], v,   N, 512, 64);
    run_gemm(h1, P[22], P[23], out, N, 512, 64);  // skip into d_out
    gat_agg_kernel<1, 64, false><<<aggBlocks, 256>>>(q, k, v, rowptr, srcs, out, N);
}

// round 4
// speedup vs baseline: 1.4158x; 1.4158x over previous
#include <cuda_runtime.h>
#include <cuda_bf16.h>
#include <cstdint>

#define NMAX 50000
#define EMAX 800000
#define KMAX 512
#define NTOTMAX 2048

// ======================= low-level helpers (sm_80-compatible PTX) ==========
__device__ __forceinline__ uint32_t smem_u32(const void* p) {
    uint32_t a;
    asm("{ .reg .u64 t; cvta.to.shared.u64 t, %1; cvt.u32.u64 %0, t; }" : "=r"(a) : "l"(p));
    return a;
}
__device__ __forceinline__ void cp16(uint32_t dst, const void* src, int srcsize) {
    asm volatile("cp.async.cg.shared.global [%0], [%1], 16, %2;"
                 :: "r"(dst), "l"(src), "r"(srcsize));
}
__device__ __forceinline__ void ldm_x4(uint32_t& r0, uint32_t& r1, uint32_t& r2, uint32_t& r3,
                                       uint32_t addr) {
    asm volatile("ldmatrix.sync.aligned.m8n8.x4.shared.b16 {%0,%1,%2,%3}, [%4];"
                 : "=r"(r0), "=r"(r1), "=r"(r2), "=r"(r3) : "r"(addr));
}
__device__ __forceinline__ void mma16816(float* c, const uint32_t* a, const uint32_t* b) {
    asm volatile("mma.sync.aligned.m16n8k16.row.col.f32.bf16.bf16.f32 "
                 "{%0,%1,%2,%3}, {%4,%5,%6,%7}, {%8,%9}, {%0,%1,%2,%3};"
                 : "+f"(c[0]), "+f"(c[1]), "+f"(c[2]), "+f"(c[3])
                 : "r"(a[0]), "r"(a[1]), "r"(a[2]), "r"(a[3]), "r"(b[0]), "r"(b[1]));
}

// ======================= scratch (device globals) =======================
__device__ float g_q [NMAX * 512];
__device__ float g_k [NMAX * 512];
__device__ float g_v [NMAX * 512];
__device__ float g_h0[NMAX * 512];
__device__ float g_h1[NMAX * 512];
__device__ __nv_bfloat16 g_ahi[NMAX * KMAX];
__device__ __nv_bfloat16 g_alo[NMAX * KMAX];
__device__ __nv_bfloat16 g_whi[3 * NTOTMAX * KMAX];
__device__ __nv_bfloat16 g_wlo[3 * NTOTMAX * KMAX];
__device__ float g_biasf[3 * NTOTMAX];
__device__ int   g_rowptr[NMAX + 1];
__device__ int   g_cnt[NMAX];
__device__ int   g_cur[NMAX];
__device__ int   g_srcs[EMAX];
__device__ int   g_is64;

// ======================= edge dtype detection =======================
__global__ void detect_kernel(const int* __restrict__ w) {
    int odd_nonzero = 0;
    for (int i = 0; i < 128; i++) odd_nonzero += (w[2 * i + 1] != 0);
    g_is64 = (odd_nonzero == 0) ? 1 : 0;
}
__device__ __forceinline__ int edge_at(const void* ei, long long idx, int is64) {
    return is64 ? (int)((const long long*)ei)[idx] : ((const int*)ei)[idx];
}

// ======================= CSR build =======================
__global__ void zero_int_kernel(int* __restrict__ p, int n) {
    int i = blockIdx.x * blockDim.x + threadIdx.x;
    if (i < n) p[i] = 0;
}
__global__ void hist_kernel(const void* __restrict__ ei, int* __restrict__ cnt, int E) {
    int e = blockIdx.x * blockDim.x + threadIdx.x;
    if (e < E) atomicAdd(&cnt[edge_at(ei, (long long)E + e, g_is64)], 1);
}
__global__ void scan_kernel(const int* __restrict__ cnt, int* __restrict__ rowptr,
                            int* __restrict__ cur, int n) {
    __shared__ int part[1024];
    const int t = threadIdx.x;
    const int chunk = (n + 1023) >> 10;
    int b = t * chunk; if (b > n) b = n;
    int e = b + chunk; if (e > n) e = n;
    int s = 0;
    for (int i = b; i < e; i++) s += cnt[i];
    part[t] = s;
    __syncthreads();
    if (t == 0) {
        int a = 0;
        for (int i = 0; i < 1024; i++) { int v = part[i]; part[i] = a; a += v; }
    }
    __syncthreads();
    int off = part[t];
    for (int i = b; i < e; i++) { rowptr[i] = off; cur[i] = off; off += cnt[i]; }
    if (t == 1023) rowptr[n] = off;
}
__global__ void scatter_kernel(const void* __restrict__ ei, int* __restrict__ cur,
                               int* __restrict__ srcs, int E) {
    int e = blockIdx.x * blockDim.x + threadIdx.x;
    if (e < E) {
        const int is64 = g_is64;
        int d = edge_at(ei, (long long)E + e, is64);
        int p = atomicAdd(&cur[d], 1);
        srcs[p] = edge_at(ei, e, is64);
    }
}

// ======================= weight prep: transpose + hi/lo split ==============
struct WDesc { const float* W; const float* b; int K; int M; int layer; int off; };
struct WTable { WDesc d[12]; };

__global__ void prep_weights_kernel(WTable t, __nv_bfloat16* __restrict__ whi,
                                    __nv_bfloat16* __restrict__ wlo, float* __restrict__ biasf) {
    const WDesc w = t.d[blockIdx.y];
    const size_t base = (size_t)w.layer * NTOTMAX * KMAX;
    const int stride = gridDim.x * blockDim.x;
    for (int i = blockIdx.x * blockDim.x + threadIdx.x; i < w.M; i += stride)
        biasf[w.layer * NTOTMAX + w.off + i] = w.b[i];
    const int total = w.K * w.M;
    for (int i = blockIdx.x * blockDim.x + threadIdx.x; i < total; i += stride) {
        int k = i / w.M, m = i % w.M;
        float v = w.W[i];
        __nv_bfloat16 hi = __float2bfloat16(v);
        float lo = v - __bfloat162float(hi);
        size_t dst = base + (size_t)(w.off + m) * w.K + k;
        whi[dst] = hi;
        wlo[dst] = __float2bfloat16(lo);
    }
}

// ======================= activation hi/lo split =======================
__global__ void split_act_kernel(const float* __restrict__ x, __nv_bfloat16* __restrict__ hi,
                                 __nv_bfloat16* __restrict__ lo, int total) {
    int i = blockIdx.x * blockDim.x + threadIdx.x;
    if (i < total) {
        float v = x[i];
        __nv_bfloat16 h = __float2bfloat16(v);
        hi[i] = h;
        lo[i] = __float2bfloat16(v - __bfloat162float(h));
    }
}

// ======================= HMMA GEMM: C[N, ntot] = A @ Wt^T + bias ===========
// A:  [Nrows, K]  bf16 hi/lo (row-major); Wt: [ntot, K] bf16 hi/lo (K-major)
// 3-pass split in register accumulators: Ahi*Bhi + Ahi*Blo + Alo*Bhi
// CTA tile 128x128, BK=32, 8 warps (2x4), warp tile 64x32, 3-stage cp.async.
#define STG_BYTES 10240                 /* 128 rows * 80B padded */
#define SMEM_TOT  (6 * STG_BYTES)       /* 3 stages x (A+B) = 61440 */

struct OutSpec { float* out[4]; int cpo; };

__global__ void __launch_bounds__(256)
gemm_mma_kernel(const __nv_bfloat16* __restrict__ Ahi, const __nv_bfloat16* __restrict__ Alo,
                const __nv_bfloat16* __restrict__ Whi, const __nv_bfloat16* __restrict__ Wlo,
                const float* __restrict__ biasf, OutSpec os, int Nrows, int K)
{
    extern __shared__ char smem[];
    const uint32_t sb = smem_u32(smem);
    const int tid = threadIdx.x, lane = tid & 31, wid = tid >> 5;
    const int wm = wid & 1, wn = wid >> 1;
    const int m0 = blockIdx.y * 128, n0 = blockIdx.x * 128;
    const int KT = K / 32, TOT = 3 * KT;

    float acc[4][4][4];
#pragma unroll
    for (int a = 0; a < 4; a++)
#pragma unroll
        for (int b = 0; b < 4; b++)
#pragma unroll
            for (int c = 0; c < 4; c++) acc[a][b][c] = 0.f;

    // two 16B-copy tasks per tensor per thread (512 tasks, 256 threads)
    const int r0 = tid >> 2, c0 = tid & 3;
    const int r1 = (tid + 256) >> 2, c1 = (tid + 256) & 3;

    auto issue = [&](int kt) {
        const int slot = kt % 3;
        const int p = kt / KT;
        const __nv_bfloat16* A = (p == 2) ? Alo : Ahi;
        const __nv_bfloat16* B = (p == 1) ? Wlo : Whi;
        const int koff = (kt - p * KT) * 32;
        const uint32_t sA = sb + slot * STG_BYTES;
        const uint32_t sB = sb + 3 * STG_BYTES + slot * STG_BYTES;
        int ar0 = m0 + r0; bool v0 = ar0 < Nrows; if (!v0) ar0 = 0;
        int ar1 = m0 + r1; bool v1 = ar1 < Nrows; if (!v1) ar1 = 0;
        cp16(sA + r0 * 80 + c0 * 16, A + (size_t)ar0 * K + koff + c0 * 8, v0 ? 16 : 0);
        cp16(sA + r1 * 80 + c1 * 16, A + (size_t)ar1 * K + koff + c1 * 8, v1 ? 16 : 0);
        cp16(sB + r0 * 80 + c0 * 16, B + (size_t)(n0 + r0) * K + koff + c0 * 8, 16);
        cp16(sB + r1 * 80 + c1 * 16, B + (size_t)(n0 + r1) * K + koff + c1 * 8, 16);
    };

    // ldmatrix base addresses (per-warp)
    const uint32_t aB = sb + (wm * 64 + (lane & 15)) * 80 + (lane >> 4) * 16;
    const uint32_t bB = sb + 3 * STG_BYTES
                      + (wn * 32 + (lane & 7) + ((lane >> 4) << 3)) * 80
                      + ((lane >> 3) & 1) * 16;

    issue(0);
    asm volatile("cp.async.commit_group;" ::: "memory");
    issue(1);
    asm volatile("cp.async.commit_group;" ::: "memory");

    for (int kt = 0; kt < TOT; kt++) {
        asm volatile("cp.async.wait_group 1;" ::: "memory");
        __syncthreads();
        if (kt + 2 < TOT) issue(kt + 2);
        asm volatile("cp.async.commit_group;" ::: "memory");

        const uint32_t sOff = (uint32_t)(kt % 3) * STG_BYTES;
#pragma unroll
        for (int ks = 0; ks < 2; ks++) {
            uint32_t a[4][4], b[2][4];
#pragma unroll
            for (int mi = 0; mi < 4; mi++)
                ldm_x4(a[mi][0], a[mi][1], a[mi][2], a[mi][3],
                       aB + sOff + mi * 16 * 80 + ks * 32);
#pragma unroll
            for (int nj = 0; nj < 2; nj++)
                ldm_x4(b[nj][0], b[nj][1], b[nj][2], b[nj][3],
                       bB + sOff + nj * 16 * 80 + ks * 32);
#pragma unroll
            for (int mi = 0; mi < 4; mi++)
#pragma unroll
                for (int ni = 0; ni < 4; ni++)
                    mma16816(acc[mi][ni], a[mi], &b[ni >> 1][(ni & 1) * 2]);
        }
    }

    // epilogue: c0,c1 -> (row, col..col+1); c2,c3 -> row+8
    const int erow = lane >> 2, ecol = (lane & 3) * 2;
#pragma unroll
    for (int mi = 0; mi < 4; mi++) {
#pragma unroll
        for (int half = 0; half < 2; half++) {
            const int gr = m0 + wm * 64 + mi * 16 + erow + half * 8;
            if (gr >= Nrows) continue;
#pragma unroll
            for (int ni = 0; ni < 4; ni++) {
                const int gc = n0 + wn * 32 + ni * 8 + ecol;
                float* dst = os.out[gc / os.cpo];
                float2 o;
                o.x = acc[mi][ni][half * 2 + 0] + biasf[gc + 0];
                o.y = acc[mi][ni][half * 2 + 1] + biasf[gc + 1];
                *reinterpret_cast<float2*>(dst + (size_t)gr * os.cpo + (gc % os.cpo)) = o;
            }
        }
    }
}

// ======================= per-node attention aggregation =======================
template<int PER>
__device__ __forceinline__ void vload(float* r, const float* __restrict__ p) {
#pragma unroll
    for (int i = 0; i < PER / 2; i++) {
        float2 t = reinterpret_cast<const float2*>(p)[i];
        r[2 * i + 0] = t.x; r[2 * i + 1] = t.y;
    }
}

template<int HEADS, int CH, bool RELU>
__global__ void __launch_bounds__(256)
gat_agg_kernel(const float* __restrict__ Q, const float* __restrict__ Kf,
               const float* __restrict__ V,
               const int* __restrict__ rowptr, const int* __restrict__ srcs,
               float* __restrict__ out, int n)
{
    constexpr int NCH = HEADS * CH;
    constexpr int PER = NCH / 32;
    constexpr int RW  = CH / PER;
    const int lane = threadIdx.x & 31;
    const int node = blockIdx.x * (blockDim.x >> 5) + (threadIdx.x >> 5);
    if (node >= n) return;

    const float scale = rsqrtf((float)CH);
    const size_t base = (size_t)node * NCH + lane * PER;

    float qv[PER], acc[PER];
    vload<PER>(qv, Q + base);
#pragma unroll
    for (int i = 0; i < PER; i++) acc[i] = 0.f;

    float m = __int_as_float(0xff800000);
    float s = 0.f;

    const int e0 = rowptr[node];
    const int e1 = rowptr[node + 1];
    for (int e = e0; e < e1; e++) {
        const int sn = srcs[e];
        const size_t sbx = (size_t)sn * NCH + lane * PER;
        float kv[PER], vv[PER];
        vload<PER>(kv, Kf + sbx);
        vload<PER>(vv, V  + sbx);

        float part = 0.f;
#pragma unroll
        for (int i = 0; i < PER; i++) part = fmaf(qv[i], kv[i], part);
#pragma unroll
        for (int off = RW >> 1; off > 0; off >>= 1)
            part += __shfl_xor_sync(0xffffffffu, part, off);

        const float alpha = part * scale;
        const float mn    = fmaxf(m, alpha);
        const float corr  = __expf(m - mn);
        const float w     = __expf(alpha - mn);
        s = s * corr + w;
#pragma unroll
        for (int i = 0; i < PER; i++) acc[i] = fmaf(acc[i], corr, w * vv[i]);
        m = mn;
    }

    const float inv = 1.f / (s + 1e-16f);
#pragma unroll
    for (int i = 0; i < PER; i++) {
        float o = out[base + i] + acc[i] * inv;
        if (RELU) o = fmaxf(o, 0.f);
        out[base + i] = o;
    }
}

// ======================= host orchestration =======================
extern "C" void kernel_launch(void* const* d_in, const int* in_sizes, int n_in,
                              void* d_out, int out_size)
{
    const float* x  = (const float*)d_in[0];
    const void*  ei = d_in[1];
    const int N = in_sizes[0] / 128;
    const int E = in_sizes[1] / 2;

    const float* P[24];
    for (int i = 0; i < 24; i++) P[i] = (const float*)d_in[2 + i];

    float *q, *k, *v, *h0, *h1, *biasf;
    __nv_bfloat16 *ahi, *alo, *whi, *wlo;
    int *rowptr, *cnt, *cur, *srcs;
    cudaGetSymbolAddress((void**)&q,  g_q);
    cudaGetSymbolAddress((void**)&k,  g_k);
    cudaGetSymbolAddress((void**)&v,  g_v);
    cudaGetSymbolAddress((void**)&h0, g_h0);
    cudaGetSymbolAddress((void**)&h1, g_h1);
    cudaGetSymbolAddress((void**)&ahi, g_ahi);
    cudaGetSymbolAddress((void**)&alo, g_alo);
    cudaGetSymbolAddress((void**)&whi, g_whi);
    cudaGetSymbolAddress((void**)&wlo, g_wlo);
    cudaGetSymbolAddress((void**)&biasf, g_biasf);
    cudaGetSymbolAddress((void**)&rowptr, g_rowptr);
    cudaGetSymbolAddress((void**)&cnt, g_cnt);
    cudaGetSymbolAddress((void**)&cur, g_cur);
    cudaGetSymbolAddress((void**)&srcs, g_srcs);

    cudaFuncSetAttribute(gemm_mma_kernel, cudaFuncAttributeMaxDynamicSharedMemorySize, SMEM_TOT);

    const int TB = 256;
    float* out = (float*)d_out;

    WTable wt;
    const int Ks[3] = {128, 512, 512};
    const int Ms[3] = {512, 512, 64};
    for (int l = 0; l < 3; l++)
        for (int j = 0; j < 4; j++) {
            wt.d[l * 4 + j].W = P[l * 8 + j * 2];
            wt.d[l * 4 + j].b = P[l * 8 + j * 2 + 1];
            wt.d[l * 4 + j].K = Ks[l];
            wt.d[l * 4 + j].M = Ms[l];
            wt.d[l * 4 + j].layer = l;
            wt.d[l * 4 + j].off = j * Ms[l];
        }

    // launch order keeps layer-0 GEMM as launch #5 (ncu -s 5 -c 1)
    detect_kernel<<<1, 1>>>((const int*)ei);                                        // 0
    prep_weights_kernel<<<dim3(64, 12), TB>>>(wt, whi, wlo, biasf);                 // 1
    split_act_kernel<<<(N * 128 + TB - 1) / TB, TB>>>(x, ahi, alo, N * 128);        // 2
    zero_int_kernel<<<(N + TB - 1) / TB, TB>>>(cnt, N);                             // 3
    hist_kernel<<<(E + TB - 1) / TB, TB>>>(ei, cnt, E);                             // 4

    const int mtiles = (N + 127) / 128;
    OutSpec os0; os0.out[0] = q; os0.out[1] = k; os0.out[2] = v; os0.out[3] = h0; os0.cpo = 512;
    gemm_mma_kernel<<<dim3(2048 / 128, mtiles), 256, SMEM_TOT>>>(                   // 5 (profiled)
        ahi, alo, whi, wlo, biasf, os0, N, 128);

    scan_kernel<<<1, 1024>>>(cnt, rowptr, cur, N);                                  // 6
    scatter_kernel<<<(E + TB - 1) / TB, TB>>>(ei, cur, srcs, E);                    // 7

    const int aggBlocks = (N + 7) / 8;
    gat_agg_kernel<8, 64, true><<<aggBlocks, 256>>>(q, k, v, rowptr, srcs, h0, N);  // 8

    // ---- layer 1 ----
    split_act_kernel<<<(N * 512 + TB - 1) / TB, TB>>>(h0, ahi, alo, N * 512);
    OutSpec os1; os1.out[0] = q; os1.out[1] = k; os1.out[2] = v; os1.out[3] = h1; os1.cpo = 512;
    gemm_mma_kernel<<<dim3(2048 / 128, mtiles), 256, SMEM_TOT>>>(
        ahi, alo, whi + (size_t)1 * NTOTMAX * KMAX, wlo + (size_t)1 * NTOTMAX * KMAX,
        biasf + NTOTMAX, os1, N, 512);
    gat_agg_kernel<8, 64, true><<<aggBlocks, 256>>>(q, k, v, rowptr, srcs, h1, N);

    // ---- layer 2 (heads=1, ch=64) ----
    split_act_kernel<<<(N * 512 + TB - 1) / TB, TB>>>(h1, ahi, alo, N * 512);
    OutSpec os2; os2.out[0] = q; os2.out[1] = k; os2.out[2] = v; os2.out[3] = out; os2.cpo = 64;
    gemm_mma_kernel<<<dim3(256 / 128, mtiles), 256, SMEM_TOT>>>(
        ahi, alo, whi + (size_t)2 * NTOTMAX * KMAX, wlo + (size_t)2 * NTOTMAX * KMAX,
        biasf + 2 * NTOTMAX, os2, N, 512);
    gat_agg_kernel<1, 64, false><<<aggBlocks, 256>>>(q, k, v, rowptr, srcs, out, N);
}

// round 5
// speedup vs baseline: 1.7149x; 1.2112x over previous
#include <cuda_runtime.h>
#include <cuda_bf16.h>
#include <cstdint>

#define NMAX 50000
#define EMAX 800000
#define KMAX 512
#define NTOTMAX 2048

// ======================= low-level helpers (sm_80-compatible PTX) ==========
__device__ __forceinline__ uint32_t smem_u32(const void* p) {
    uint32_t a;
    asm("{ .reg .u64 t; cvta.to.shared.u64 t, %1; cvt.u32.u64 %0, t; }" : "=r"(a) : "l"(p));
    return a;
}
__device__ __forceinline__ void cp16(uint32_t dst, const void* src, int srcsize) {
    asm volatile("cp.async.cg.shared.global [%0], [%1], 16, %2;"
                 :: "r"(dst), "l"(src), "r"(srcsize));
}
__device__ __forceinline__ void ldm_x4(uint32_t& r0, uint32_t& r1, uint32_t& r2, uint32_t& r3,
                                       uint32_t addr) {
    asm volatile("ldmatrix.sync.aligned.m8n8.x4.shared.b16 {%0,%1,%2,%3}, [%4];"
                 : "=r"(r0), "=r"(r1), "=r"(r2), "=r"(r3) : "r"(addr));
}
__device__ __forceinline__ void mma16816(float* c, const uint32_t* a, const uint32_t* b) {
    asm volatile("mma.sync.aligned.m16n8k16.row.col.f32.bf16.bf16.f32 "
                 "{%0,%1,%2,%3}, {%4,%5,%6,%7}, {%8,%9}, {%0,%1,%2,%3};"
                 : "+f"(c[0]), "+f"(c[1]), "+f"(c[2]), "+f"(c[3])
                 : "r"(a[0]), "r"(a[1]), "r"(a[2]), "r"(a[3]), "r"(b[0]), "r"(b[1]));
}

// ======================= scratch (device globals) =======================
__device__ float g_q [NMAX * 512];
__device__ float g_k [NMAX * 512];
__device__ float g_v [NMAX * 512];
__device__ float g_h0[NMAX * 512];
__device__ float g_h1[NMAX * 512];
__device__ __nv_bfloat16 g_ahi[NMAX * KMAX];
__device__ __nv_bfloat16 g_alo[NMAX * KMAX];
__device__ __nv_bfloat16 g_whi[3 * NTOTMAX * KMAX];
__device__ __nv_bfloat16 g_wlo[3 * NTOTMAX * KMAX];
__device__ float g_biasf[3 * NTOTMAX];
__device__ int   g_rowptr[NMAX + 1];
__device__ int   g_cnt[NMAX];
__device__ int   g_cur[NMAX];
__device__ int   g_srcs[EMAX];
__device__ int   g_is64;

// ======================= edge dtype detection =======================
__global__ void detect_kernel(const int* __restrict__ w) {
    int odd_nonzero = 0;
    for (int i = 0; i < 128; i++) odd_nonzero += (w[2 * i + 1] != 0);
    g_is64 = (odd_nonzero == 0) ? 1 : 0;
}
__device__ __forceinline__ int edge_at(const void* ei, long long idx, int is64) {
    return is64 ? (int)((const long long*)ei)[idx] : ((const int*)ei)[idx];
}

// ======================= CSR build =======================
__global__ void zero_int_kernel(int* __restrict__ p, int n) {
    int i = blockIdx.x * blockDim.x + threadIdx.x;
    if (i < n) p[i] = 0;
}
__global__ void hist_kernel(const void* __restrict__ ei, int* __restrict__ cnt, int E) {
    int e = blockIdx.x * blockDim.x + threadIdx.x;
    if (e < E) atomicAdd(&cnt[edge_at(ei, (long long)E + e, g_is64)], 1);
}
__global__ void scan_kernel(const int* __restrict__ cnt, int* __restrict__ rowptr,
                            int* __restrict__ cur, int n) {
    __shared__ int part[1024];
    const int t = threadIdx.x;
    const int chunk = (n + 1023) >> 10;
    int b = t * chunk; if (b > n) b = n;
    int e = b + chunk; if (e > n) e = n;
    int s = 0;
    for (int i = b; i < e; i++) s += cnt[i];
    part[t] = s;
    __syncthreads();
    if (t == 0) {
        int a = 0;
        for (int i = 0; i < 1024; i++) { int v = part[i]; part[i] = a; a += v; }
    }
    __syncthreads();
    int off = part[t];
    for (int i = b; i < e; i++) { rowptr[i] = off; cur[i] = off; off += cnt[i]; }
    if (t == 1023) rowptr[n] = off;
}
__global__ void scatter_kernel(const void* __restrict__ ei, int* __restrict__ cur,
                               int* __restrict__ srcs, int E) {
    int e = blockIdx.x * blockDim.x + threadIdx.x;
    if (e < E) {
        const int is64 = g_is64;
        int d = edge_at(ei, (long long)E + e, is64);
        int p = atomicAdd(&cur[d], 1);
        srcs[p] = edge_at(ei, e, is64);
    }
}

// ======================= weight prep: transpose + hi/lo split ==============
struct WDesc { const float* W; const float* b; int K; int M; int layer; int off; };
struct WTable { WDesc d[12]; };

__global__ void prep_weights_kernel(WTable t, __nv_bfloat16* __restrict__ whi,
                                    __nv_bfloat16* __restrict__ wlo, float* __restrict__ biasf) {
    const WDesc w = t.d[blockIdx.y];
    const size_t base = (size_t)w.layer * NTOTMAX * KMAX;
    const int stride = gridDim.x * blockDim.x;
    for (int i = blockIdx.x * blockDim.x + threadIdx.x; i < w.M; i += stride)
        biasf[w.layer * NTOTMAX + w.off + i] = w.b[i];
    const int total = w.K * w.M;
    for (int i = blockIdx.x * blockDim.x + threadIdx.x; i < total; i += stride) {
        int k = i / w.M, m = i % w.M;
        float v = w.W[i];
        __nv_bfloat16 hi = __float2bfloat16(v);
        float lo = v - __bfloat162float(hi);
        size_t dst = base + (size_t)(w.off + m) * w.K + k;
        whi[dst] = hi;
        wlo[dst] = __float2bfloat16(lo);
    }
}

// ======================= activation hi/lo split (input x only) =============
__global__ void split_act_kernel(const float* __restrict__ x, __nv_bfloat16* __restrict__ hi,
                                 __nv_bfloat16* __restrict__ lo, int total) {
    int i = blockIdx.x * blockDim.x + threadIdx.x;
    if (i < total) {
        float v = x[i];
        __nv_bfloat16 h = __float2bfloat16(v);
        hi[i] = h;
        lo[i] = __float2bfloat16(v - __bfloat162float(h));
    }
}

// ======================= HMMA GEMM: C[N, ntot] = A @ Wt^T + bias ===========
// 3-pass bf16 split in register accumulators: Ahi*Bhi + Ahi*Blo + Alo*Bhi
// CTA tile 128x128, BK=32, 8 warps (2x4), warp tile 64x32, 4-stage cp.async.
#define STAGES 4
#define STG_BYTES 10240                 /* 128 rows * 80B padded */
#define SMEM_TOT  (2 * STAGES * STG_BYTES)   /* 81920 */

struct OutSpec { float* out[4]; int cpo; };

__global__ void __launch_bounds__(256, 2)
gemm_mma_kernel(const __nv_bfloat16* __restrict__ Ahi, const __nv_bfloat16* __restrict__ Alo,
                const __nv_bfloat16* __restrict__ Whi, const __nv_bfloat16* __restrict__ Wlo,
                const float* __restrict__ biasf, OutSpec os, int Nrows, int K)
{
    extern __shared__ char smem[];
    const uint32_t sb = smem_u32(smem);
    const int tid = threadIdx.x, lane = tid & 31, wid = tid >> 5;
    const int wm = wid & 1, wn = wid >> 1;
    const int m0 = blockIdx.y * 128, n0 = blockIdx.x * 128;
    const int KT = K / 32, TOT = 3 * KT;

    float acc[4][4][4];
#pragma unroll
    for (int a = 0; a < 4; a++)
#pragma unroll
        for (int b = 0; b < 4; b++)
#pragma unroll
            for (int c = 0; c < 4; c++) acc[a][b][c] = 0.f;

    const int r0 = tid >> 2, c0 = tid & 3;
    const int r1 = (tid + 256) >> 2, c1 = (tid + 256) & 3;

    auto issue = [&](int kt) {
        const int slot = kt % STAGES;
        const int p = kt / KT;
        const __nv_bfloat16* A = (p == 2) ? Alo : Ahi;
        const __nv_bfloat16* B = (p == 1) ? Wlo : Whi;
        const int koff = (kt - p * KT) * 32;
        const uint32_t sA = sb + slot * STG_BYTES;
        const uint32_t sB = sb + STAGES * STG_BYTES + slot * STG_BYTES;
        int ar0 = m0 + r0; bool v0 = ar0 < Nrows; if (!v0) ar0 = 0;
        int ar1 = m0 + r1; bool v1 = ar1 < Nrows; if (!v1) ar1 = 0;
        cp16(sA + r0 * 80 + c0 * 16, A + (size_t)ar0 * K + koff + c0 * 8, v0 ? 16 : 0);
        cp16(sA + r1 * 80 + c1 * 16, A + (size_t)ar1 * K + koff + c1 * 8, v1 ? 16 : 0);
        cp16(sB + r0 * 80 + c0 * 16, B + (size_t)(n0 + r0) * K + koff + c0 * 8, 16);
        cp16(sB + r1 * 80 + c1 * 16, B + (size_t)(n0 + r1) * K + koff + c1 * 8, 16);
    };

    const uint32_t aB = sb + (wm * 64 + (lane & 15)) * 80 + (lane >> 4) * 16;
    const uint32_t bB = sb + STAGES * STG_BYTES
                      + (wn * 32 + (lane & 7) + ((lane >> 4) << 3)) * 80
                      + ((lane >> 3) & 1) * 16;

    issue(0); asm volatile("cp.async.commit_group;" ::: "memory");
    issue(1); asm volatile("cp.async.commit_group;" ::: "memory");
    issue(2); asm volatile("cp.async.commit_group;" ::: "memory");

    for (int kt = 0; kt < TOT; kt++) {
        asm volatile("cp.async.wait_group 2;" ::: "memory");
        __syncthreads();
        if (kt + 3 < TOT) issue(kt + 3);
        asm volatile("cp.async.commit_group;" ::: "memory");

        const uint32_t sOff = (uint32_t)(kt % STAGES) * STG_BYTES;
#pragma unroll
        for (int ks = 0; ks < 2; ks++) {
            uint32_t a[4][4], b[2][4];
#pragma unroll
            for (int mi = 0; mi < 4; mi++)
                ldm_x4(a[mi][0], a[mi][1], a[mi][2], a[mi][3],
                       aB + sOff + mi * 16 * 80 + ks * 32);
#pragma unroll
            for (int nj = 0; nj < 2; nj++)
                ldm_x4(b[nj][0], b[nj][1], b[nj][2], b[nj][3],
                       bB + sOff + nj * 16 * 80 + ks * 32);
#pragma unroll
            for (int mi = 0; mi < 4; mi++)
#pragma unroll
                for (int ni = 0; ni < 4; ni++)
                    mma16816(acc[mi][ni], a[mi], &b[ni >> 1][(ni & 1) * 2]);
        }
    }

    const int erow = lane >> 2, ecol = (lane & 3) * 2;
#pragma unroll
    for (int mi = 0; mi < 4; mi++) {
#pragma unroll
        for (int half = 0; half < 2; half++) {
            const int gr = m0 + wm * 64 + mi * 16 + erow + half * 8;
            if (gr >= Nrows) continue;
#pragma unroll
            for (int ni = 0; ni < 4; ni++) {
                const int gc = n0 + wn * 32 + ni * 8 + ecol;
                float* dst = os.out[gc / os.cpo];
                float2 o;
                o.x = acc[mi][ni][half * 2 + 0] + biasf[gc + 0];
                o.y = acc[mi][ni][half * 2 + 1] + biasf[gc + 1];
                *reinterpret_cast<float2*>(dst + (size_t)gr * os.cpo + (gc % os.cpo)) = o;
            }
        }
    }
}

// ======================= per-node attention aggregation =======================
template<int PER>
__device__ __forceinline__ void vload(float* r, const float* __restrict__ p) {
    if constexpr ((PER & 3) == 0) {
#pragma unroll
        for (int i = 0; i < PER / 4; i++) {
            float4 t = reinterpret_cast<const float4*>(p)[i];
            r[4 * i + 0] = t.x; r[4 * i + 1] = t.y;
            r[4 * i + 2] = t.z; r[4 * i + 3] = t.w;
        }
    } else {
#pragma unroll
        for (int i = 0; i < PER / 2; i++) {
            float2 t = reinterpret_cast<const float2*>(p)[i];
            r[2 * i + 0] = t.x; r[2 * i + 1] = t.y;
        }
    }
}

// One warp per destination node; 2-edge software pipelining; online softmax.
// Optionally fuses the bf16 hi/lo activation split into the epilogue.
template<int HEADS, int CH, bool RELU, bool SPLIT>
__global__ void __launch_bounds__(256)
gat_agg_kernel(const float* __restrict__ Q, const float* __restrict__ Kf,
               const float* __restrict__ V,
               const int* __restrict__ rowptr, const int* __restrict__ srcs,
               float* __restrict__ out,
               __nv_bfloat16* __restrict__ hi, __nv_bfloat16* __restrict__ lo, int n)
{
    constexpr int NCH = HEADS * CH;
    constexpr int PER = NCH / 32;
    constexpr int RW  = CH / PER;
    const int lane = threadIdx.x & 31;
    const int node = blockIdx.x * (blockDim.x >> 5) + (threadIdx.x >> 5);
    if (node >= n) return;

    const float scale = rsqrtf((float)CH);
    const size_t base = (size_t)node * NCH + lane * PER;

    float qv[PER], acc[PER];
    vload<PER>(qv, Q + base);
#pragma unroll
    for (int i = 0; i < PER; i++) acc[i] = 0.f;

    float m = __int_as_float(0xff800000);
    float s = 0.f;

    const int e0 = rowptr[node];
    const int e1 = rowptr[node + 1];
    int e = e0;
    for (; e + 2 <= e1; e += 2) {
        const int s0 = srcs[e], s1 = srcs[e + 1];
        const size_t b0 = (size_t)s0 * NCH + lane * PER;
        const size_t b1 = (size_t)s1 * NCH + lane * PER;
        float k0[PER], v0[PER], k1[PER], v1[PER];
        vload<PER>(k0, Kf + b0);
        vload<PER>(k1, Kf + b1);
        vload<PER>(v0, V  + b0);
        vload<PER>(v1, V  + b1);

        float p0 = 0.f, p1 = 0.f;
#pragma unroll
        for (int i = 0; i < PER; i++) { p0 = fmaf(qv[i], k0[i], p0); p1 = fmaf(qv[i], k1[i], p1); }
#pragma unroll
        for (int off = RW >> 1; off > 0; off >>= 1) {
            p0 += __shfl_xor_sync(0xffffffffu, p0, off);
            p1 += __shfl_xor_sync(0xffffffffu, p1, off);
        }
        const float a0 = p0 * scale, a1 = p1 * scale;
        const float mn = fmaxf(m, fmaxf(a0, a1));
        const float corr = __expf(m - mn);
        const float w0 = __expf(a0 - mn);
        const float w1 = __expf(a1 - mn);
        s = s * corr + w0 + w1;
#pragma unroll
        for (int i = 0; i < PER; i++)
            acc[i] = fmaf(acc[i], corr, fmaf(w0, v0[i], w1 * v1[i]));
        m = mn;
    }
    if (e < e1) {
        const int sn = srcs[e];
        const size_t sbx = (size_t)sn * NCH + lane * PER;
        float kv[PER], vv[PER];
        vload<PER>(kv, Kf + sbx);
        vload<PER>(vv, V  + sbx);
        float part = 0.f;
#pragma unroll
        for (int i = 0; i < PER; i++) part = fmaf(qv[i], kv[i], part);
#pragma unroll
        for (int off = RW >> 1; off > 0; off >>= 1)
            part += __shfl_xor_sync(0xffffffffu, part, off);
        const float alpha = part * scale;
        const float mn = fmaxf(m, alpha);
        const float corr = __expf(m - mn);
        const float w = __expf(alpha - mn);
        s = s * corr + w;
#pragma unroll
        for (int i = 0; i < PER; i++) acc[i] = fmaf(acc[i], corr, w * vv[i]);
        m = mn;
    }

    const float inv = 1.f / (s + 1e-16f);
#pragma unroll
    for (int i = 0; i < PER; i++) {
        float o = out[base + i] + acc[i] * inv;
        if (RELU) o = fmaxf(o, 0.f);
        out[base + i] = o;
        if (SPLIT) {
            __nv_bfloat16 h = __float2bfloat16(o);
            hi[base + i] = h;
            lo[base + i] = __float2bfloat16(o - __bfloat162float(h));
        }
    }
}

// ======================= host orchestration =======================
extern "C" void kernel_launch(void* const* d_in, const int* in_sizes, int n_in,
                              void* d_out, int out_size)
{
    const float* x  = (const float*)d_in[0];
    const void*  ei = d_in[1];
    const int N = in_sizes[0] / 128;
    const int E = in_sizes[1] / 2;

    const float* P[24];
    for (int i = 0; i < 24; i++) P[i] = (const float*)d_in[2 + i];

    float *q, *k, *v, *h0, *h1, *biasf;
    __nv_bfloat16 *ahi, *alo, *whi, *wlo;
    int *rowptr, *cnt, *cur, *srcs;
    cudaGetSymbolAddress((void**)&q,  g_q);
    cudaGetSymbolAddress((void**)&k,  g_k);
    cudaGetSymbolAddress((void**)&v,  g_v);
    cudaGetSymbolAddress((void**)&h0, g_h0);
    cudaGetSymbolAddress((void**)&h1, g_h1);
    cudaGetSymbolAddress((void**)&ahi, g_ahi);
    cudaGetSymbolAddress((void**)&alo, g_alo);
    cudaGetSymbolAddress((void**)&whi, g_whi);
    cudaGetSymbolAddress((void**)&wlo, g_wlo);
    cudaGetSymbolAddress((void**)&biasf, g_biasf);
    cudaGetSymbolAddress((void**)&rowptr, g_rowptr);
    cudaGetSymbolAddress((void**)&cnt, g_cnt);
    cudaGetSymbolAddress((void**)&cur, g_cur);
    cudaGetSymbolAddress((void**)&srcs, g_srcs);

    cudaFuncSetAttribute(gemm_mma_kernel, cudaFuncAttributeMaxDynamicSharedMemorySize, SMEM_TOT);

    // side stream + events (created once; never allocates device memory)
    static cudaStream_t s2 = nullptr;
    static cudaEvent_t evA = nullptr, evB = nullptr;
    if (!s2) {
        cudaStreamCreateWithFlags(&s2, cudaStreamNonBlocking);
        cudaEventCreateWithFlags(&evA, cudaEventDisableTiming);
        cudaEventCreateWithFlags(&evB, cudaEventDisableTiming);
    }

    const int TB = 256;
    float* out = (float*)d_out;

    WTable wt;
    const int Ks[3] = {128, 512, 512};
    const int Ms[3] = {512, 512, 64};
    for (int l = 0; l < 3; l++)
        for (int j = 0; j < 4; j++) {
            wt.d[l * 4 + j].W = P[l * 8 + j * 2];
            wt.d[l * 4 + j].b = P[l * 8 + j * 2 + 1];
            wt.d[l * 4 + j].K = Ks[l];
            wt.d[l * 4 + j].M = Ms[l];
            wt.d[l * 4 + j].layer = l;
            wt.d[l * 4 + j].off = j * Ms[l];
        }

    // ---- fork: CSR build on s2, GEMM prep/compute on main stream ----
    detect_kernel<<<1, 1>>>((const int*)ei);
    cudaEventRecord(evA, 0);
    cudaStreamWaitEvent(s2, evA, 0);
    zero_int_kernel<<<(N + TB - 1) / TB, TB, 0, s2>>>(cnt, N);
    hist_kernel<<<(E + TB - 1) / TB, TB, 0, s2>>>(ei, cnt, E);
    scan_kernel<<<1, 1024, 0, s2>>>(cnt, rowptr, cur, N);
    scatter_kernel<<<(E + TB - 1) / TB, TB, 0, s2>>>(ei, cur, srcs, E);
    cudaEventRecord(evB, s2);

    prep_weights_kernel<<<dim3(64, 12), TB>>>(wt, whi, wlo, biasf);
    split_act_kernel<<<(N * 128 + TB - 1) / TB, TB>>>(x, ahi, alo, N * 128);

    const int mtiles = (N + 127) / 128;
    OutSpec os0; os0.out[0] = q; os0.out[1] = k; os0.out[2] = v; os0.out[3] = h0; os0.cpo = 512;
    gemm_mma_kernel<<<dim3(2048 / 128, mtiles), 256, SMEM_TOT>>>(
        ahi, alo, whi, wlo, biasf, os0, N, 128);

    cudaStreamWaitEvent(0, evB, 0);   // CSR ready before aggregation

    const int aggBlocks = (N + 7) / 8;
    gat_agg_kernel<8, 64, true, true><<<aggBlocks, 256>>>(
        q, k, v, rowptr, srcs, h0, ahi, alo, N);

    // ---- layer 1 ----
    OutSpec os1; os1.out[0] = q; os1.out[1] = k; os1.out[2] = v; os1.out[3] = h1; os1.cpo = 512;
    gemm_mma_kernel<<<dim3(2048 / 128, mtiles), 256, SMEM_TOT>>>(
        ahi, alo, whi + (size_t)1 * NTOTMAX * KMAX, wlo + (size_t)1 * NTOTMAX * KMAX,
        biasf + NTOTMAX, os1, N, 512);
    gat_agg_kernel<8, 64, true, true><<<aggBlocks, 256>>>(
        q, k, v, rowptr, srcs, h1, ahi, alo, N);

    // ---- layer 2 (heads=1, ch=64) ----
    OutSpec os2; os2.out[0] = q; os2.out[1] = k; os2.out[2] = v; os2.out[3] = out; os2.cpo = 64;
    gemm_mma_kernel<<<dim3(256 / 128, mtiles), 256, SMEM_TOT>>>(
        ahi, alo, whi + (size_t)2 * NTOTMAX * KMAX, wlo + (size_t)2 * NTOTMAX * KMAX,
        biasf + 2 * NTOTMAX, os2, N, 512);
    gat_agg_kernel<1, 64, false, false><<<aggBlocks, 256>>>(
        q, k, v, rowptr, srcs, out, nullptr, nullptr, N);
}

// round 6
// speedup vs baseline: 1.9408x; 1.1318x over previous
#include <cuda_runtime.h>
#include <cuda_bf16.h>
#include <cuda_fp16.h>
#include <cstdint>

#define NMAX 50000
#define EMAX 800000
#define KMAX 512
#define NTOTMAX 2048

// ======================= low-level helpers (sm_80-compatible PTX) ==========
__device__ __forceinline__ uint32_t smem_u32(const void* p) {
    uint32_t a;
    asm("{ .reg .u64 t; cvta.to.shared.u64 t, %1; cvt.u32.u64 %0, t; }" : "=r"(a) : "l"(p));
    return a;
}
__device__ __forceinline__ void cp16(uint32_t dst, const void* src, int srcsize) {
    asm volatile("cp.async.cg.shared.global [%0], [%1], 16, %2;"
                 :: "r"(dst), "l"(src), "r"(srcsize));
}
__device__ __forceinline__ void ldm_x4(uint32_t& r0, uint32_t& r1, uint32_t& r2, uint32_t& r3,
                                       uint32_t addr) {
    asm volatile("ldmatrix.sync.aligned.m8n8.x4.shared.b16 {%0,%1,%2,%3}, [%4];"
                 : "=r"(r0), "=r"(r1), "=r"(r2), "=r"(r3) : "r"(addr));
}
__device__ __forceinline__ void mma16816(float* c, const uint32_t* a, const uint32_t* b) {
    asm volatile("mma.sync.aligned.m16n8k16.row.col.f32.bf16.bf16.f32 "
                 "{%0,%1,%2,%3}, {%4,%5,%6,%7}, {%8,%9}, {%0,%1,%2,%3};"
                 : "+f"(c[0]), "+f"(c[1]), "+f"(c[2]), "+f"(c[3])
                 : "r"(a[0]), "r"(a[1]), "r"(a[2]), "r"(a[3]), "r"(b[0]), "r"(b[1]));
}

// ======================= scratch (device globals) =======================
__device__ float  g_q [NMAX * 512];
__device__ __half g_kh[NMAX * 512];
__device__ __half g_vh[NMAX * 512];
__device__ float  g_h0[NMAX * 512];
__device__ float  g_h1[NMAX * 512];
__device__ __nv_bfloat16 g_ahi[NMAX * KMAX];
__device__ __nv_bfloat16 g_alo[NMAX * KMAX];
__device__ __nv_bfloat16 g_whi[3 * NTOTMAX * KMAX];
__device__ __nv_bfloat16 g_wlo[3 * NTOTMAX * KMAX];
__device__ float g_biasf[3 * NTOTMAX];
__device__ int   g_rowptr[NMAX + 1];
__device__ int   g_cnt[NMAX];
__device__ int   g_cur[NMAX];
__device__ int   g_srcs[EMAX];
__device__ int   g_is64;

// ======================= edge dtype detection =======================
__global__ void detect_kernel(const int* __restrict__ w) {
    int odd_nonzero = 0;
    for (int i = 0; i < 128; i++) odd_nonzero += (w[2 * i + 1] != 0);
    g_is64 = (odd_nonzero == 0) ? 1 : 0;
}
__device__ __forceinline__ int edge_at(const void* ei, long long idx, int is64) {
    return is64 ? (int)((const long long*)ei)[idx] : ((const int*)ei)[idx];
}

// ======================= CSR build =======================
__global__ void zero_int_kernel(int* __restrict__ p, int n) {
    int i = blockIdx.x * blockDim.x + threadIdx.x;
    if (i < n) p[i] = 0;
}
__global__ void hist_kernel(const void* __restrict__ ei, int* __restrict__ cnt, int E) {
    int e = blockIdx.x * blockDim.x + threadIdx.x;
    if (e < E) atomicAdd(&cnt[edge_at(ei, (long long)E + e, g_is64)], 1);
}
__global__ void scan_kernel(const int* __restrict__ cnt, int* __restrict__ rowptr,
                            int* __restrict__ cur, int n) {
    __shared__ int part[1024];
    const int t = threadIdx.x;
    const int chunk = (n + 1023) >> 10;
    int b = t * chunk; if (b > n) b = n;
    int e = b + chunk; if (e > n) e = n;
    int s = 0;
    for (int i = b; i < e; i++) s += cnt[i];
    part[t] = s;
    __syncthreads();
    if (t == 0) {
        int a = 0;
        for (int i = 0; i < 1024; i++) { int v = part[i]; part[i] = a; a += v; }
    }
    __syncthreads();
    int off = part[t];
    for (int i = b; i < e; i++) { rowptr[i] = off; cur[i] = off; off += cnt[i]; }
    if (t == 1023) rowptr[n] = off;
}
__global__ void scatter_kernel(const void* __restrict__ ei, int* __restrict__ cur,
                               int* __restrict__ srcs, int E) {
    int e = blockIdx.x * blockDim.x + threadIdx.x;
    if (e < E) {
        const int is64 = g_is64;
        int d = edge_at(ei, (long long)E + e, is64);
        int p = atomicAdd(&cur[d], 1);
        srcs[p] = edge_at(ei, e, is64);
    }
}

// ======================= weight prep: transpose + hi/lo split ==============
struct WDesc { const float* W; const float* b; int K; int M; int layer; int off; };
struct WTable { WDesc d[12]; };

__global__ void prep_weights_kernel(WTable t, __nv_bfloat16* __restrict__ whi,
                                    __nv_bfloat16* __restrict__ wlo, float* __restrict__ biasf) {
    const WDesc w = t.d[blockIdx.y];
    const size_t base = (size_t)w.layer * NTOTMAX * KMAX;
    const int stride = gridDim.x * blockDim.x;
    for (int i = blockIdx.x * blockDim.x + threadIdx.x; i < w.M; i += stride)
        biasf[w.layer * NTOTMAX + w.off + i] = w.b[i];
    const int total = w.K * w.M;
    for (int i = blockIdx.x * blockDim.x + threadIdx.x; i < total; i += stride) {
        int k = i / w.M, m = i % w.M;
        float v = w.W[i];
        __nv_bfloat16 hi = __float2bfloat16(v);
        float lo = v - __bfloat162float(hi);
        size_t dst = base + (size_t)(w.off + m) * w.K + k;
        whi[dst] = hi;
        wlo[dst] = __float2bfloat16(lo);
    }
}

// ======================= activation hi/lo split (input x only) =============
__global__ void split_act_kernel(const float* __restrict__ x, __nv_bfloat16* __restrict__ hi,
                                 __nv_bfloat16* __restrict__ lo, int total) {
    int i = blockIdx.x * blockDim.x + threadIdx.x;
    if (i < total) {
        float v = x[i];
        __nv_bfloat16 h = __float2bfloat16(v);
        hi[i] = h;
        lo[i] = __float2bfloat16(v - __bfloat162float(h));
    }
}

// ======================= HMMA GEMM: C[N, ntot] = A @ Wt^T + bias ===========
// 3-pass bf16 split in register accumulators: Ahi*Bhi + Ahi*Blo + Alo*Bhi
// CTA tile 128x128, BK=32, 8 warps (2x4), warp tile 64x32, 4-stage cp.async.
// Output slots can be fp32 or fp16 (half_mask).
#define STAGES 4
#define STG_BYTES 10240                 /* 128 rows * 80B padded */
#define SMEM_TOT  (2 * STAGES * STG_BYTES)   /* 81920 */

struct OutSpec { void* out[4]; int half_mask; int cpo; };

__global__ void __launch_bounds__(256, 2)
gemm_mma_kernel(const __nv_bfloat16* __restrict__ Ahi, const __nv_bfloat16* __restrict__ Alo,
                const __nv_bfloat16* __restrict__ Whi, const __nv_bfloat16* __restrict__ Wlo,
                const float* __restrict__ biasf, OutSpec os, int Nrows, int K)
{
    extern __shared__ char smem[];
    const uint32_t sb = smem_u32(smem);
    const int tid = threadIdx.x, lane = tid & 31, wid = tid >> 5;
    const int wm = wid & 1, wn = wid >> 1;
    const int m0 = blockIdx.y * 128, n0 = blockIdx.x * 128;
    const int KT = K / 32, TOT = 3 * KT;

    float acc[4][4][4];
#pragma unroll
    for (int a = 0; a < 4; a++)
#pragma unroll
        for (int b = 0; b < 4; b++)
#pragma unroll
            for (int c = 0; c < 4; c++) acc[a][b][c] = 0.f;

    const int r0 = tid >> 2, c0 = tid & 3;
    const int r1 = (tid + 256) >> 2, c1 = (tid + 256) & 3;

    auto issue = [&](int kt) {
        const int slot = kt % STAGES;
        const int p = kt / KT;
        const __nv_bfloat16* A = (p == 2) ? Alo : Ahi;
        const __nv_bfloat16* B = (p == 1) ? Wlo : Whi;
        const int koff = (kt - p * KT) * 32;
        const uint32_t sA = sb + slot * STG_BYTES;
        const uint32_t sB = sb + STAGES * STG_BYTES + slot * STG_BYTES;
        int ar0 = m0 + r0; bool v0 = ar0 < Nrows; if (!v0) ar0 = 0;
        int ar1 = m0 + r1; bool v1 = ar1 < Nrows; if (!v1) ar1 = 0;
        cp16(sA + r0 * 80 + c0 * 16, A + (size_t)ar0 * K + koff + c0 * 8, v0 ? 16 : 0);
        cp16(sA + r1 * 80 + c1 * 16, A + (size_t)ar1 * K + koff + c1 * 8, v1 ? 16 : 0);
        cp16(sB + r0 * 80 + c0 * 16, B + (size_t)(n0 + r0) * K + koff + c0 * 8, 16);
        cp16(sB + r1 * 80 + c1 * 16, B + (size_t)(n0 + r1) * K + koff + c1 * 8, 16);
    };

    const uint32_t aB = sb + (wm * 64 + (lane & 15)) * 80 + (lane >> 4) * 16;
    const uint32_t bB = sb + STAGES * STG_BYTES
                      + (wn * 32 + (lane & 7) + ((lane >> 4) << 3)) * 80
                      + ((lane >> 3) & 1) * 16;

    issue(0); asm volatile("cp.async.commit_group;" ::: "memory");
    issue(1); asm volatile("cp.async.commit_group;" ::: "memory");
    issue(2); asm volatile("cp.async.commit_group;" ::: "memory");

    for (int kt = 0; kt < TOT; kt++) {
        asm volatile("cp.async.wait_group 2;" ::: "memory");
        __syncthreads();
        if (kt + 3 < TOT) issue(kt + 3);
        asm volatile("cp.async.commit_group;" ::: "memory");

        const uint32_t sOff = (uint32_t)(kt % STAGES) * STG_BYTES;
#pragma unroll
        for (int ks = 0; ks < 2; ks++) {
            uint32_t a[4][4], b[2][4];
#pragma unroll
            for (int mi = 0; mi < 4; mi++)
                ldm_x4(a[mi][0], a[mi][1], a[mi][2], a[mi][3],
                       aB + sOff + mi * 16 * 80 + ks * 32);
#pragma unroll
            for (int nj = 0; nj < 2; nj++)
                ldm_x4(b[nj][0], b[nj][1], b[nj][2], b[nj][3],
                       bB + sOff + nj * 16 * 80 + ks * 32);
#pragma unroll
            for (int mi = 0; mi < 4; mi++)
#pragma unroll
                for (int ni = 0; ni < 4; ni++)
                    mma16816(acc[mi][ni], a[mi], &b[ni >> 1][(ni & 1) * 2]);
        }
    }

    const int erow = lane >> 2, ecol = (lane & 3) * 2;
#pragma unroll
    for (int mi = 0; mi < 4; mi++) {
#pragma unroll
        for (int half = 0; half < 2; half++) {
            const int gr = m0 + wm * 64 + mi * 16 + erow + half * 8;
            if (gr >= Nrows) continue;
#pragma unroll
            for (int ni = 0; ni < 4; ni++) {
                const int gc = n0 + wn * 32 + ni * 8 + ecol;
                const int slot = gc / os.cpo;
                const int loc  = gc % os.cpo;
                float ox = acc[mi][ni][half * 2 + 0] + biasf[gc + 0];
                float oy = acc[mi][ni][half * 2 + 1] + biasf[gc + 1];
                if (os.half_mask & (1 << slot)) {
                    __half2 h2 = __floats2half2_rn(ox, oy);
                    *reinterpret_cast<__half2*>((__half*)os.out[slot] + (size_t)gr * os.cpo + loc) = h2;
                } else {
                    float2 o = make_float2(ox, oy);
                    *reinterpret_cast<float2*>((float*)os.out[slot] + (size_t)gr * os.cpo + loc) = o;
                }
            }
        }
    }
}

// ======================= per-node attention aggregation =======================
template<int PER>
__device__ __forceinline__ void vloadf(float* r, const float* __restrict__ p) {
#pragma unroll
    for (int i = 0; i < PER / 2; i++) {
        float2 t = reinterpret_cast<const float2*>(p)[i];
        r[2 * i + 0] = t.x; r[2 * i + 1] = t.y;
    }
}
template<int PER>
__device__ __forceinline__ void vloadh(float* r, const __half* __restrict__ p) {
    if constexpr (PER % 8 == 0) {
#pragma unroll
        for (int i = 0; i < PER / 8; i++) {
            uint4 t = reinterpret_cast<const uint4*>(p)[i];
            const __half2* h = reinterpret_cast<const __half2*>(&t);
#pragma unroll
            for (int j = 0; j < 4; j++) {
                float2 f = __half22float2(h[j]);
                r[i * 8 + j * 2 + 0] = f.x;
                r[i * 8 + j * 2 + 1] = f.y;
            }
        }
    } else {
        float2 f = __half22float2(*reinterpret_cast<const __half2*>(p));
        r[0] = f.x; r[1] = f.y;
    }
}

// One warp per destination node; 2-edge software pipelining; online softmax.
// K/V gathered in fp16. Optionally fuses bf16 hi/lo split into the epilogue.
template<int HEADS, int CH, bool RELU, bool SPLIT>
__global__ void __launch_bounds__(256)
gat_agg_kernel(const float* __restrict__ Q, const __half* __restrict__ Kf,
               const __half* __restrict__ V,
               const int* __restrict__ rowptr, const int* __restrict__ srcs,
               float* __restrict__ out,
               __nv_bfloat16* __restrict__ hi, __nv_bfloat16* __restrict__ lo, int n)
{
    constexpr int NCH = HEADS * CH;
    constexpr int PER = NCH / 32;
    constexpr int RW  = CH / PER;
    const int lane = threadIdx.x & 31;
    const int node = blockIdx.x * (blockDim.x >> 5) + (threadIdx.x >> 5);
    if (node >= n) return;

    const float scale = rsqrtf((float)CH);
    const size_t base = (size_t)node * NCH + lane * PER;

    float qv[PER], acc[PER];
    vloadf<PER>(qv, Q + base);
#pragma unroll
    for (int i = 0; i < PER; i++) acc[i] = 0.f;

    float m = __int_as_float(0xff800000);
    float s = 0.f;

    const int e0 = rowptr[node];
    const int e1 = rowptr[node + 1];
    int e = e0;
    for (; e + 2 <= e1; e += 2) {
        const int s0 = srcs[e], s1 = srcs[e + 1];
        const size_t b0 = (size_t)s0 * NCH + lane * PER;
        const size_t b1 = (size_t)s1 * NCH + lane * PER;
        float k0[PER], v0[PER], k1[PER], v1[PER];
        vloadh<PER>(k0, Kf + b0);
        vloadh<PER>(k1, Kf + b1);
        vloadh<PER>(v0, V  + b0);
        vloadh<PER>(v1, V  + b1);

        float p0 = 0.f, p1 = 0.f;
#pragma unroll
        for (int i = 0; i < PER; i++) { p0 = fmaf(qv[i], k0[i], p0); p1 = fmaf(qv[i], k1[i], p1); }
#pragma unroll
        for (int off = RW >> 1; off > 0; off >>= 1) {
            p0 += __shfl_xor_sync(0xffffffffu, p0, off);
            p1 += __shfl_xor_sync(0xffffffffu, p1, off);
        }
        const float a0 = p0 * scale, a1 = p1 * scale;
        const float mn = fmaxf(m, fmaxf(a0, a1));
        const float corr = __expf(m - mn);
        const float w0 = __expf(a0 - mn);
        const float w1 = __expf(a1 - mn);
        s = s * corr + w0 + w1;
#pragma unroll
        for (int i = 0; i < PER; i++)
            acc[i] = fmaf(acc[i], corr, fmaf(w0, v0[i], w1 * v1[i]));
        m = mn;
    }
    if (e < e1) {
        const int sn = srcs[e];
        const size_t sbx = (size_t)sn * NCH + lane * PER;
        float kv[PER], vv[PER];
        vloadh<PER>(kv, Kf + sbx);
        vloadh<PER>(vv, V  + sbx);
        float part = 0.f;
#pragma unroll
        for (int i = 0; i < PER; i++) part = fmaf(qv[i], kv[i], part);
#pragma unroll
        for (int off = RW >> 1; off > 0; off >>= 1)
            part += __shfl_xor_sync(0xffffffffu, part, off);
        const float alpha = part * scale;
        const float mn = fmaxf(m, alpha);
        const float corr = __expf(m - mn);
        const float w = __expf(alpha - mn);
        s = s * corr + w;
#pragma unroll
        for (int i = 0; i < PER; i++) acc[i] = fmaf(acc[i], corr, w * vv[i]);
        m = mn;
    }

    const float inv = 1.f / (s + 1e-16f);
#pragma unroll
    for (int i = 0; i < PER; i++) {
        float o = out[base + i] + acc[i] * inv;
        if (RELU) o = fmaxf(o, 0.f);
        out[base + i] = o;
        if (SPLIT) {
            __nv_bfloat16 h = __float2bfloat16(o);
            hi[base + i] = h;
            lo[base + i] = __float2bfloat16(o - __bfloat162float(h));
        }
    }
}

// ======================= host orchestration =======================
extern "C" void kernel_launch(void* const* d_in, const int* in_sizes, int n_in,
                              void* d_out, int out_size)
{
    const float* x  = (const float*)d_in[0];
    const void*  ei = d_in[1];
    const int N = in_sizes[0] / 128;
    const int E = in_sizes[1] / 2;

    const float* P[24];
    for (int i = 0; i < 24; i++) P[i] = (const float*)d_in[2 + i];

    float *q, *h0, *h1, *biasf;
    __half *kh, *vh;
    __nv_bfloat16 *ahi, *alo, *whi, *wlo;
    int *rowptr, *cnt, *cur, *srcs;
    cudaGetSymbolAddress((void**)&q,  g_q);
    cudaGetSymbolAddress((void**)&kh, g_kh);
    cudaGetSymbolAddress((void**)&vh, g_vh);
    cudaGetSymbolAddress((void**)&h0, g_h0);
    cudaGetSymbolAddress((void**)&h1, g_h1);
    cudaGetSymbolAddress((void**)&ahi, g_ahi);
    cudaGetSymbolAddress((void**)&alo, g_alo);
    cudaGetSymbolAddress((void**)&whi, g_whi);
    cudaGetSymbolAddress((void**)&wlo, g_wlo);
    cudaGetSymbolAddress((void**)&biasf, g_biasf);
    cudaGetSymbolAddress((void**)&rowptr, g_rowptr);
    cudaGetSymbolAddress((void**)&cnt, g_cnt);
    cudaGetSymbolAddress((void**)&cur, g_cur);
    cudaGetSymbolAddress((void**)&srcs, g_srcs);

    cudaFuncSetAttribute(gemm_mma_kernel, cudaFuncAttributeMaxDynamicSharedMemorySize, SMEM_TOT);

    // side stream + events (created once; never allocates device memory)
    static cudaStream_t s2 = nullptr;
    static cudaEvent_t evA = nullptr, evB = nullptr;
    if (!s2) {
        cudaStreamCreateWithFlags(&s2, cudaStreamNonBlocking);
        cudaEventCreateWithFlags(&evA, cudaEventDisableTiming);
        cudaEventCreateWithFlags(&evB, cudaEventDisableTiming);
    }

    const int TB = 256;
    float* out = (float*)d_out;

    WTable wt;
    const int Ks[3] = {128, 512, 512};
    const int Ms[3] = {512, 512, 64};
    for (int l = 0; l < 3; l++)
        for (int j = 0; j < 4; j++) {
            wt.d[l * 4 + j].W = P[l * 8 + j * 2];
            wt.d[l * 4 + j].b = P[l * 8 + j * 2 + 1];
            wt.d[l * 4 + j].K = Ks[l];
            wt.d[l * 4 + j].M = Ms[l];
            wt.d[l * 4 + j].layer = l;
            wt.d[l * 4 + j].off = j * Ms[l];
        }

    // ---- fork: CSR build on s2, GEMM prep/compute on main stream ----
    detect_kernel<<<1, 1>>>((const int*)ei);
    cudaEventRecord(evA, 0);
    cudaStreamWaitEvent(s2, evA, 0);
    zero_int_kernel<<<(N + TB - 1) / TB, TB, 0, s2>>>(cnt, N);
    hist_kernel<<<(E + TB - 1) / TB, TB, 0, s2>>>(ei, cnt, E);
    scan_kernel<<<1, 1024, 0, s2>>>(cnt, rowptr, cur, N);
    scatter_kernel<<<(E + TB - 1) / TB, TB, 0, s2>>>(ei, cur, srcs, E);
    cudaEventRecord(evB, s2);

    prep_weights_kernel<<<dim3(64, 12), TB>>>(wt, whi, wlo, biasf);
    split_act_kernel<<<(N * 128 + TB - 1) / TB, TB>>>(x, ahi, alo, N * 128);

    const int mtiles = (N + 127) / 128;
    OutSpec os0;
    os0.out[0] = q; os0.out[1] = kh; os0.out[2] = vh; os0.out[3] = h0;
    os0.half_mask = 0b0110; os0.cpo = 512;
    gemm_mma_kernel<<<dim3(2048 / 128, mtiles), 256, SMEM_TOT>>>(
        ahi, alo, whi, wlo, biasf, os0, N, 128);

    cudaStreamWaitEvent(0, evB, 0);   // CSR ready before aggregation

    const int aggBlocks = (N + 7) / 8;
    gat_agg_kernel<8, 64, true, true><<<aggBlocks, 256>>>(
        q, kh, vh, rowptr, srcs, h0, ahi, alo, N);

    // ---- layer 1 ----
    OutSpec os1;
    os1.out[0] = q; os1.out[1] = kh; os1.out[2] = vh; os1.out[3] = h1;
    os1.half_mask = 0b0110; os1.cpo = 512;
    gemm_mma_kernel<<<dim3(2048 / 128, mtiles), 256, SMEM_TOT>>>(
        ahi, alo, whi + (size_t)1 * NTOTMAX * KMAX, wlo + (size_t)1 * NTOTMAX * KMAX,
        biasf + NTOTMAX, os1, N, 512);
    gat_agg_kernel<8, 64, true, true><<<aggBlocks, 256>>>(
        q, kh, vh, rowptr, srcs, h1, ahi, alo, N);

    // ---- layer 2 (heads=1, ch=64) ----
    OutSpec os2;
    os2.out[0] = q; os2.out[1] = kh; os2.out[2] = vh; os2.out[3] = out;
    os2.half_mask = 0b0110; os2.cpo = 64;
    gemm_mma_kernel<<<dim3(256 / 128, mtiles), 256, SMEM_TOT>>>(
        ahi, alo, whi + (size_t)2 * NTOTMAX * KMAX, wlo + (size_t)2 * NTOTMAX * KMAX,
        biasf + 2 * NTOTMAX, os2, N, 512);
    gat_agg_kernel<1, 64, false, false><<<aggBlocks, 256>>>(
        q, kh, vh, rowptr, srcs, out, nullptr, nullptr, N);
}

// round 7
// speedup vs baseline: 2.0350x; 1.0485x over previous
#include <cuda_runtime.h>
#include <cuda_bf16.h>
#include <cuda_fp16.h>
#include <cstdint>

#define NMAX 50000
#define EMAX 800000
#define KMAX 512
#define NTOTMAX 2048

// ======================= low-level helpers (sm_80-compatible PTX) ==========
__device__ __forceinline__ uint32_t smem_u32(const void* p) {
    uint32_t a;
    asm("{ .reg .u64 t; cvta.to.shared.u64 t, %1; cvt.u32.u64 %0, t; }" : "=r"(a) : "l"(p));
    return a;
}
__device__ __forceinline__ void cp16(uint32_t dst, const void* src, int srcsize) {
    asm volatile("cp.async.cg.shared.global [%0], [%1], 16, %2;"
                 :: "r"(dst), "l"(src), "r"(srcsize));
}
__device__ __forceinline__ void ldm_x4(uint32_t& r0, uint32_t& r1, uint32_t& r2, uint32_t& r3,
                                       uint32_t addr) {
    asm volatile("ldmatrix.sync.aligned.m8n8.x4.shared.b16 {%0,%1,%2,%3}, [%4];"
                 : "=r"(r0), "=r"(r1), "=r"(r2), "=r"(r3) : "r"(addr));
}
__device__ __forceinline__ void mma16816(float* c, const uint32_t* a, const uint32_t* b) {
    asm volatile("mma.sync.aligned.m16n8k16.row.col.f32.bf16.bf16.f32 "
                 "{%0,%1,%2,%3}, {%4,%5,%6,%7}, {%8,%9}, {%0,%1,%2,%3};"
                 : "+f"(c[0]), "+f"(c[1]), "+f"(c[2]), "+f"(c[3])
                 : "r"(a[0]), "r"(a[1]), "r"(a[2]), "r"(a[3]), "r"(b[0]), "r"(b[1]));
}

// ======================= scratch (device globals) =======================
__device__ float  g_q [NMAX * 512];
__device__ __half g_kh[NMAX * 512];
__device__ __half g_vh[NMAX * 512];
__device__ float  g_h0[NMAX * 512];
__device__ float  g_h1[NMAX * 512];
__device__ __nv_bfloat16 g_ahi[NMAX * KMAX];
__device__ __nv_bfloat16 g_alo[NMAX * KMAX];
__device__ __nv_bfloat16 g_whi[3 * NTOTMAX * KMAX];
__device__ __nv_bfloat16 g_wlo[3 * NTOTMAX * KMAX];
__device__ float g_biasf[3 * NTOTMAX];
__device__ int   g_rowptr[NMAX + 1];
__device__ int   g_cnt[NMAX];
__device__ int   g_cur[NMAX];
__device__ int   g_srcs[EMAX];
__device__ int   g_is64;

// ======================= edge dtype detection =======================
__global__ void detect_kernel(const int* __restrict__ w) {
    int odd_nonzero = 0;
    for (int i = 0; i < 128; i++) odd_nonzero += (w[2 * i + 1] != 0);
    g_is64 = (odd_nonzero == 0) ? 1 : 0;
}
__device__ __forceinline__ int edge_at(const void* ei, long long idx, int is64) {
    return is64 ? (int)((const long long*)ei)[idx] : ((const int*)ei)[idx];
}

// ======================= CSR build =======================
__global__ void zero_int_kernel(int* __restrict__ p, int n) {
    int i = blockIdx.x * blockDim.x + threadIdx.x;
    if (i < n) p[i] = 0;
}
__global__ void hist_kernel(const void* __restrict__ ei, int* __restrict__ cnt, int E) {
    int e = blockIdx.x * blockDim.x + threadIdx.x;
    if (e < E) atomicAdd(&cnt[edge_at(ei, (long long)E + e, g_is64)], 1);
}
__global__ void scan_kernel(const int* __restrict__ cnt, int* __restrict__ rowptr,
                            int* __restrict__ cur, int n) {
    __shared__ int part[1024];
    const int t = threadIdx.x;
    const int chunk = (n + 1023) >> 10;
    int b = t * chunk; if (b > n) b = n;
    int e = b + chunk; if (e > n) e = n;
    int s = 0;
    for (int i = b; i < e; i++) s += cnt[i];
    part[t] = s;
    __syncthreads();
    if (t == 0) {
        int a = 0;
        for (int i = 0; i < 1024; i++) { int v = part[i]; part[i] = a; a += v; }
    }
    __syncthreads();
    int off = part[t];
    for (int i = b; i < e; i++) { rowptr[i] = off; cur[i] = off; off += cnt[i]; }
    if (t == 1023) rowptr[n] = off;
}
__global__ void scatter_kernel(const void* __restrict__ ei, int* __restrict__ cur,
                               int* __restrict__ srcs, int E) {
    int e = blockIdx.x * blockDim.x + threadIdx.x;
    if (e < E) {
        const int is64 = g_is64;
        int d = edge_at(ei, (long long)E + e, is64);
        int p = atomicAdd(&cur[d], 1);
        srcs[p] = edge_at(ei, e, is64);
    }
}

// ======================= weight prep: transpose + hi/lo split ==============
struct WDesc { const float* W; const float* b; int K; int M; int layer; int off; };
struct WTable { WDesc d[12]; };

__global__ void prep_weights_kernel(WTable t, __nv_bfloat16* __restrict__ whi,
                                    __nv_bfloat16* __restrict__ wlo, float* __restrict__ biasf) {
    const WDesc w = t.d[blockIdx.y];
    const size_t base = (size_t)w.layer * NTOTMAX * KMAX;
    const int stride = gridDim.x * blockDim.x;
    for (int i = blockIdx.x * blockDim.x + threadIdx.x; i < w.M; i += stride)
        biasf[w.layer * NTOTMAX + w.off + i] = w.b[i];
    const int total = w.K * w.M;
    for (int i = blockIdx.x * blockDim.x + threadIdx.x; i < total; i += stride) {
        int k = i / w.M, m = i % w.M;
        float v = w.W[i];
        __nv_bfloat16 hi = __float2bfloat16(v);
        float lo = v - __bfloat162float(hi);
        size_t dst = base + (size_t)(w.off + m) * w.K + k;
        whi[dst] = hi;
        wlo[dst] = __float2bfloat16(lo);
    }
}

// ======================= activation hi/lo split (input x only) =============
__global__ void split_act_kernel(const float* __restrict__ x, __nv_bfloat16* __restrict__ hi,
                                 __nv_bfloat16* __restrict__ lo, int total) {
    int i = blockIdx.x * blockDim.x + threadIdx.x;
    if (i < total) {
        float v = x[i];
        __nv_bfloat16 h = __float2bfloat16(v);
        hi[i] = h;
        lo[i] = __float2bfloat16(v - __bfloat162float(h));
    }
}

// ======================= HMMA GEMM: C[N, ntot] = A @ Wt^T + bias ===========
// 3-pass bf16 split in register accumulators: Ahi*Bhi + Alo*Bhi + Ahi*Blo
// kc-outer / pass-inner: per K-chunk load 4 tiles (Ahi,Alo,Bhi,Blo) into
// dedicated double-buffered regions; one wait+sync per chunk; explicit reuse.
// CTA tile 128x128, BK=32, 8 warps (2x4), warp tile 64x32.
#define STG_BYTES 10240                 /* 128 rows * 80B padded */
#define SMEM_TOT  (8 * STG_BYTES)       /* 4 tensors x 2 slots = 81920 */

struct OutSpec { void* out[4]; int half_mask; int cpo; };

__global__ void __launch_bounds__(256, 2)
gemm_mma_kernel(const __nv_bfloat16* __restrict__ Ahi, const __nv_bfloat16* __restrict__ Alo,
                const __nv_bfloat16* __restrict__ Whi, const __nv_bfloat16* __restrict__ Wlo,
                const float* __restrict__ biasf, OutSpec os, int Nrows, int K)
{
    extern __shared__ char smem[];
    const uint32_t sb = smem_u32(smem);
    const int tid = threadIdx.x, lane = tid & 31, wid = tid >> 5;
    const int wm = wid & 1, wn = wid >> 1;
    const int m0 = blockIdx.y * 128, n0 = blockIdx.x * 128;
    const int KT = K / 32;

    float acc[4][4][4];
#pragma unroll
    for (int a = 0; a < 4; a++)
#pragma unroll
        for (int b = 0; b < 4; b++)
#pragma unroll
            for (int c = 0; c < 4; c++) acc[a][b][c] = 0.f;

    const int r0 = tid >> 2, c0 = tid & 3;
    const int r1 = r0 + 64;

    // region(tensor, slot) base: tensor 0=Ahi 1=Alo 2=Bhi 3=Blo
    auto issueKC = [&](int kc) {
        const int slot = kc & 1;
        const int koff = kc * 32;
        int ar0 = m0 + r0; bool v0 = ar0 < Nrows; if (!v0) ar0 = 0;
        int ar1 = m0 + r1; bool v1 = ar1 < Nrows; if (!v1) ar1 = 0;
        const uint32_t sAhi = sb + (0 * 2 + slot) * STG_BYTES;
        const uint32_t sAlo = sb + (1 * 2 + slot) * STG_BYTES;
        const uint32_t sBhi = sb + (2 * 2 + slot) * STG_BYTES;
        const uint32_t sBlo = sb + (3 * 2 + slot) * STG_BYTES;
        const uint32_t ro0 = r0 * 80 + c0 * 16, ro1 = r1 * 80 + c0 * 16;
        cp16(sAhi + ro0, Ahi + (size_t)ar0 * K + koff + c0 * 8, v0 ? 16 : 0);
        cp16(sAhi + ro1, Ahi + (size_t)ar1 * K + koff + c0 * 8, v1 ? 16 : 0);
        cp16(sAlo + ro0, Alo + (size_t)ar0 * K + koff + c0 * 8, v0 ? 16 : 0);
        cp16(sAlo + ro1, Alo + (size_t)ar1 * K + koff + c0 * 8, v1 ? 16 : 0);
        cp16(sBhi + ro0, Whi + (size_t)(n0 + r0) * K + koff + c0 * 8, 16);
        cp16(sBhi + ro1, Whi + (size_t)(n0 + r1) * K + koff + c0 * 8, 16);
        cp16(sBlo + ro0, Wlo + (size_t)(n0 + r0) * K + koff + c0 * 8, 16);
        cp16(sBlo + ro1, Wlo + (size_t)(n0 + r1) * K + koff + c0 * 8, 16);
    };

    // per-warp ldmatrix local offsets (within a region)
    const uint32_t aLoc = (uint32_t)((wm * 64 + (lane & 15)) * 80 + (lane >> 4) * 16);
    const uint32_t bLoc = (uint32_t)((wn * 32 + (lane & 7) + ((lane >> 4) << 3)) * 80
                                     + ((lane >> 3) & 1) * 16);

    issueKC(0);
    asm volatile("cp.async.commit_group;" ::: "memory");

    for (int kc = 0; kc < KT; kc++) {
        asm volatile("cp.async.wait_group 0;" ::: "memory");
        __syncthreads();
        if (kc + 1 < KT) {
            issueKC(kc + 1);
            asm volatile("cp.async.commit_group;" ::: "memory");
        }
        const int slot = kc & 1;
#pragma unroll
        for (int pass = 0; pass < 3; pass++) {
            const int aR = (pass == 1) ? 1 : 0;     // Alo on pass 1
            const int bR = (pass == 2) ? 3 : 2;     // Blo on pass 2
            const uint32_t aBase = sb + (uint32_t)(aR * 2 + slot) * STG_BYTES + aLoc;
            const uint32_t bBase = sb + (uint32_t)(bR * 2 + slot) * STG_BYTES + bLoc;
#pragma unroll
            for (int ks = 0; ks < 2; ks++) {
                uint32_t a[4][4], b[2][4];
#pragma unroll
                for (int mi = 0; mi < 4; mi++)
                    ldm_x4(a[mi][0], a[mi][1], a[mi][2], a[mi][3],
                           aBase + mi * 16 * 80 + ks * 32);
#pragma unroll
                for (int nj = 0; nj < 2; nj++)
                    ldm_x4(b[nj][0], b[nj][1], b[nj][2], b[nj][3],
                           bBase + nj * 16 * 80 + ks * 32);
#pragma unroll
                for (int mi = 0; mi < 4; mi++)
#pragma unroll
                    for (int ni = 0; ni < 4; ni++)
                        mma16816(acc[mi][ni], a[mi], &b[ni >> 1][(ni & 1) * 2]);
            }
        }
    }

    const int erow = lane >> 2, ecol = (lane & 3) * 2;
#pragma unroll
    for (int mi = 0; mi < 4; mi++) {
#pragma unroll
        for (int half = 0; half < 2; half++) {
            const int gr = m0 + wm * 64 + mi * 16 + erow + half * 8;
            if (gr >= Nrows) continue;
#pragma unroll
            for (int ni = 0; ni < 4; ni++) {
                const int gc = n0 + wn * 32 + ni * 8 + ecol;
                const int slot = gc / os.cpo;
                const int loc  = gc % os.cpo;
                float ox = acc[mi][ni][half * 2 + 0] + biasf[gc + 0];
                float oy = acc[mi][ni][half * 2 + 1] + biasf[gc + 1];
                if (os.half_mask & (1 << slot)) {
                    __half2 h2 = __floats2half2_rn(ox, oy);
                    *reinterpret_cast<__half2*>((__half*)os.out[slot] + (size_t)gr * os.cpo + loc) = h2;
                } else {
                    float2 o = make_float2(ox, oy);
                    *reinterpret_cast<float2*>((float*)os.out[slot] + (size_t)gr * os.cpo + loc) = o;
                }
            }
        }
    }
}

// ======================= per-node attention aggregation =======================
template<int PER>
__device__ __forceinline__ void vloadf(float* r, const float* __restrict__ p) {
#pragma unroll
    for (int i = 0; i < PER / 2; i++) {
        float2 t = reinterpret_cast<const float2*>(p)[i];
        r[2 * i + 0] = t.x; r[2 * i + 1] = t.y;
    }
}
template<int PER>
__device__ __forceinline__ void vloadh(float* r, const __half* __restrict__ p) {
    if constexpr (PER % 8 == 0) {
#pragma unroll
        for (int i = 0; i < PER / 8; i++) {
            uint4 t = reinterpret_cast<const uint4*>(p)[i];
            const __half2* h = reinterpret_cast<const __half2*>(&t);
#pragma unroll
            for (int j = 0; j < 4; j++) {
                float2 f = __half22float2(h[j]);
                r[i * 8 + j * 2 + 0] = f.x;
                r[i * 8 + j * 2 + 1] = f.y;
            }
        }
    } else {
        float2 f = __half22float2(*reinterpret_cast<const __half2*>(p));
        r[0] = f.x; r[1] = f.y;
    }
}

// One warp per destination node; 2-edge software pipelining; online softmax.
// K/V gathered in fp16. Optionally fuses bf16 hi/lo split into the epilogue.
template<int HEADS, int CH, bool RELU, bool SPLIT>
__global__ void __launch_bounds__(256)
gat_agg_kernel(const float* __restrict__ Q, const __half* __restrict__ Kf,
               const __half* __restrict__ V,
               const int* __restrict__ rowptr, const int* __restrict__ srcs,
               float* __restrict__ out,
               __nv_bfloat16* __restrict__ hi, __nv_bfloat16* __restrict__ lo, int n)
{
    constexpr int NCH = HEADS * CH;
    constexpr int PER = NCH / 32;
    constexpr int RW  = CH / PER;
    const int lane = threadIdx.x & 31;
    const int node = blockIdx.x * (blockDim.x >> 5) + (threadIdx.x >> 5);
    if (node >= n) return;

    const float scale = rsqrtf((float)CH);
    const size_t base = (size_t)node * NCH + lane * PER;

    float qv[PER], acc[PER];
    vloadf<PER>(qv, Q + base);
#pragma unroll
    for (int i = 0; i < PER; i++) acc[i] = 0.f;

    float m = __int_as_float(0xff800000);
    float s = 0.f;

    const int e0 = rowptr[node];
    const int e1 = rowptr[node + 1];
    int e = e0;
    for (; e + 2 <= e1; e += 2) {
        const int s0 = srcs[e], s1 = srcs[e + 1];
        const size_t b0 = (size_t)s0 * NCH + lane * PER;
        const size_t b1 = (size_t)s1 * NCH + lane * PER;
        float k0[PER], v0[PER], k1[PER], v1[PER];
        vloadh<PER>(k0, Kf + b0);
        vloadh<PER>(k1, Kf + b1);
        vloadh<PER>(v0, V  + b0);
        vloadh<PER>(v1, V  + b1);

        float p0 = 0.f, p1 = 0.f;
#pragma unroll
        for (int i = 0; i < PER; i++) { p0 = fmaf(qv[i], k0[i], p0); p1 = fmaf(qv[i], k1[i], p1); }
#pragma unroll
        for (int off = RW >> 1; off > 0; off >>= 1) {
            p0 += __shfl_xor_sync(0xffffffffu, p0, off);
            p1 += __shfl_xor_sync(0xffffffffu, p1, off);
        }
        const float a0 = p0 * scale, a1 = p1 * scale;
        const float mn = fmaxf(m, fmaxf(a0, a1));
        const float corr = __expf(m - mn);
        const float w0 = __expf(a0 - mn);
        const float w1 = __expf(a1 - mn);
        s = s * corr + w0 + w1;
#pragma unroll
        for (int i = 0; i < PER; i++)
            acc[i] = fmaf(acc[i], corr, fmaf(w0, v0[i], w1 * v1[i]));
        m = mn;
    }
    if (e < e1) {
        const int sn = srcs[e];
        const size_t sbx = (size_t)sn * NCH + lane * PER;
        float kv[PER], vv[PER];
        vloadh<PER>(kv, Kf + sbx);
        vloadh<PER>(vv, V  + sbx);
        float part = 0.f;
#pragma unroll
        for (int i = 0; i < PER; i++) part = fmaf(qv[i], kv[i], part);
#pragma unroll
        for (int off = RW >> 1; off > 0; off >>= 1)
            part += __shfl_xor_sync(0xffffffffu, part, off);
        const float alpha = part * scale;
        const float mn = fmaxf(m, alpha);
        const float corr = __expf(m - mn);
        const float w = __expf(alpha - mn);
        s = s * corr + w;
#pragma unroll
        for (int i = 0; i < PER; i++) acc[i] = fmaf(acc[i], corr, w * vv[i]);
        m = mn;
    }

    const float inv = 1.f / (s + 1e-16f);
#pragma unroll
    for (int i = 0; i < PER; i++) {
        float o = out[base + i] + acc[i] * inv;
        if (RELU) o = fmaxf(o, 0.f);
        out[base + i] = o;
        if (SPLIT) {
            __nv_bfloat16 h = __float2bfloat16(o);
            hi[base + i] = h;
            lo[base + i] = __float2bfloat16(o - __bfloat162float(h));
        }
    }
}

// ======================= host orchestration =======================
extern "C" void kernel_launch(void* const* d_in, const int* in_sizes, int n_in,
                              void* d_out, int out_size)
{
    const float* x  = (const float*)d_in[0];
    const void*  ei = d_in[1];
    const int N = in_sizes[0] / 128;
    const int E = in_sizes[1] / 2;

    const float* P[24];
    for (int i = 0; i < 24; i++) P[i] = (const float*)d_in[2 + i];

    float *q, *h0, *h1, *biasf;
    __half *kh, *vh;
    __nv_bfloat16 *ahi, *alo, *whi, *wlo;
    int *rowptr, *cnt, *cur, *srcs;
    cudaGetSymbolAddress((void**)&q,  g_q);
    cudaGetSymbolAddress((void**)&kh, g_kh);
    cudaGetSymbolAddress((void**)&vh, g_vh);
    cudaGetSymbolAddress((void**)&h0, g_h0);
    cudaGetSymbolAddress((void**)&h1, g_h1);
    cudaGetSymbolAddress((void**)&ahi, g_ahi);
    cudaGetSymbolAddress((void**)&alo, g_alo);
    cudaGetSymbolAddress((void**)&whi, g_whi);
    cudaGetSymbolAddress((void**)&wlo, g_wlo);
    cudaGetSymbolAddress((void**)&biasf, g_biasf);
    cudaGetSymbolAddress((void**)&rowptr, g_rowptr);
    cudaGetSymbolAddress((void**)&cnt, g_cnt);
    cudaGetSymbolAddress((void**)&cur, g_cur);
    cudaGetSymbolAddress((void**)&srcs, g_srcs);

    cudaFuncSetAttribute(gemm_mma_kernel, cudaFuncAttributeMaxDynamicSharedMemorySize, SMEM_TOT);

    // side stream + events (created once; never allocates device memory)
    static cudaStream_t s2 = nullptr;
    static cudaEvent_t evA = nullptr, evB = nullptr;
    if (!s2) {
        cudaStreamCreateWithFlags(&s2, cudaStreamNonBlocking);
        cudaEventCreateWithFlags(&evA, cudaEventDisableTiming);
        cudaEventCreateWithFlags(&evB, cudaEventDisableTiming);
    }

    const int TB = 256;
    float* out = (float*)d_out;

    WTable wt;
    const int Ks[3] = {128, 512, 512};
    const int Ms[3] = {512, 512, 64};
    for (int l = 0; l < 3; l++)
        for (int j = 0; j < 4; j++) {
            wt.d[l * 4 + j].W = P[l * 8 + j * 2];
            wt.d[l * 4 + j].b = P[l * 8 + j * 2 + 1];
            wt.d[l * 4 + j].K = Ks[l];
            wt.d[l * 4 + j].M = Ms[l];
            wt.d[l * 4 + j].layer = l;
            wt.d[l * 4 + j].off = j * Ms[l];
        }

    // ---- fork: CSR build on s2, GEMM prep/compute on main stream ----
    detect_kernel<<<1, 1>>>((const int*)ei);
    cudaEventRecord(evA, 0);
    cudaStreamWaitEvent(s2, evA, 0);
    zero_int_kernel<<<(N + TB - 1) / TB, TB, 0, s2>>>(cnt, N);
    hist_kernel<<<(E + TB - 1) / TB, TB, 0, s2>>>(ei, cnt, E);
    scan_kernel<<<1, 1024, 0, s2>>>(cnt, rowptr, cur, N);
    scatter_kernel<<<(E + TB - 1) / TB, TB, 0, s2>>>(ei, cur, srcs, E);
    cudaEventRecord(evB, s2);

    prep_weights_kernel<<<dim3(64, 12), TB>>>(wt, whi, wlo, biasf);
    split_act_kernel<<<(N * 128 + TB - 1) / TB, TB>>>(x, ahi, alo, N * 128);

    const int mtiles = (N + 127) / 128;
    OutSpec os0;
    os0.out[0] = q; os0.out[1] = kh; os0.out[2] = vh; os0.out[3] = h0;
    os0.half_mask = 0b0110; os0.cpo = 512;
    gemm_mma_kernel<<<dim3(2048 / 128, mtiles), 256, SMEM_TOT>>>(
        ahi, alo, whi, wlo, biasf, os0, N, 128);

    cudaStreamWaitEvent(0, evB, 0);   // CSR ready before aggregation

    const int aggBlocks = (N + 7) / 8;
    gat_agg_kernel<8, 64, true, true><<<aggBlocks, 256>>>(
        q, kh, vh, rowptr, srcs, h0, ahi, alo, N);

    // ---- layer 1 ----
    OutSpec os1;
    os1.out[0] = q; os1.out[1] = kh; os1.out[2] = vh; os1.out[3] = h1;
    os1.half_mask = 0b0110; os1.cpo = 512;
    gemm_mma_kernel<<<dim3(2048 / 128, mtiles), 256, SMEM_TOT>>>(
        ahi, alo, whi + (size_t)1 * NTOTMAX * KMAX, wlo + (size_t)1 * NTOTMAX * KMAX,
        biasf + NTOTMAX, os1, N, 512);
    gat_agg_kernel<8, 64, true, true><<<aggBlocks, 256>>>(
        q, kh, vh, rowptr, srcs, h1, ahi, alo, N);

    // ---- layer 2 (heads=1, ch=64) ----
    OutSpec os2;
    os2.out[0] = q; os2.out[1] = kh; os2.out[2] = vh; os2.out[3] = out;
    os2.half_mask = 0b0110; os2.cpo = 64;
    gemm_mma_kernel<<<dim3(256 / 128, mtiles), 256, SMEM_TOT>>>(
        ahi, alo, whi + (size_t)2 * NTOTMAX * KMAX, wlo + (size_t)2 * NTOTMAX * KMAX,
        biasf + 2 * NTOTMAX, os2, N, 512);
    gat_agg_kernel<1, 64, false, false><<<aggBlocks, 256>>>(
        q, kh, vh, rowptr, srcs, out, nullptr, nullptr, N);
}

// round 8
// speedup vs baseline: 2.1599x; 1.0614x over previous
#include <cuda_runtime.h>
#include <cuda_bf16.h>
#include <cuda_fp16.h>
#include <cstdint>

#define NMAX 50000
#define EMAX 800000
#define KMAX 512
#define NTOTMAX 2048

// ======================= low-level helpers (sm_80-compatible PTX) ==========
__device__ __forceinline__ uint32_t smem_u32(const void* p) {
    uint32_t a;
    asm("{ .reg .u64 t; cvta.to.shared.u64 t, %1; cvt.u32.u64 %0, t; }" : "=r"(a) : "l"(p));
    return a;
}
__device__ __forceinline__ void cp16(uint32_t dst, const void* src, int srcsize) {
    asm volatile("cp.async.cg.shared.global [%0], [%1], 16, %2;"
                 :: "r"(dst), "l"(src), "r"(srcsize));
}
__device__ __forceinline__ void ldm_x4(uint32_t& r0, uint32_t& r1, uint32_t& r2, uint32_t& r3,
                                       uint32_t addr) {
    asm volatile("ldmatrix.sync.aligned.m8n8.x4.shared.b16 {%0,%1,%2,%3}, [%4];"
                 : "=r"(r0), "=r"(r1), "=r"(r2), "=r"(r3) : "r"(addr));
}
__device__ __forceinline__ void mma16816(float* c, const uint32_t* a, const uint32_t* b) {
    asm volatile("mma.sync.aligned.m16n8k16.row.col.f32.bf16.bf16.f32 "
                 "{%0,%1,%2,%3}, {%4,%5,%6,%7}, {%8,%9}, {%0,%1,%2,%3};"
                 : "+f"(c[0]), "+f"(c[1]), "+f"(c[2]), "+f"(c[3])
                 : "r"(a[0]), "r"(a[1]), "r"(a[2]), "r"(a[3]), "r"(b[0]), "r"(b[1]));
}

// ======================= scratch (device globals) =======================
__device__ float  g_q [NMAX * 512];
__device__ __half g_kh[NMAX * 512];
__device__ __half g_vh[NMAX * 512];
__device__ float  g_h0[NMAX * 512];
__device__ float  g_h1[NMAX * 512];
__device__ __nv_bfloat16 g_ahi[NMAX * KMAX];
__device__ __nv_bfloat16 g_alo[NMAX * KMAX];
__device__ __nv_bfloat16 g_whi[3 * NTOTMAX * KMAX];
__device__ __nv_bfloat16 g_wlo[3 * NTOTMAX * KMAX];
__device__ float g_biasf[3 * NTOTMAX];
__device__ int   g_rowptr[NMAX + 1];
__device__ int   g_cnt[NMAX];
__device__ int   g_cur[NMAX];
__device__ int   g_srcs[EMAX];
__device__ int   g_is64;

// ======================= edge dtype detection =======================
__global__ void detect_kernel(const int* __restrict__ w) {
    int odd_nonzero = 0;
    for (int i = 0; i < 128; i++) odd_nonzero += (w[2 * i + 1] != 0);
    g_is64 = (odd_nonzero == 0) ? 1 : 0;
}
__device__ __forceinline__ int edge_at(const void* ei, long long idx, int is64) {
    return is64 ? (int)((const long long*)ei)[idx] : ((const int*)ei)[idx];
}

// ======================= CSR build =======================
__global__ void zero_int_kernel(int* __restrict__ p, int n) {
    int i = blockIdx.x * blockDim.x + threadIdx.x;
    if (i < n) p[i] = 0;
}
__global__ void hist_kernel(const void* __restrict__ ei, int* __restrict__ cnt, int E) {
    int e = blockIdx.x * blockDim.x + threadIdx.x;
    if (e < E) atomicAdd(&cnt[edge_at(ei, (long long)E + e, g_is64)], 1);
}
__global__ void scan_kernel(const int* __restrict__ cnt, int* __restrict__ rowptr,
                            int* __restrict__ cur, int n) {
    __shared__ int part[1024];
    const int t = threadIdx.x;
    const int chunk = (n + 1023) >> 10;
    int b = t * chunk; if (b > n) b = n;
    int e = b + chunk; if (e > n) e = n;
    int s = 0;
    for (int i = b; i < e; i++) s += cnt[i];
    part[t] = s;
    __syncthreads();
    if (t == 0) {
        int a = 0;
        for (int i = 0; i < 1024; i++) { int v = part[i]; part[i] = a; a += v; }
    }
    __syncthreads();
    int off = part[t];
    for (int i = b; i < e; i++) { rowptr[i] = off; cur[i] = off; off += cnt[i]; }
    if (t == 1023) rowptr[n] = off;
}
__global__ void scatter_kernel(const void* __restrict__ ei, int* __restrict__ cur,
                               int* __restrict__ srcs, int E) {
    int e = blockIdx.x * blockDim.x + threadIdx.x;
    if (e < E) {
        const int is64 = g_is64;
        int d = edge_at(ei, (long long)E + e, is64);
        int p = atomicAdd(&cur[d], 1);
        srcs[p] = edge_at(ei, e, is64);
    }
}

// ======================= weight prep: transpose + hi/lo split ==============
struct WDesc { const float* W; const float* b; int K; int M; int layer; int off; };
struct WTable { WDesc d[12]; };

__global__ void prep_weights_kernel(WTable t, int y0, __nv_bfloat16* __restrict__ whi,
                                    __nv_bfloat16* __restrict__ wlo, float* __restrict__ biasf) {
    const WDesc w = t.d[y0 + blockIdx.y];
    const size_t base = (size_t)w.layer * NTOTMAX * KMAX;
    const int stride = gridDim.x * blockDim.x;
    for (int i = blockIdx.x * blockDim.x + threadIdx.x; i < w.M; i += stride)
        biasf[w.layer * NTOTMAX + w.off + i] = w.b[i];
    const int total = w.K * w.M;
    for (int i = blockIdx.x * blockDim.x + threadIdx.x; i < total; i += stride) {
        int k = i / w.M, m = i % w.M;
        float v = w.W[i];
        __nv_bfloat16 hi = __float2bfloat16(v);
        float lo = v - __bfloat162float(hi);
        size_t dst = base + (size_t)(w.off + m) * w.K + k;
        whi[dst] = hi;
        wlo[dst] = __float2bfloat16(lo);
    }
}

// ======================= activation hi/lo split (input x only) =============
__global__ void split_act_kernel(const float* __restrict__ x, __nv_bfloat16* __restrict__ hi,
                                 __nv_bfloat16* __restrict__ lo, int total) {
    int i = blockIdx.x * blockDim.x + threadIdx.x;
    if (i < total) {
        float v = x[i];
        __nv_bfloat16 h = __float2bfloat16(v);
        hi[i] = h;
        lo[i] = __float2bfloat16(v - __bfloat162float(h));
    }
}

// ======================= HMMA GEMM: C[N, ntot] = A @ Wt^T + bias ===========
// bf16 split in register accumulators: Ahi*Bhi + Alo*Bhi (+ Ahi*Blo).
// Column tiles flagged in lp_mask skip the Ahi*Blo pass (and the Blo loads).
// kc-outer / pass-inner, double-buffered 4-region SMEM, one wait+sync per kc.
// CTA tile 128x128, BK=32, 8 warps (2x4), warp tile 64x32.
#define STG_BYTES 10240                 /* 128 rows * 80B padded */
#define SMEM_TOT  (8 * STG_BYTES)       /* 4 tensors x 2 slots = 81920 */

struct OutSpec { void* out[4]; int half_mask; int cpo; };

__global__ void __launch_bounds__(256, 2)
gemm_mma_kernel(const __nv_bfloat16* __restrict__ Ahi, const __nv_bfloat16* __restrict__ Alo,
                const __nv_bfloat16* __restrict__ Whi, const __nv_bfloat16* __restrict__ Wlo,
                const float* __restrict__ biasf, OutSpec os, int Nrows, int K,
                uint32_t lp_mask)
{
    extern __shared__ char smem[];
    const uint32_t sb = smem_u32(smem);
    const int tid = threadIdx.x, lane = tid & 31, wid = tid >> 5;
    const int wm = wid & 1, wn = wid >> 1;
    const int m0 = blockIdx.y * 128, n0 = blockIdx.x * 128;
    const int KT = K / 32;
    const bool lp = (lp_mask >> blockIdx.x) & 1u;   // low-precision tile: 2 passes

    float acc[4][4][4];
#pragma unroll
    for (int a = 0; a < 4; a++)
#pragma unroll
        for (int b = 0; b < 4; b++)
#pragma unroll
            for (int c = 0; c < 4; c++) acc[a][b][c] = 0.f;

    const int r0 = tid >> 2, c0 = tid & 3;
    const int r1 = r0 + 64;

    // region(tensor, slot) base: tensor 0=Ahi 1=Alo 2=Bhi 3=Blo
    auto issueKC = [&](int kc) {
        const int slot = kc & 1;
        const int koff = kc * 32;
        int ar0 = m0 + r0; bool v0 = ar0 < Nrows; if (!v0) ar0 = 0;
        int ar1 = m0 + r1; bool v1 = ar1 < Nrows; if (!v1) ar1 = 0;
        const uint32_t sAhi = sb + (0 * 2 + slot) * STG_BYTES;
        const uint32_t sAlo = sb + (1 * 2 + slot) * STG_BYTES;
        const uint32_t sBhi = sb + (2 * 2 + slot) * STG_BYTES;
        const uint32_t sBlo = sb + (3 * 2 + slot) * STG_BYTES;
        const uint32_t ro0 = r0 * 80 + c0 * 16, ro1 = r1 * 80 + c0 * 16;
        cp16(sAhi + ro0, Ahi + (size_t)ar0 * K + koff + c0 * 8, v0 ? 16 : 0);
        cp16(sAhi + ro1, Ahi + (size_t)ar1 * K + koff + c0 * 8, v1 ? 16 : 0);
        cp16(sAlo + ro0, Alo + (size_t)ar0 * K + koff + c0 * 8, v0 ? 16 : 0);
        cp16(sAlo + ro1, Alo + (size_t)ar1 * K + koff + c0 * 8, v1 ? 16 : 0);
        cp16(sBhi + ro0, Whi + (size_t)(n0 + r0) * K + koff + c0 * 8, 16);
        cp16(sBhi + ro1, Whi + (size_t)(n0 + r1) * K + koff + c0 * 8, 16);
        if (!lp) {
            cp16(sBlo + ro0, Wlo + (size_t)(n0 + r0) * K + koff + c0 * 8, 16);
            cp16(sBlo + ro1, Wlo + (size_t)(n0 + r1) * K + koff + c0 * 8, 16);
        }
    };

    // per-warp ldmatrix local offsets (within a region)
    const uint32_t aLoc = (uint32_t)((wm * 64 + (lane & 15)) * 80 + (lane >> 4) * 16);
    const uint32_t bLoc = (uint32_t)((wn * 32 + (lane & 7) + ((lane >> 4) << 3)) * 80
                                     + ((lane >> 3) & 1) * 16);

    issueKC(0);
    asm volatile("cp.async.commit_group;" ::: "memory");

    for (int kc = 0; kc < KT; kc++) {
        asm volatile("cp.async.wait_group 0;" ::: "memory");
        __syncthreads();
        if (kc + 1 < KT) {
            issueKC(kc + 1);
            asm volatile("cp.async.commit_group;" ::: "memory");
        }
        const int slot = kc & 1;
#pragma unroll
        for (int pass = 0; pass < 3; pass++) {
            if (pass == 2 && lp) break;           // skip W-lo correction on lp tiles
            const int aR = (pass == 1) ? 1 : 0;   // Alo on pass 1
            const int bR = (pass == 2) ? 3 : 2;   // Blo on pass 2
            const uint32_t aBase = sb + (uint32_t)(aR * 2 + slot) * STG_BYTES + aLoc;
            const uint32_t bBase = sb + (uint32_t)(bR * 2 + slot) * STG_BYTES + bLoc;
#pragma unroll
            for (int ks = 0; ks < 2; ks++) {
                uint32_t a[4][4], b[2][4];
#pragma unroll
                for (int mi = 0; mi < 4; mi++)
                    ldm_x4(a[mi][0], a[mi][1], a[mi][2], a[mi][3],
                           aBase + mi * 16 * 80 + ks * 32);
#pragma unroll
                for (int nj = 0; nj < 2; nj++)
                    ldm_x4(b[nj][0], b[nj][1], b[nj][2], b[nj][3],
                           bBase + nj * 16 * 80 + ks * 32);
#pragma unroll
                for (int mi = 0; mi < 4; mi++)
#pragma unroll
                    for (int ni = 0; ni < 4; ni++)
                        mma16816(acc[mi][ni], a[mi], &b[ni >> 1][(ni & 1) * 2]);
            }
        }
    }

    const int erow = lane >> 2, ecol = (lane & 3) * 2;
#pragma unroll
    for (int mi = 0; mi < 4; mi++) {
#pragma unroll
        for (int half = 0; half < 2; half++) {
            const int gr = m0 + wm * 64 + mi * 16 + erow + half * 8;
            if (gr >= Nrows) continue;
#pragma unroll
            for (int ni = 0; ni < 4; ni++) {
                const int gc = n0 + wn * 32 + ni * 8 + ecol;
                const int slot = gc / os.cpo;
                const int loc  = gc % os.cpo;
                float ox = acc[mi][ni][half * 2 + 0] + biasf[gc + 0];
                float oy = acc[mi][ni][half * 2 + 1] + biasf[gc + 1];
                if (os.half_mask & (1 << slot)) {
                    __half2 h2 = __floats2half2_rn(ox, oy);
                    *reinterpret_cast<__half2*>((__half*)os.out[slot] + (size_t)gr * os.cpo + loc) = h2;
                } else {
                    float2 o = make_float2(ox, oy);
                    *reinterpret_cast<float2*>((float*)os.out[slot] + (size_t)gr * os.cpo + loc) = o;
                }
            }
        }
    }
}

// ======================= per-node attention aggregation =======================
template<int PER>
__device__ __forceinline__ void vloadf(float* r, const float* __restrict__ p) {
#pragma unroll
    for (int i = 0; i < PER / 2; i++) {
        float2 t = reinterpret_cast<const float2*>(p)[i];
        r[2 * i + 0] = t.x; r[2 * i + 1] = t.y;
    }
}
template<int PER>
__device__ __forceinline__ void vloadh(float* r, const __half* __restrict__ p) {
    if constexpr (PER % 8 == 0) {
#pragma unroll
        for (int i = 0; i < PER / 8; i++) {
            uint4 t = reinterpret_cast<const uint4*>(p)[i];
            const __half2* h = reinterpret_cast<const __half2*>(&t);
#pragma unroll
            for (int j = 0; j < 4; j++) {
                float2 f = __half22float2(h[j]);
                r[i * 8 + j * 2 + 0] = f.x;
                r[i * 8 + j * 2 + 1] = f.y;
            }
        }
    } else {
        float2 f = __half22float2(*reinterpret_cast<const __half2*>(p));
        r[0] = f.x; r[1] = f.y;
    }
}

// One warp per destination node; 4-edge phase-split pipeline (gather 4 k-rows,
// reduce 4 logits, reuse registers for 4 v-rows, one rescale per 4 edges).
// K/V gathered in fp16. Optionally fuses bf16 hi/lo split into the epilogue.
template<int HEADS, int CH, bool RELU, bool SPLIT>
__global__ void __launch_bounds__(256)
gat_agg_kernel(const float* __restrict__ Q, const __half* __restrict__ Kf,
               const __half* __restrict__ V,
               const int* __restrict__ rowptr, const int* __restrict__ srcs,
               float* __restrict__ out,
               __nv_bfloat16* __restrict__ hi, __nv_bfloat16* __restrict__ lo, int n)
{
    constexpr int NCH = HEADS * CH;
    constexpr int PER = NCH / 32;
    constexpr int RW  = CH / PER;
    const int lane = threadIdx.x & 31;
    const int node = blockIdx.x * (blockDim.x >> 5) + (threadIdx.x >> 5);
    if (node >= n) return;

    const float scale = rsqrtf((float)CH);
    const size_t base = (size_t)node * NCH + lane * PER;

    float qv[PER], acc[PER];
    vloadf<PER>(qv, Q + base);
#pragma unroll
    for (int i = 0; i < PER; i++) acc[i] = 0.f;

    float m = __int_as_float(0xff800000);
    float s = 0.f;

    const int e0 = rowptr[node];
    const int e1 = rowptr[node + 1];
    int e = e0;
    for (; e + 4 <= e1; e += 4) {
        size_t b[4];
#pragma unroll
        for (int j = 0; j < 4; j++)
            b[j] = (size_t)srcs[e + j] * NCH + lane * PER;

        float t0[PER], t1[PER], t2[PER], t3[PER];
        vloadh<PER>(t0, Kf + b[0]);
        vloadh<PER>(t1, Kf + b[1]);
        vloadh<PER>(t2, Kf + b[2]);
        vloadh<PER>(t3, Kf + b[3]);

        float p0 = 0.f, p1 = 0.f, p2 = 0.f, p3 = 0.f;
#pragma unroll
        for (int i = 0; i < PER; i++) {
            p0 = fmaf(qv[i], t0[i], p0); p1 = fmaf(qv[i], t1[i], p1);
            p2 = fmaf(qv[i], t2[i], p2); p3 = fmaf(qv[i], t3[i], p3);
        }
#pragma unroll
        for (int off = RW >> 1; off > 0; off >>= 1) {
            p0 += __shfl_xor_sync(0xffffffffu, p0, off);
            p1 += __shfl_xor_sync(0xffffffffu, p1, off);
            p2 += __shfl_xor_sync(0xffffffffu, p2, off);
            p3 += __shfl_xor_sync(0xffffffffu, p3, off);
        }
        const float a0 = p0 * scale, a1 = p1 * scale;
        const float a2 = p2 * scale, a3 = p3 * scale;
        const float mn = fmaxf(fmaxf(m, fmaxf(a0, a1)), fmaxf(a2, a3));
        const float corr = __expf(m - mn);
        const float w0 = __expf(a0 - mn), w1 = __expf(a1 - mn);
        const float w2 = __expf(a2 - mn), w3 = __expf(a3 - mn);
        s = s * corr + (w0 + w1) + (w2 + w3);

        // reuse t* registers for the v gather
        vloadh<PER>(t0, V + b[0]);
        vloadh<PER>(t1, V + b[1]);
        vloadh<PER>(t2, V + b[2]);
        vloadh<PER>(t3, V + b[3]);
#pragma unroll
        for (int i = 0; i < PER; i++)
            acc[i] = fmaf(acc[i], corr,
                          fmaf(w0, t0[i], fmaf(w1, t1[i], fmaf(w2, t2[i], w3 * t3[i]))));
        m = mn;
    }
    for (; e < e1; e++) {
        const int sn = srcs[e];
        const size_t sbx = (size_t)sn * NCH + lane * PER;
        float kv[PER], vv[PER];
        vloadh<PER>(kv, Kf + sbx);
        vloadh<PER>(vv, V  + sbx);
        float part = 0.f;
#pragma unroll
        for (int i = 0; i < PER; i++) part = fmaf(qv[i], kv[i], part);
#pragma unroll
        for (int off = RW >> 1; off > 0; off >>= 1)
            part += __shfl_xor_sync(0xffffffffu, part, off);
        const float alpha = part * scale;
        const float mn = fmaxf(m, alpha);
        const float corr = __expf(m - mn);
        const float w = __expf(alpha - mn);
        s = s * corr + w;
#pragma unroll
        for (int i = 0; i < PER; i++) acc[i] = fmaf(acc[i], corr, w * vv[i]);
        m = mn;
    }

    const float inv = 1.f / (s + 1e-16f);
#pragma unroll
    for (int i = 0; i < PER; i++) {
        float o = out[base + i] + acc[i] * inv;
        if (RELU) o = fmaxf(o, 0.f);
        out[base + i] = o;
        if (SPLIT) {
            __nv_bfloat16 h = __float2bfloat16(o);
            hi[base + i] = h;
            lo[base + i] = __float2bfloat16(o - __bfloat162float(h));
        }
    }
}

// ======================= host orchestration =======================
extern "C" void kernel_launch(void* const* d_in, const int* in_sizes, int n_in,
                              void* d_out, int out_size)
{
    const float* x  = (const float*)d_in[0];
    const void*  ei = d_in[1];
    const int N = in_sizes[0] / 128;
    const int E = in_sizes[1] / 2;

    const float* P[24];
    for (int i = 0; i < 24; i++) P[i] = (const float*)d_in[2 + i];

    float *q, *h0, *h1, *biasf;
    __half *kh, *vh;
    __nv_bfloat16 *ahi, *alo, *whi, *wlo;
    int *rowptr, *cnt, *cur, *srcs;
    cudaGetSymbolAddress((void**)&q,  g_q);
    cudaGetSymbolAddress((void**)&kh, g_kh);
    cudaGetSymbolAddress((void**)&vh, g_vh);
    cudaGetSymbolAddress((void**)&h0, g_h0);
    cudaGetSymbolAddress((void**)&h1, g_h1);
    cudaGetSymbolAddress((void**)&ahi, g_ahi);
    cudaGetSymbolAddress((void**)&alo, g_alo);
    cudaGetSymbolAddress((void**)&whi, g_whi);
    cudaGetSymbolAddress((void**)&wlo, g_wlo);
    cudaGetSymbolAddress((void**)&biasf, g_biasf);
    cudaGetSymbolAddress((void**)&rowptr, g_rowptr);
    cudaGetSymbolAddress((void**)&cnt, g_cnt);
    cudaGetSymbolAddress((void**)&cur, g_cur);
    cudaGetSymbolAddress((void**)&srcs, g_srcs);

    cudaFuncSetAttribute(gemm_mma_kernel, cudaFuncAttributeMaxDynamicSharedMemorySize, SMEM_TOT);

    // side stream + events (created once; never allocates device memory)
    static cudaStream_t s2 = nullptr;
    static cudaEvent_t evA = nullptr, evB = nullptr, evC = nullptr;
    if (!s2) {
        cudaStreamCreateWithFlags(&s2, cudaStreamNonBlocking);
        cudaEventCreateWithFlags(&evA, cudaEventDisableTiming);
        cudaEventCreateWithFlags(&evB, cudaEventDisableTiming);
        cudaEventCreateWithFlags(&evC, cudaEventDisableTiming);
    }

    const int TB = 256;
    float* out = (float*)d_out;

    WTable wt;
    const int Ks[3] = {128, 512, 512};
    const int Ms[3] = {512, 512, 64};
    for (int l = 0; l < 3; l++)
        for (int j = 0; j < 4; j++) {
            wt.d[l * 4 + j].W = P[l * 8 + j * 2];
            wt.d[l * 4 + j].b = P[l * 8 + j * 2 + 1];
            wt.d[l * 4 + j].K = Ks[l];
            wt.d[l * 4 + j].M = Ms[l];
            wt.d[l * 4 + j].layer = l;
            wt.d[l * 4 + j].off = j * Ms[l];
        }

    // v column tiles (1024..1535 => tiles 8-11) for layers 0/1 use 2-pass
    const uint32_t LP01 = 0x0F00u;

    // ---- fork: CSR build + layer-1/2 weight prep on s2 ----
    detect_kernel<<<1, 1>>>((const int*)ei);
    cudaEventRecord(evA, 0);
    cudaStreamWaitEvent(s2, evA, 0);
    zero_int_kernel<<<(N + TB - 1) / TB, TB, 0, s2>>>(cnt, N);
    hist_kernel<<<(E + TB - 1) / TB, TB, 0, s2>>>(ei, cnt, E);
    scan_kernel<<<1, 1024, 0, s2>>>(cnt, rowptr, cur, N);
    scatter_kernel<<<(E + TB - 1) / TB, TB, 0, s2>>>(ei, cur, srcs, E);
    cudaEventRecord(evB, s2);
    prep_weights_kernel<<<dim3(64, 8), TB, 0, s2>>>(wt, 4, whi, wlo, biasf);
    cudaEventRecord(evC, s2);

    // main stream: layer-0 prep + GEMM-0
    prep_weights_kernel<<<dim3(64, 4), TB>>>(wt, 0, whi, wlo, biasf);
    split_act_kernel<<<(N * 128 + TB - 1) / TB, TB>>>(x, ahi, alo, N * 128);

    const int mtiles = (N + 127) / 128;
    OutSpec os0;
    os0.out[0] = q; os0.out[1] = kh; os0.out[2] = vh; os0.out[3] = h0;
    os0.half_mask = 0b0110; os0.cpo = 512;
    gemm_mma_kernel<<<dim3(2048 / 128, mtiles), 256, SMEM_TOT>>>(
        ahi, alo, whi, wlo, biasf, os0, N, 128, LP01);

    cudaStreamWaitEvent(0, evB, 0);   // CSR ready before aggregation

    const int aggBlocks = (N + 7) / 8;
    gat_agg_kernel<8, 64, true, true><<<aggBlocks, 256>>>(
        q, kh, vh, rowptr, srcs, h0, ahi, alo, N);

    cudaStreamWaitEvent(0, evC, 0);   // layer-1/2 weights ready

    // ---- layer 1 ----
    OutSpec os1;
    os1.out[0] = q; os1.out[1] = kh; os1.out[2] = vh; os1.out[3] = h1;
    os1.half_mask = 0b0110; os1.cpo = 512;
    gemm_mma_kernel<<<dim3(2048 / 128, mtiles), 256, SMEM_TOT>>>(
        ahi, alo, whi + (size_t)1 * NTOTMAX * KMAX, wlo + (size_t)1 * NTOTMAX * KMAX,
        biasf + NTOTMAX, os1, N, 512, LP01);
    gat_agg_kernel<8, 64, true, true><<<aggBlocks, 256>>>(
        q, kh, vh, rowptr, srcs, h1, ahi, alo, N);

    // ---- layer 2 (heads=1, ch=64) ----
    OutSpec os2;
    os2.out[0] = q; os2.out[1] = kh; os2.out[2] = vh; os2.out[3] = out;
    os2.half_mask = 0b0110; os2.cpo = 64;
    gemm_mma_kernel<<<dim3(256 / 128, mtiles), 256, SMEM_TOT>>>(
        ahi, alo, whi + (size_t)2 * NTOTMAX * KMAX, wlo + (size_t)2 * NTOTMAX * KMAX,
        biasf + 2 * NTOTMAX, os2, N, 512, 0u);
    gat_agg_kernel<1, 64, false, false><<<aggBlocks, 256>>>(
        q, kh, vh, rowptr, srcs, out, nullptr, nullptr, N);
}

// round 9
// speedup vs baseline: 2.2225x; 1.0290x over previous
#include <cuda_runtime.h>
#include <cuda_bf16.h>
#include <cuda_fp16.h>
#include <cstdint>

#define NMAX 50000
#define EMAX 800000
#define KMAX 512
#define NTOTMAX 2048

// ======================= low-level helpers (sm_80-compatible PTX) ==========
__device__ __forceinline__ uint32_t smem_u32(const void* p) {
    uint32_t a;
    asm("{ .reg .u64 t; cvta.to.shared.u64 t, %1; cvt.u32.u64 %0, t; }" : "=r"(a) : "l"(p));
    return a;
}
__device__ __forceinline__ void cp16(uint32_t dst, const void* src, int srcsize) {
    asm volatile("cp.async.cg.shared.global [%0], [%1], 16, %2;"
                 :: "r"(dst), "l"(src), "r"(srcsize));
}
__device__ __forceinline__ void ldm_x4(uint32_t& r0, uint32_t& r1, uint32_t& r2, uint32_t& r3,
                                       uint32_t addr) {
    asm volatile("ldmatrix.sync.aligned.m8n8.x4.shared.b16 {%0,%1,%2,%3}, [%4];"
                 : "=r"(r0), "=r"(r1), "=r"(r2), "=r"(r3) : "r"(addr));
}
__device__ __forceinline__ void mma16816(float* c, const uint32_t* a, const uint32_t* b) {
    asm volatile("mma.sync.aligned.m16n8k16.row.col.f32.f16.f16.f32 "
                 "{%0,%1,%2,%3}, {%4,%5,%6,%7}, {%8,%9}, {%0,%1,%2,%3};"
                 : "+f"(c[0]), "+f"(c[1]), "+f"(c[2]), "+f"(c[3])
                 : "r"(a[0]), "r"(a[1]), "r"(a[2]), "r"(a[3]), "r"(b[0]), "r"(b[1]));
}

// ======================= scratch (device globals) =======================
__device__ float  g_q [NMAX * 512];
__device__ __half g_kh[NMAX * 512];
__device__ __half g_vh[NMAX * 512];
__device__ float  g_h0[NMAX * 512];
__device__ float  g_h1[NMAX * 512];
__device__ __half g_ahi[NMAX * KMAX];
__device__ __half g_alo[NMAX * KMAX];
__device__ __half g_whi[3 * NTOTMAX * KMAX];
__device__ __half g_wlo[3 * NTOTMAX * KMAX];
__device__ float g_biasf[3 * NTOTMAX];
__device__ int   g_rowptr[NMAX + 1];
__device__ int   g_cnt[NMAX];
__device__ int   g_cur[NMAX];
__device__ int   g_srcs[EMAX];
__device__ int   g_is64;

// ======================= edge dtype detection =======================
__global__ void detect_kernel(const int* __restrict__ w) {
    int odd_nonzero = 0;
    for (int i = 0; i < 128; i++) odd_nonzero += (w[2 * i + 1] != 0);
    g_is64 = (odd_nonzero == 0) ? 1 : 0;
}
__device__ __forceinline__ int edge_at(const void* ei, long long idx, int is64) {
    return is64 ? (int)((const long long*)ei)[idx] : ((const int*)ei)[idx];
}

// ======================= CSR build =======================
__global__ void zero_int_kernel(int* __restrict__ p, int n) {
    int i = blockIdx.x * blockDim.x + threadIdx.x;
    if (i < n) p[i] = 0;
}
__global__ void hist_kernel(const void* __restrict__ ei, int* __restrict__ cnt, int E) {
    int e = blockIdx.x * blockDim.x + threadIdx.x;
    if (e < E) atomicAdd(&cnt[edge_at(ei, (long long)E + e, g_is64)], 1);
}
__global__ void scan_kernel(const int* __restrict__ cnt, int* __restrict__ rowptr,
                            int* __restrict__ cur, int n) {
    __shared__ int part[1024];
    const int t = threadIdx.x;
    const int chunk = (n + 1023) >> 10;
    int b = t * chunk; if (b > n) b = n;
    int e = b + chunk; if (e > n) e = n;
    int s = 0;
    for (int i = b; i < e; i++) s += cnt[i];
    part[t] = s;
    __syncthreads();
    if (t == 0) {
        int a = 0;
        for (int i = 0; i < 1024; i++) { int v = part[i]; part[i] = a; a += v; }
    }
    __syncthreads();
    int off = part[t];
    for (int i = b; i < e; i++) { rowptr[i] = off; cur[i] = off; off += cnt[i]; }
    if (t == 1023) rowptr[n] = off;
}
__global__ void scatter_kernel(const void* __restrict__ ei, int* __restrict__ cur,
                               int* __restrict__ srcs, int E) {
    int e = blockIdx.x * blockDim.x + threadIdx.x;
    if (e < E) {
        const int is64 = g_is64;
        int d = edge_at(ei, (long long)E + e, is64);
        int p = atomicAdd(&cur[d], 1);
        srcs[p] = edge_at(ei, e, is64);
    }
}

// ======================= weight prep: transpose + fp16 hi/lo split =========
struct WDesc { const float* W; const float* b; int K; int M; int layer; int off; };
struct WTable { WDesc d[12]; };

__global__ void prep_weights_kernel(WTable t, int y0, __half* __restrict__ whi,
                                    __half* __restrict__ wlo, float* __restrict__ biasf) {
    const WDesc w = t.d[y0 + blockIdx.y];
    const size_t base = (size_t)w.layer * NTOTMAX * KMAX;
    const int stride = gridDim.x * blockDim.x;
    for (int i = blockIdx.x * blockDim.x + threadIdx.x; i < w.M; i += stride)
        biasf[w.layer * NTOTMAX + w.off + i] = w.b[i];
    const int total = w.K * w.M;
    for (int i = blockIdx.x * blockDim.x + threadIdx.x; i < total; i += stride) {
        int k = i / w.M, m = i % w.M;
        float v = w.W[i];
        __half hi = __float2half(v);
        float lo = v - __half2float(hi);
        size_t dst = base + (size_t)(w.off + m) * w.K + k;
        whi[dst] = hi;
        wlo[dst] = __float2half(lo);
    }
}

// ======================= activation fp16 hi/lo split (input x only) ========
__global__ void split_act_kernel(const float* __restrict__ x, __half* __restrict__ hi,
                                 __half* __restrict__ lo, int total) {
    int i = blockIdx.x * blockDim.x + threadIdx.x;
    if (i < total) {
        float v = x[i];
        __half h = __float2half(v);
        hi[i] = h;
        lo[i] = __float2half(v - __half2float(h));
    }
}

// ======================= HMMA GEMM: C[N, ntot] = A @ Wt^T + bias ===========
// fp16 split in register accumulators: Ahi*Bhi + Alo*Bhi (+ Ahi*Blo).
// Column tiles flagged in lp_mask skip the Ahi*Blo pass (and the Blo loads);
// fp16 residuals make the dropped term ~2^-12 (8x finer than bf16).
// kc-outer / pass-inner, double-buffered 4-region SMEM, one wait+sync per kc.
// CTA tile 128x128, BK=32, 8 warps (2x4), warp tile 64x32.
#define STG_BYTES 10240                 /* 128 rows * 80B padded */
#define SMEM_TOT  (8 * STG_BYTES)       /* 4 tensors x 2 slots = 81920 */

struct OutSpec { void* out[4]; int half_mask; int cpo; };

__global__ void __launch_bounds__(256, 2)
gemm_mma_kernel(const __half* __restrict__ Ahi, const __half* __restrict__ Alo,
                const __half* __restrict__ Whi, const __half* __restrict__ Wlo,
                const float* __restrict__ biasf, OutSpec os, int Nrows, int K,
                uint32_t lp_mask)
{
    extern __shared__ char smem[];
    const uint32_t sb = smem_u32(smem);
    const int tid = threadIdx.x, lane = tid & 31, wid = tid >> 5;
    const int wm = wid & 1, wn = wid >> 1;
    const int m0 = blockIdx.y * 128, n0 = blockIdx.x * 128;
    const int KT = K / 32;
    const bool lp = (lp_mask >> blockIdx.x) & 1u;   // low-precision tile: 2 passes

    float acc[4][4][4];
#pragma unroll
    for (int a = 0; a < 4; a++)
#pragma unroll
        for (int b = 0; b < 4; b++)
#pragma unroll
            for (int c = 0; c < 4; c++) acc[a][b][c] = 0.f;

    const int r0 = tid >> 2, c0 = tid & 3;
    const int r1 = r0 + 64;

    // region(tensor, slot) base: tensor 0=Ahi 1=Alo 2=Bhi 3=Blo
    auto issueKC = [&](int kc) {
        const int slot = kc & 1;
        const int koff = kc * 32;
        int ar0 = m0 + r0; bool v0 = ar0 < Nrows; if (!v0) ar0 = 0;
        int ar1 = m0 + r1; bool v1 = ar1 < Nrows; if (!v1) ar1 = 0;
        const uint32_t sAhi = sb + (0 * 2 + slot) * STG_BYTES;
        const uint32_t sAlo = sb + (1 * 2 + slot) * STG_BYTES;
        const uint32_t sBhi = sb + (2 * 2 + slot) * STG_BYTES;
        const uint32_t sBlo = sb + (3 * 2 + slot) * STG_BYTES;
        const uint32_t ro0 = r0 * 80 + c0 * 16, ro1 = r1 * 80 + c0 * 16;
        cp16(sAhi + ro0, Ahi + (size_t)ar0 * K + koff + c0 * 8, v0 ? 16 : 0);
        cp16(sAhi + ro1, Ahi + (size_t)ar1 * K + koff + c0 * 8, v1 ? 16 : 0);
        cp16(sAlo + ro0, Alo + (size_t)ar0 * K + koff + c0 * 8, v0 ? 16 : 0);
        cp16(sAlo + ro1, Alo + (size_t)ar1 * K + koff + c0 * 8, v1 ? 16 : 0);
        cp16(sBhi + ro0, Whi + (size_t)(n0 + r0) * K + koff + c0 * 8, 16);
        cp16(sBhi + ro1, Whi + (size_t)(n0 + r1) * K + koff + c0 * 8, 16);
        if (!lp) {
            cp16(sBlo + ro0, Wlo + (size_t)(n0 + r0) * K + koff + c0 * 8, 16);
            cp16(sBlo + ro1, Wlo + (size_t)(n0 + r1) * K + koff + c0 * 8, 16);
        }
    };

    // per-warp ldmatrix local offsets (within a region)
    const uint32_t aLoc = (uint32_t)((wm * 64 + (lane & 15)) * 80 + (lane >> 4) * 16);
    const uint32_t bLoc = (uint32_t)((wn * 32 + (lane & 7) + ((lane >> 4) << 3)) * 80
                                     + ((lane >> 3) & 1) * 16);

    issueKC(0);
    asm volatile("cp.async.commit_group;" ::: "memory");

    for (int kc = 0; kc < KT; kc++) {
        asm volatile("cp.async.wait_group 0;" ::: "memory");
        __syncthreads();
        if (kc + 1 < KT) {
            issueKC(kc + 1);
            asm volatile("cp.async.commit_group;" ::: "memory");
        }
        const int slot = kc & 1;
#pragma unroll
        for (int pass = 0; pass < 3; pass++) {
            if (pass == 2 && lp) break;           // skip W-lo correction on lp tiles
            const int aR = (pass == 1) ? 1 : 0;   // Alo on pass 1
            const int bR = (pass == 2) ? 3 : 2;   // Blo on pass 2
            const uint32_t aBase = sb + (uint32_t)(aR * 2 + slot) * STG_BYTES + aLoc;
            const uint32_t bBase = sb + (uint32_t)(bR * 2 + slot) * STG_BYTES + bLoc;
#pragma unroll
            for (int ks = 0; ks < 2; ks++) {
                uint32_t a[4][4], b[2][4];
#pragma unroll
                for (int mi = 0; mi < 4; mi++)
                    ldm_x4(a[mi][0], a[mi][1], a[mi][2], a[mi][3],
                           aBase + mi * 16 * 80 + ks * 32);
#pragma unroll
                for (int nj = 0; nj < 2; nj++)
                    ldm_x4(b[nj][0], b[nj][1], b[nj][2], b[nj][3],
                           bBase + nj * 16 * 80 + ks * 32);
#pragma unroll
                for (int mi = 0; mi < 4; mi++)
#pragma unroll
                    for (int ni = 0; ni < 4; ni++)
                        mma16816(acc[mi][ni], a[mi], &b[ni >> 1][(ni & 1) * 2]);
            }
        }
    }

    const int erow = lane >> 2, ecol = (lane & 3) * 2;
#pragma unroll
    for (int mi = 0; mi < 4; mi++) {
#pragma unroll
        for (int half = 0; half < 2; half++) {
            const int gr = m0 + wm * 64 + mi * 16 + erow + half * 8;
            if (gr >= Nrows) continue;
#pragma unroll
            for (int ni = 0; ni < 4; ni++) {
                const int gc = n0 + wn * 32 + ni * 8 + ecol;
                const int slot = gc / os.cpo;
                const int loc  = gc % os.cpo;
                float ox = acc[mi][ni][half * 2 + 0] + biasf[gc + 0];
                float oy = acc[mi][ni][half * 2 + 1] + biasf[gc + 1];
                if (os.half_mask & (1 << slot)) {
                    __half2 h2 = __floats2half2_rn(ox, oy);
                    *reinterpret_cast<__half2*>((__half*)os.out[slot] + (size_t)gr * os.cpo + loc) = h2;
                } else {
                    float2 o = make_float2(ox, oy);
                    *reinterpret_cast<float2*>((float*)os.out[slot] + (size_t)gr * os.cpo + loc) = o;
                }
            }
        }
    }
}

// ======================= per-node attention aggregation =======================
template<int PER>
__device__ __forceinline__ void vloadf(float* r, const float* __restrict__ p) {
#pragma unroll
    for (int i = 0; i < PER / 2; i++) {
        float2 t = reinterpret_cast<const float2*>(p)[i];
        r[2 * i + 0] = t.x; r[2 * i + 1] = t.y;
    }
}
template<int PER>
__device__ __forceinline__ void vloadh(float* r, const __half* __restrict__ p) {
    if constexpr (PER % 8 == 0) {
#pragma unroll
        for (int i = 0; i < PER / 8; i++) {
            uint4 t = reinterpret_cast<const uint4*>(p)[i];
            const __half2* h = reinterpret_cast<const __half2*>(&t);
#pragma unroll
            for (int j = 0; j < 4; j++) {
                float2 f = __half22float2(h[j]);
                r[i * 8 + j * 2 + 0] = f.x;
                r[i * 8 + j * 2 + 1] = f.y;
            }
        }
    } else {
        float2 f = __half22float2(*reinterpret_cast<const __half2*>(p));
        r[0] = f.x; r[1] = f.y;
    }
}

// One warp per destination node; 4-edge phase-split pipeline (gather 4 k-rows,
// reduce 4 logits, reuse registers for 4 v-rows, one rescale per 4 edges).
// K/V gathered in fp16. Optionally fuses fp16 hi/lo split into the epilogue.
template<int HEADS, int CH, bool RELU, bool SPLIT>
__global__ void __launch_bounds__(256)
gat_agg_kernel(const float* __restrict__ Q, const __half* __restrict__ Kf,
               const __half* __restrict__ V,
               const int* __restrict__ rowptr, const int* __restrict__ srcs,
               float* __restrict__ out,
               __half* __restrict__ hi, __half* __restrict__ lo, int n)
{
    constexpr int NCH = HEADS * CH;
    constexpr int PER = NCH / 32;
    constexpr int RW  = CH / PER;
    const int lane = threadIdx.x & 31;
    const int node = blockIdx.x * (blockDim.x >> 5) + (threadIdx.x >> 5);
    if (node >= n) return;

    const float scale = rsqrtf((float)CH);
    const size_t base = (size_t)node * NCH + lane * PER;

    float qv[PER], acc[PER];
    vloadf<PER>(qv, Q + base);
#pragma unroll
    for (int i = 0; i < PER; i++) acc[i] = 0.f;

    float m = __int_as_float(0xff800000);
    float s = 0.f;

    const int e0 = rowptr[node];
    const int e1 = rowptr[node + 1];
    int e = e0;
    for (; e + 4 <= e1; e += 4) {
        size_t b[4];
#pragma unroll
        for (int j = 0; j < 4; j++)
            b[j] = (size_t)srcs[e + j] * NCH + lane * PER;

        float t0[PER], t1[PER], t2[PER], t3[PER];
        vloadh<PER>(t0, Kf + b[0]);
        vloadh<PER>(t1, Kf + b[1]);
        vloadh<PER>(t2, Kf + b[2]);
        vloadh<PER>(t3, Kf + b[3]);

        float p0 = 0.f, p1 = 0.f, p2 = 0.f, p3 = 0.f;
#pragma unroll
        for (int i = 0; i < PER; i++) {
            p0 = fmaf(qv[i], t0[i], p0); p1 = fmaf(qv[i], t1[i], p1);
            p2 = fmaf(qv[i], t2[i], p2); p3 = fmaf(qv[i], t3[i], p3);
        }
#pragma unroll
        for (int off = RW >> 1; off > 0; off >>= 1) {
            p0 += __shfl_xor_sync(0xffffffffu, p0, off);
            p1 += __shfl_xor_sync(0xffffffffu, p1, off);
            p2 += __shfl_xor_sync(0xffffffffu, p2, off);
            p3 += __shfl_xor_sync(0xffffffffu, p3, off);
        }
        const float a0 = p0 * scale, a1 = p1 * scale;
        const float a2 = p2 * scale, a3 = p3 * scale;
        const float mn = fmaxf(fmaxf(m, fmaxf(a0, a1)), fmaxf(a2, a3));
        const float corr = __expf(m - mn);
        const float w0 = __expf(a0 - mn), w1 = __expf(a1 - mn);
        const float w2 = __expf(a2 - mn), w3 = __expf(a3 - mn);
        s = s * corr + (w0 + w1) + (w2 + w3);

        // reuse t* registers for the v gather
        vloadh<PER>(t0, V + b[0]);
        vloadh<PER>(t1, V + b[1]);
        vloadh<PER>(t2, V + b[2]);
        vloadh<PER>(t3, V + b[3]);
#pragma unroll
        for (int i = 0; i < PER; i++)
            acc[i] = fmaf(acc[i], corr,
                          fmaf(w0, t0[i], fmaf(w1, t1[i], fmaf(w2, t2[i], w3 * t3[i]))));
        m = mn;
    }
    for (; e < e1; e++) {
        const int sn = srcs[e];
        const size_t sbx = (size_t)sn * NCH + lane * PER;
        float kv[PER], vv[PER];
        vloadh<PER>(kv, Kf + sbx);
        vloadh<PER>(vv, V  + sbx);
        float part = 0.f;
#pragma unroll
        for (int i = 0; i < PER; i++) part = fmaf(qv[i], kv[i], part);
#pragma unroll
        for (int off = RW >> 1; off > 0; off >>= 1)
            part += __shfl_xor_sync(0xffffffffu, part, off);
        const float alpha = part * scale;
        const float mn = fmaxf(m, alpha);
        const float corr = __expf(m - mn);
        const float w = __expf(alpha - mn);
        s = s * corr + w;
#pragma unroll
        for (int i = 0; i < PER; i++) acc[i] = fmaf(acc[i], corr, w * vv[i]);
        m = mn;
    }

    const float inv = 1.f / (s + 1e-16f);
#pragma unroll
    for (int i = 0; i < PER; i++) {
        float o = out[base + i] + acc[i] * inv;
        if (RELU) o = fmaxf(o, 0.f);
        out[base + i] = o;
        if (SPLIT) {
            __half h = __float2half(o);
            hi[base + i] = h;
            lo[base + i] = __float2half(o - __half2float(h));
        }
    }
}

// ======================= host orchestration =======================
extern "C" void kernel_launch(void* const* d_in, const int* in_sizes, int n_in,
                              void* d_out, int out_size)
{
    const float* x  = (const float*)d_in[0];
    const void*  ei = d_in[1];
    const int N = in_sizes[0] / 128;
    const int E = in_sizes[1] / 2;

    const float* P[24];
    for (int i = 0; i < 24; i++) P[i] = (const float*)d_in[2 + i];

    float *q, *h0, *h1, *biasf;
    __half *kh, *vh;
    __half *ahi, *alo, *whi, *wlo;
    int *rowptr, *cnt, *cur, *srcs;
    cudaGetSymbolAddress((void**)&q,  g_q);
    cudaGetSymbolAddress((void**)&kh, g_kh);
    cudaGetSymbolAddress((void**)&vh, g_vh);
    cudaGetSymbolAddress((void**)&h0, g_h0);
    cudaGetSymbolAddress((void**)&h1, g_h1);
    cudaGetSymbolAddress((void**)&ahi, g_ahi);
    cudaGetSymbolAddress((void**)&alo, g_alo);
    cudaGetSymbolAddress((void**)&whi, g_whi);
    cudaGetSymbolAddress((void**)&wlo, g_wlo);
    cudaGetSymbolAddress((void**)&biasf, g_biasf);
    cudaGetSymbolAddress((void**)&rowptr, g_rowptr);
    cudaGetSymbolAddress((void**)&cnt, g_cnt);
    cudaGetSymbolAddress((void**)&cur, g_cur);
    cudaGetSymbolAddress((void**)&srcs, g_srcs);

    cudaFuncSetAttribute(gemm_mma_kernel, cudaFuncAttributeMaxDynamicSharedMemorySize, SMEM_TOT);

    // side stream + events (created once; never allocates device memory)
    static cudaStream_t s2 = nullptr;
    static cudaEvent_t evA = nullptr, evB = nullptr, evC = nullptr;
    if (!s2) {
        cudaStreamCreateWithFlags(&s2, cudaStreamNonBlocking);
        cudaEventCreateWithFlags(&evA, cudaEventDisableTiming);
        cudaEventCreateWithFlags(&evB, cudaEventDisableTiming);
        cudaEventCreateWithFlags(&evC, cudaEventDisableTiming);
    }

    const int TB = 256;
    float* out = (float*)d_out;

    WTable wt;
    const int Ks[3] = {128, 512, 512};
    const int Ms[3] = {512, 512, 64};
    for (int l = 0; l < 3; l++)
        for (int j = 0; j < 4; j++) {
            wt.d[l * 4 + j].W = P[l * 8 + j * 2];
            wt.d[l * 4 + j].b = P[l * 8 + j * 2 + 1];
            wt.d[l * 4 + j].K = Ks[l];
            wt.d[l * 4 + j].M = Ms[l];
            wt.d[l * 4 + j].layer = l;
            wt.d[l * 4 + j].off = j * Ms[l];
        }

    // k+v column tiles (512..1535 => tiles 4-11) for layers 0/1 use 2-pass fp16
    const uint32_t LP01 = 0x0FF0u;

    // ---- fork: CSR build + layer-1/2 weight prep on s2 ----
    detect_kernel<<<1, 1>>>((const int*)ei);
    cudaEventRecord(evA, 0);
    cudaStreamWaitEvent(s2, evA, 0);
    zero_int_kernel<<<(N + TB - 1) / TB, TB, 0, s2>>>(cnt, N);
    hist_kernel<<<(E + TB - 1) / TB, TB, 0, s2>>>(ei, cnt, E);
    scan_kernel<<<1, 1024, 0, s2>>>(cnt, rowptr, cur, N);
    scatter_kernel<<<(E + TB - 1) / TB, TB, 0, s2>>>(ei, cur, srcs, E);
    cudaEventRecord(evB, s2);
    prep_weights_kernel<<<dim3(64, 8), TB, 0, s2>>>(wt, 4, whi, wlo, biasf);
    cudaEventRecord(evC, s2);

    // main stream: layer-0 prep + GEMM-0
    prep_weights_kernel<<<dim3(64, 4), TB>>>(wt, 0, whi, wlo, biasf);
    split_act_kernel<<<(N * 128 + TB - 1) / TB, TB>>>(x, ahi, alo, N * 128);

    const int mtiles = (N + 127) / 128;
    OutSpec os0;
    os0.out[0] = q; os0.out[1] = kh; os0.out[2] = vh; os0.out[3] = h0;
    os0.half_mask = 0b0110; os0.cpo = 512;
    gemm_mma_kernel<<<dim3(2048 / 128, mtiles), 256, SMEM_TOT>>>(
        ahi, alo, whi, wlo, biasf, os0, N, 128, LP01);

    cudaStreamWaitEvent(0, evB, 0);   // CSR ready before aggregation

    const int aggBlocks = (N + 7) / 8;
    gat_agg_kernel<8, 64, true, true><<<aggBlocks, 256>>>(
        q, kh, vh, rowptr, srcs, h0, ahi, alo, N);

    cudaStreamWaitEvent(0, evC, 0);   // layer-1/2 weights ready

    // ---- layer 1 ----
    OutSpec os1;
    os1.out[0] = q; os1.out[1] = kh; os1.out[2] = vh; os1.out[3] = h1;
    os1.half_mask = 0b0110; os1.cpo = 512;
    gemm_mma_kernel<<<dim3(2048 / 128, mtiles), 256, SMEM_TOT>>>(
        ahi, alo, whi + (size_t)1 * NTOTMAX * KMAX, wlo + (size_t)1 * NTOTMAX * KMAX,
        biasf + NTOTMAX, os1, N, 512, LP01);
    gat_agg_kernel<8, 64, true, true><<<aggBlocks, 256>>>(
        q, kh, vh, rowptr, srcs, h1, ahi, alo, N);

    // ---- layer 2 (heads=1, ch=64) ----
    OutSpec os2;
    os2.out[0] = q; os2.out[1] = kh; os2.out[2] = vh; os2.out[3] = out;
    os2.half_mask = 0b0110; os2.cpo = 64;
    gemm_mma_kernel<<<dim3(256 / 128, mtiles), 256, SMEM_TOT>>>(
        ahi, alo, whi + (size_t)2 * NTOTMAX * KMAX, wlo + (size_t)2 * NTOTMAX * KMAX,
        biasf + 2 * NTOTMAX, os2, N, 512, 0u);
    gat_agg_kernel<1, 64, false, false><<<aggBlocks, 256>>>(
        q, kh, vh, rowptr, srcs, out, nullptr, nullptr, N);
}

// round 10
// speedup vs baseline: 2.4318x; 1.0942x over previous
#include <cuda_runtime.h>
#include <cuda_fp16.h>
#include <cstdint>

#define NMAX 50000
#define EMAX 800000
#define KMAX 512
#define NTOTMAX 2048

// ======================= low-level helpers (sm_80-compatible PTX) ==========
__device__ __forceinline__ uint32_t smem_u32(const void* p) {
    uint32_t a;
    asm("{ .reg .u64 t; cvta.to.shared.u64 t, %1; cvt.u32.u64 %0, t; }" : "=r"(a) : "l"(p));
    return a;
}
__device__ __forceinline__ void cp16(uint32_t dst, const void* src, int srcsize) {
    asm volatile("cp.async.cg.shared.global [%0], [%1], 16, %2;"
                 :: "r"(dst), "l"(src), "r"(srcsize));
}
__device__ __forceinline__ void ldm_x4(uint32_t& r0, uint32_t& r1, uint32_t& r2, uint32_t& r3,
                                       uint32_t addr) {
    asm volatile("ldmatrix.sync.aligned.m8n8.x4.shared.b16 {%0,%1,%2,%3}, [%4];"
                 : "=r"(r0), "=r"(r1), "=r"(r2), "=r"(r3) : "r"(addr));
}
__device__ __forceinline__ void mma16816(float* c, const uint32_t* a, const uint32_t* b) {
    asm volatile("mma.sync.aligned.m16n8k16.row.col.f32.f16.f16.f32 "
                 "{%0,%1,%2,%3}, {%4,%5,%6,%7}, {%8,%9}, {%0,%1,%2,%3};"
                 : "+f"(c[0]), "+f"(c[1]), "+f"(c[2]), "+f"(c[3])
                 : "r"(a[0]), "r"(a[1]), "r"(a[2]), "r"(a[3]), "r"(b[0]), "r"(b[1]));
}

// ======================= scratch (device globals) =======================
__device__ float  g_q [NMAX * 512];
__device__ __half g_kh[NMAX * 512];
__device__ __half g_vh[NMAX * 512];
__device__ float  g_h0[NMAX * 512];
__device__ float  g_h1[NMAX * 512];
__device__ __half g_ahi[NMAX * KMAX];
__device__ __half g_alo[NMAX * KMAX];
__device__ __half g_whi[3 * NTOTMAX * KMAX];
__device__ __half g_wlo[3 * NTOTMAX * KMAX];
__device__ float g_biasf[3 * NTOTMAX];
__device__ int   g_rowptr[NMAX + 1];
__device__ int   g_cnt[NMAX];
__device__ int   g_cur[NMAX];
__device__ int   g_srcs[EMAX];
__device__ int   g_is64;

// ======================= edge dtype detection =======================
__global__ void detect_kernel(const int* __restrict__ w) {
    int odd_nonzero = 0;
    for (int i = 0; i < 128; i++) odd_nonzero += (w[2 * i + 1] != 0);
    g_is64 = (odd_nonzero == 0) ? 1 : 0;
}
__device__ __forceinline__ int edge_at(const void* ei, long long idx, int is64) {
    return is64 ? (int)((const long long*)ei)[idx] : ((const int*)ei)[idx];
}

// ======================= CSR build =======================
__global__ void zero_int_kernel(int* __restrict__ p, int n) {
    int i = blockIdx.x * blockDim.x + threadIdx.x;
    if (i < n) p[i] = 0;
}
__global__ void hist_kernel(const void* __restrict__ ei, int* __restrict__ cnt, int E) {
    int e = blockIdx.x * blockDim.x + threadIdx.x;
    if (e < E) atomicAdd(&cnt[edge_at(ei, (long long)E + e, g_is64)], 1);
}
__global__ void scan_kernel(const int* __restrict__ cnt, int* __restrict__ rowptr,
                            int* __restrict__ cur, int n) {
    __shared__ int part[1024];
    const int t = threadIdx.x;
    const int chunk = (n + 1023) >> 10;
    int b = t * chunk; if (b > n) b = n;
    int e = b + chunk; if (e > n) e = n;
    int s = 0;
    for (int i = b; i < e; i++) s += cnt[i];
    part[t] = s;
    __syncthreads();
    if (t == 0) {
        int a = 0;
        for (int i = 0; i < 1024; i++) { int v = part[i]; part[i] = a; a += v; }
    }
    __syncthreads();
    int off = part[t];
    for (int i = b; i < e; i++) { rowptr[i] = off; cur[i] = off; off += cnt[i]; }
    if (t == 1023) rowptr[n] = off;
}
__global__ void scatter_kernel(const void* __restrict__ ei, int* __restrict__ cur,
                               int* __restrict__ srcs, int E) {
    int e = blockIdx.x * blockDim.x + threadIdx.x;
    if (e < E) {
        const int is64 = g_is64;
        int d = edge_at(ei, (long long)E + e, is64);
        int p = atomicAdd(&cur[d], 1);
        srcs[p] = edge_at(ei, e, is64);
    }
}

// ======================= weight prep: transpose + fp16 hi/lo split =========
struct WDesc { const float* W; const float* b; int K; int M; int layer; int off; };
struct WTable { WDesc d[12]; };

__global__ void prep_weights_kernel(WTable t, int y0, __half* __restrict__ whi,
                                    __half* __restrict__ wlo, float* __restrict__ biasf) {
    const WDesc w = t.d[y0 + blockIdx.y];
    const size_t base = (size_t)w.layer * NTOTMAX * KMAX;
    const int stride = gridDim.x * blockDim.x;
    for (int i = blockIdx.x * blockDim.x + threadIdx.x; i < w.M; i += stride)
        biasf[w.layer * NTOTMAX + w.off + i] = w.b[i];
    const int total = w.K * w.M;
    for (int i = blockIdx.x * blockDim.x + threadIdx.x; i < total; i += stride) {
        int k = i / w.M, m = i % w.M;
        float v = w.W[i];
        __half hi = __float2half(v);
        float lo = v - __half2float(hi);
        size_t dst = base + (size_t)(w.off + m) * w.K + k;
        whi[dst] = hi;
        wlo[dst] = __float2half(lo);
    }
}

// ======================= activation fp16 hi/lo split (input x only) ========
__global__ void split_act_kernel(const float* __restrict__ x, __half* __restrict__ hi,
                                 __half* __restrict__ lo, int total) {
    int i = blockIdx.x * blockDim.x + threadIdx.x;
    if (i < total) {
        float v = x[i];
        __half h = __float2half(v);
        hi[i] = h;
        lo[i] = __float2half(v - __half2float(h));
    }
}

// ======================= HMMA GEMM: C[N, ntot] = A @ Wt^T + bias ===========
// fp16 split in register accumulators. Per-column-tile pass count:
//   3-pass: Ahi*Bhi + Alo*Bhi + Ahi*Blo   (skip / output tiles)
//   2-pass: Ahi*Bhi + Alo*Bhi             (lp2 tiles: q)
//   1-pass: Ahi*Bhi                       (lp1 tiles: k,v — already fp16-stored)
// Unneeded Alo/Blo tile loads are skipped per level.
// kc-outer / pass-inner, double-buffered 4-region SMEM, one wait+sync per kc.
// CTA tile 128x128, BK=32, 8 warps (2x4), warp tile 64x32.
#define STG_BYTES 10240                 /* 128 rows * 80B padded */
#define SMEM_TOT  (8 * STG_BYTES)       /* 4 tensors x 2 slots = 81920 */

struct OutSpec { void* out[4]; int half_mask; int cpo; };

__global__ void __launch_bounds__(256, 2)
gemm_mma_kernel(const __half* __restrict__ Ahi, const __half* __restrict__ Alo,
                const __half* __restrict__ Whi, const __half* __restrict__ Wlo,
                const float* __restrict__ biasf, OutSpec os, int Nrows, int K,
                uint32_t lp2_mask, uint32_t lp1_mask)
{
    extern __shared__ char smem[];
    const uint32_t sb = smem_u32(smem);
    const int tid = threadIdx.x, lane = tid & 31, wid = tid >> 5;
    const int wm = wid & 1, wn = wid >> 1;
    const int m0 = blockIdx.y * 128, n0 = blockIdx.x * 128;
    const int KT = K / 32;
    const int npass = ((lp1_mask >> blockIdx.x) & 1u) ? 1
                    : (((lp2_mask >> blockIdx.x) & 1u) ? 2 : 3);

    float acc[4][4][4];
#pragma unroll
    for (int a = 0; a < 4; a++)
#pragma unroll
        for (int b = 0; b < 4; b++)
#pragma unroll
            for (int c = 0; c < 4; c++) acc[a][b][c] = 0.f;

    const int r0 = tid >> 2, c0 = tid & 3;
    const int r1 = r0 + 64;

    // region(tensor, slot) base: tensor 0=Ahi 1=Alo 2=Bhi 3=Blo
    auto issueKC = [&](int kc) {
        const int slot = kc & 1;
        const int koff = kc * 32;
        int ar0 = m0 + r0; bool v0 = ar0 < Nrows; if (!v0) ar0 = 0;
        int ar1 = m0 + r1; bool v1 = ar1 < Nrows; if (!v1) ar1 = 0;
        const uint32_t sAhi = sb + (0 * 2 + slot) * STG_BYTES;
        const uint32_t sAlo = sb + (1 * 2 + slot) * STG_BYTES;
        const uint32_t sBhi = sb + (2 * 2 + slot) * STG_BYTES;
        const uint32_t sBlo = sb + (3 * 2 + slot) * STG_BYTES;
        const uint32_t ro0 = r0 * 80 + c0 * 16, ro1 = r1 * 80 + c0 * 16;
        cp16(sAhi + ro0, Ahi + (size_t)ar0 * K + koff + c0 * 8, v0 ? 16 : 0);
        cp16(sAhi + ro1, Ahi + (size_t)ar1 * K + koff + c0 * 8, v1 ? 16 : 0);
        if (npass >= 2) {
            cp16(sAlo + ro0, Alo + (size_t)ar0 * K + koff + c0 * 8, v0 ? 16 : 0);
            cp16(sAlo + ro1, Alo + (size_t)ar1 * K + koff + c0 * 8, v1 ? 16 : 0);
        }
        cp16(sBhi + ro0, Whi + (size_t)(n0 + r0) * K + koff + c0 * 8, 16);
        cp16(sBhi + ro1, Whi + (size_t)(n0 + r1) * K + koff + c0 * 8, 16);
        if (npass == 3) {
            cp16(sBlo + ro0, Wlo + (size_t)(n0 + r0) * K + koff + c0 * 8, 16);
            cp16(sBlo + ro1, Wlo + (size_t)(n0 + r1) * K + koff + c0 * 8, 16);
        }
    };

    // per-warp ldmatrix local offsets (within a region)
    const uint32_t aLoc = (uint32_t)((wm * 64 + (lane & 15)) * 80 + (lane >> 4) * 16);
    const uint32_t bLoc = (uint32_t)((wn * 32 + (lane & 7) + ((lane >> 4) << 3)) * 80
                                     + ((lane >> 3) & 1) * 16);

    issueKC(0);
    asm volatile("cp.async.commit_group;" ::: "memory");

    for (int kc = 0; kc < KT; kc++) {
        asm volatile("cp.async.wait_group 0;" ::: "memory");
        __syncthreads();
        if (kc + 1 < KT) {
            issueKC(kc + 1);
            asm volatile("cp.async.commit_group;" ::: "memory");
        }
        const int slot = kc & 1;
#pragma unroll
        for (int pass = 0; pass < 3; pass++) {
            if (pass >= npass) break;
            const int aR = (pass == 1) ? 1 : 0;   // Alo on pass 1
            const int bR = (pass == 2) ? 3 : 2;   // Blo on pass 2
            const uint32_t aBase = sb + (uint32_t)(aR * 2 + slot) * STG_BYTES + aLoc;
            const uint32_t bBase = sb + (uint32_t)(bR * 2 + slot) * STG_BYTES + bLoc;
#pragma unroll
            for (int ks = 0; ks < 2; ks++) {
                uint32_t a[4][4], b[2][4];
#pragma unroll
                for (int mi = 0; mi < 4; mi++)
                    ldm_x4(a[mi][0], a[mi][1], a[mi][2], a[mi][3],
                           aBase + mi * 16 * 80 + ks * 32);
#pragma unroll
                for (int nj = 0; nj < 2; nj++)
                    ldm_x4(b[nj][0], b[nj][1], b[nj][2], b[nj][3],
                           bBase + nj * 16 * 80 + ks * 32);
#pragma unroll
                for (int mi = 0; mi < 4; mi++)
#pragma unroll
                    for (int ni = 0; ni < 4; ni++)
                        mma16816(acc[mi][ni], a[mi], &b[ni >> 1][(ni & 1) * 2]);
            }
        }
    }

    const int erow = lane >> 2, ecol = (lane & 3) * 2;
#pragma unroll
    for (int mi = 0; mi < 4; mi++) {
#pragma unroll
        for (int half = 0; half < 2; half++) {
            const int gr = m0 + wm * 64 + mi * 16 + erow + half * 8;
            if (gr >= Nrows) continue;
#pragma unroll
            for (int ni = 0; ni < 4; ni++) {
                const int gc = n0 + wn * 32 + ni * 8 + ecol;
                const int slot = gc / os.cpo;
                const int loc  = gc % os.cpo;
                float ox = acc[mi][ni][half * 2 + 0] + biasf[gc + 0];
                float oy = acc[mi][ni][half * 2 + 1] + biasf[gc + 1];
                if (os.half_mask & (1 << slot)) {
                    __half2 h2 = __floats2half2_rn(ox, oy);
                    *reinterpret_cast<__half2*>((__half*)os.out[slot] + (size_t)gr * os.cpo + loc) = h2;
                } else {
                    float2 o = make_float2(ox, oy);
                    *reinterpret_cast<float2*>((float*)os.out[slot] + (size_t)gr * os.cpo + loc) = o;
                }
            }
        }
    }
}

// ======================= per-node attention aggregation =======================
template<int PER>
__device__ __forceinline__ void vloadf(float* r, const float* __restrict__ p) {
#pragma unroll
    for (int i = 0; i < PER / 2; i++) {
        float2 t = reinterpret_cast<const float2*>(p)[i];
        r[2 * i + 0] = t.x; r[2 * i + 1] = t.y;
    }
}
template<int PER>
__device__ __forceinline__ void vloadh(float* r, const __half* __restrict__ p) {
    if constexpr (PER % 8 == 0) {
#pragma unroll
        for (int i = 0; i < PER / 8; i++) {
            uint4 t = reinterpret_cast<const uint4*>(p)[i];
            const __half2* h = reinterpret_cast<const __half2*>(&t);
#pragma unroll
            for (int j = 0; j < 4; j++) {
                float2 f = __half22float2(h[j]);
                r[i * 8 + j * 2 + 0] = f.x;
                r[i * 8 + j * 2 + 1] = f.y;
            }
        }
    } else {
        float2 f = __half22float2(*reinterpret_cast<const __half2*>(p));
        r[0] = f.x; r[1] = f.y;
    }
}

// One warp per destination node; 4-edge phase-split pipeline (gather 4 k-rows,
// reduce 4 logits, reuse registers for 4 v-rows, one rescale per 4 edges).
// K/V gathered in fp16. Optionally fuses fp16 hi/lo split into the epilogue.
template<int HEADS, int CH, bool RELU, bool SPLIT>
__global__ void __launch_bounds__(256)
gat_agg_kernel(const float* __restrict__ Q, const __half* __restrict__ Kf,
               const __half* __restrict__ V,
               const int* __restrict__ rowptr, const int* __restrict__ srcs,
               float* __restrict__ out,
               __half* __restrict__ hi, __half* __restrict__ lo, int n)
{
    constexpr int NCH = HEADS * CH;
    constexpr int PER = NCH / 32;
    constexpr int RW  = CH / PER;
    const int lane = threadIdx.x & 31;
    const int node = blockIdx.x * (blockDim.x >> 5) + (threadIdx.x >> 5);
    if (node >= n) return;

    const float scale = rsqrtf((float)CH);
    const size_t base = (size_t)node * NCH + lane * PER;

    float qv[PER], acc[PER];
    vloadf<PER>(qv, Q + base);
#pragma unroll
    for (int i = 0; i < PER; i++) acc[i] = 0.f;

    float m = __int_as_float(0xff800000);
    float s = 0.f;

    const int e0 = rowptr[node];
    const int e1 = rowptr[node + 1];
    int e = e0;
    for (; e + 4 <= e1; e += 4) {
        size_t b[4];
#pragma unroll
        for (int j = 0; j < 4; j++)
            b[j] = (size_t)srcs[e + j] * NCH + lane * PER;

        float t0[PER], t1[PER], t2[PER], t3[PER];
        vloadh<PER>(t0, Kf + b[0]);
        vloadh<PER>(t1, Kf + b[1]);
        vloadh<PER>(t2, Kf + b[2]);
        vloadh<PER>(t3, Kf + b[3]);

        float p0 = 0.f, p1 = 0.f, p2 = 0.f, p3 = 0.f;
#pragma unroll
        for (int i = 0; i < PER; i++) {
            p0 = fmaf(qv[i], t0[i], p0); p1 = fmaf(qv[i], t1[i], p1);
            p2 = fmaf(qv[i], t2[i], p2); p3 = fmaf(qv[i], t3[i], p3);
        }
#pragma unroll
        for (int off = RW >> 1; off > 0; off >>= 1) {
            p0 += __shfl_xor_sync(0xffffffffu, p0, off);
            p1 += __shfl_xor_sync(0xffffffffu, p1, off);
            p2 += __shfl_xor_sync(0xffffffffu, p2, off);
            p3 += __shfl_xor_sync(0xffffffffu, p3, off);
        }
        const float a0 = p0 * scale, a1 = p1 * scale;
        const float a2 = p2 * scale, a3 = p3 * scale;
        const float mn = fmaxf(fmaxf(m, fmaxf(a0, a1)), fmaxf(a2, a3));
        const float corr = __expf(m - mn);
        const float w0 = __expf(a0 - mn), w1 = __expf(a1 - mn);
        const float w2 = __expf(a2 - mn), w3 = __expf(a3 - mn);
        s = s * corr + (w0 + w1) + (w2 + w3);

        // reuse t* registers for the v gather
        vloadh<PER>(t0, V + b[0]);
        vloadh<PER>(t1, V + b[1]);
        vloadh<PER>(t2, V + b[2]);
        vloadh<PER>(t3, V + b[3]);
#pragma unroll
        for (int i = 0; i < PER; i++)
            acc[i] = fmaf(acc[i], corr,
                          fmaf(w0, t0[i], fmaf(w1, t1[i], fmaf(w2, t2[i], w3 * t3[i]))));
        m = mn;
    }
    for (; e < e1; e++) {
        const int sn = srcs[e];
        const size_t sbx = (size_t)sn * NCH + lane * PER;
        float kv[PER], vv[PER];
        vloadh<PER>(kv, Kf + sbx);
        vloadh<PER>(vv, V  + sbx);
        float part = 0.f;
#pragma unroll
        for (int i = 0; i < PER; i++) part = fmaf(qv[i], kv[i], part);
#pragma unroll
        for (int off = RW >> 1; off > 0; off >>= 1)
            part += __shfl_xor_sync(0xffffffffu, part, off);
        const float alpha = part * scale;
        const float mn = fmaxf(m, alpha);
        const float corr = __expf(m - mn);
        const float w = __expf(alpha - mn);
        s = s * corr + w;
#pragma unroll
        for (int i = 0; i < PER; i++) acc[i] = fmaf(acc[i], corr, w * vv[i]);
        m = mn;
    }

    const float inv = 1.f / (s + 1e-16f);
#pragma unroll
    for (int i = 0; i < PER; i++) {
        float o = out[base + i] + acc[i] * inv;
        if (RELU) o = fmaxf(o, 0.f);
        out[base + i] = o;
        if (SPLIT) {
            __half h = __float2half(o);
            hi[base + i] = h;
            lo[base + i] = __float2half(o - __half2float(h));
        }
    }
}

// ======================= host orchestration =======================
extern "C" void kernel_launch(void* const* d_in, const int* in_sizes, int n_in,
                              void* d_out, int out_size)
{
    const float* x  = (const float*)d_in[0];
    const void*  ei = d_in[1];
    const int N = in_sizes[0] / 128;
    const int E = in_sizes[1] / 2;

    const float* P[24];
    for (int i = 0; i < 24; i++) P[i] = (const float*)d_in[2 + i];

    float *q, *h0, *h1, *biasf;
    __half *kh, *vh;
    __half *ahi, *alo, *whi, *wlo;
    int *rowptr, *cnt, *cur, *srcs;
    cudaGetSymbolAddress((void**)&q,  g_q);
    cudaGetSymbolAddress((void**)&kh, g_kh);
    cudaGetSymbolAddress((void**)&vh, g_vh);
    cudaGetSymbolAddress((void**)&h0, g_h0);
    cudaGetSymbolAddress((void**)&h1, g_h1);
    cudaGetSymbolAddress((void**)&ahi, g_ahi);
    cudaGetSymbolAddress((void**)&alo, g_alo);
    cudaGetSymbolAddress((void**)&whi, g_whi);
    cudaGetSymbolAddress((void**)&wlo, g_wlo);
    cudaGetSymbolAddress((void**)&biasf, g_biasf);
    cudaGetSymbolAddress((void**)&rowptr, g_rowptr);
    cudaGetSymbolAddress((void**)&cnt, g_cnt);
    cudaGetSymbolAddress((void**)&cur, g_cur);
    cudaGetSymbolAddress((void**)&srcs, g_srcs);

    cudaFuncSetAttribute(gemm_mma_kernel, cudaFuncAttributeMaxDynamicSharedMemorySize, SMEM_TOT);

    // side stream + events (created once; never allocates device memory)
    static cudaStream_t s2 = nullptr;
    static cudaEvent_t evA = nullptr, evB = nullptr, evC = nullptr;
    if (!s2) {
        cudaStreamCreateWithFlags(&s2, cudaStreamNonBlocking);
        cudaEventCreateWithFlags(&evA, cudaEventDisableTiming);
        cudaEventCreateWithFlags(&evB, cudaEventDisableTiming);
        cudaEventCreateWithFlags(&evC, cudaEventDisableTiming);
    }

    const int TB = 256;
    float* out = (float*)d_out;

    WTable wt;
    const int Ks[3] = {128, 512, 512};
    const int Ms[3] = {512, 512, 64};
    for (int l = 0; l < 3; l++)
        for (int j = 0; j < 4; j++) {
            wt.d[l * 4 + j].W = P[l * 8 + j * 2];
            wt.d[l * 4 + j].b = P[l * 8 + j * 2 + 1];
            wt.d[l * 4 + j].K = Ks[l];
            wt.d[l * 4 + j].M = Ms[l];
            wt.d[l * 4 + j].layer = l;
            wt.d[l * 4 + j].off = j * Ms[l];
        }

    // layers 0/1 column tiles: q (0-3) 2-pass, k+v (4-11) 1-pass, skip (12-15) 3-pass
    const uint32_t LP2_01 = 0x000Fu;
    const uint32_t LP1_01 = 0x0FF0u;

    // ---- fork: CSR build + layer-1/2 weight prep on s2 ----
    detect_kernel<<<1, 1>>>((const int*)ei);
    cudaEventRecord(evA, 0);
    cudaStreamWaitEvent(s2, evA, 0);
    zero_int_kernel<<<(N + TB - 1) / TB, TB, 0, s2>>>(cnt, N);
    hist_kernel<<<(E + TB - 1) / TB, TB, 0, s2>>>(ei, cnt, E);
    scan_kernel<<<1, 1024, 0, s2>>>(cnt, rowptr, cur, N);
    scatter_kernel<<<(E + TB - 1) / TB, TB, 0, s2>>>(ei, cur, srcs, E);
    cudaEventRecord(evB, s2);
    prep_weights_kernel<<<dim3(64, 8), TB, 0, s2>>>(wt, 4, whi, wlo, biasf);
    cudaEventRecord(evC, s2);

    // main stream: layer-0 prep + GEMM-0
    prep_weights_kernel<<<dim3(64, 4), TB>>>(wt, 0, whi, wlo, biasf);
    split_act_kernel<<<(N * 128 + TB - 1) / TB, TB>>>(x, ahi, alo, N * 128);

    const int mtiles = (N + 127) / 128;
    OutSpec os0;
    os0.out[0] = q; os0.out[1] = kh; os0.out[2] = vh; os0.out[3] = h0;
    os0.half_mask = 0b0110; os0.cpo = 512;
    gemm_mma_kernel<<<dim3(2048 / 128, mtiles), 256, SMEM_TOT>>>(
        ahi, alo, whi, wlo, biasf, os0, N, 128, LP2_01, LP1_01);

    cudaStreamWaitEvent(0, evB, 0);   // CSR ready before aggregation

    const int aggBlocks = (N + 7) / 8;
    gat_agg_kernel<8, 64, true, true><<<aggBlocks, 256>>>(
        q, kh, vh, rowptr, srcs, h0, ahi, alo, N);

    cudaStreamWaitEvent(0, evC, 0);   // layer-1/2 weights ready

    // ---- layer 1 ----
    OutSpec os1;
    os1.out[0] = q; os1.out[1] = kh; os1.out[2] = vh; os1.out[3] = h1;
    os1.half_mask = 0b0110; os1.cpo = 512;
    gemm_mma_kernel<<<dim3(2048 / 128, mtiles), 256, SMEM_TOT>>>(
        ahi, alo, whi + (size_t)1 * NTOTMAX * KMAX, wlo + (size_t)1 * NTOTMAX * KMAX,
        biasf + NTOTMAX, os1, N, 512, LP2_01, LP1_01);
    gat_agg_kernel<8, 64, true, true><<<aggBlocks, 256>>>(
        q, kh, vh, rowptr, srcs, h1, ahi, alo, N);

    // ---- layer 2 (heads=1, ch=64): full 3-pass everywhere ----
    OutSpec os2;
    os2.out[0] = q; os2.out[1] = kh; os2.out[2] = vh; os2.out[3] = out;
    os2.half_mask = 0b0110; os2.cpo = 64;
    gemm_mma_kernel<<<dim3(256 / 128, mtiles), 256, SMEM_TOT>>>(
        ahi, alo, whi + (size_t)2 * NTOTMAX * KMAX, wlo + (size_t)2 * NTOTMAX * KMAX,
        biasf + 2 * NTOTMAX, os2, N, 512, 0u, 0u);
    gat_agg_kernel<1, 64, false, false><<<aggBlocks, 256>>>(
        q, kh, vh, rowptr, srcs, out, nullptr, nullptr, N);
}

// round 11
// speedup vs baseline: 2.5435x; 1.0459x over previous
#include <cuda_runtime.h>
#include <cuda_fp16.h>
#include <cstdint>

#define NMAX 50000
#define EMAX 800000
#define KMAX 512
#define NTOTMAX 2048

// ======================= low-level helpers (sm_80-compatible PTX) ==========
__device__ __forceinline__ uint32_t smem_u32(const void* p) {
    uint32_t a;
    asm("{ .reg .u64 t; cvta.to.shared.u64 t, %1; cvt.u32.u64 %0, t; }" : "=r"(a) : "l"(p));
    return a;
}
__device__ __forceinline__ void cp16(uint32_t dst, const void* src, int srcsize) {
    asm volatile("cp.async.cg.shared.global [%0], [%1], 16, %2;"
                 :: "r"(dst), "l"(src), "r"(srcsize));
}
__device__ __forceinline__ void ldm_x4(uint32_t& r0, uint32_t& r1, uint32_t& r2, uint32_t& r3,
                                       uint32_t addr) {
    asm volatile("ldmatrix.sync.aligned.m8n8.x4.shared.b16 {%0,%1,%2,%3}, [%4];"
                 : "=r"(r0), "=r"(r1), "=r"(r2), "=r"(r3) : "r"(addr));
}
__device__ __forceinline__ void mma16816(float* c, const uint32_t* a, const uint32_t* b) {
    asm volatile("mma.sync.aligned.m16n8k16.row.col.f32.f16.f16.f32 "
                 "{%0,%1,%2,%3}, {%4,%5,%6,%7}, {%8,%9}, {%0,%1,%2,%3};"
                 : "+f"(c[0]), "+f"(c[1]), "+f"(c[2]), "+f"(c[3])
                 : "r"(a[0]), "r"(a[1]), "r"(a[2]), "r"(a[3]), "r"(b[0]), "r"(b[1]));
}

// ======================= scratch (device globals) =======================
__device__ float  g_q [NMAX * 512];
__device__ __half g_kh[NMAX * 512];
__device__ __half g_vh[NMAX * 512];
__device__ float  g_h0[NMAX * 512];
__device__ float  g_h1[NMAX * 512];
__device__ __half g_ahi[NMAX * KMAX];
__device__ __half g_alo[NMAX * KMAX];
__device__ __half g_whi[3 * NTOTMAX * KMAX];
__device__ __half g_wlo[3 * NTOTMAX * KMAX];
__device__ float g_biasf[3 * NTOTMAX];
__device__ int   g_rowptr[NMAX + 1];
__device__ int   g_cnt[NMAX];
__device__ int   g_cur[NMAX];
__device__ int   g_srcs[EMAX];
__device__ int   g_is64;

// ======================= edge dtype detection =======================
__global__ void detect_kernel(const int* __restrict__ w) {
    int odd_nonzero = 0;
    for (int i = 0; i < 128; i++) odd_nonzero += (w[2 * i + 1] != 0);
    g_is64 = (odd_nonzero == 0) ? 1 : 0;
}
__device__ __forceinline__ int edge_at(const void* ei, long long idx, int is64) {
    return is64 ? (int)((const long long*)ei)[idx] : ((const int*)ei)[idx];
}

// ======================= CSR build =======================
__global__ void zero_int_kernel(int* __restrict__ p, int n) {
    int i = blockIdx.x * blockDim.x + threadIdx.x;
    if (i < n) p[i] = 0;
}
__global__ void hist_kernel(const void* __restrict__ ei, int* __restrict__ cnt, int E) {
    int e = blockIdx.x * blockDim.x + threadIdx.x;
    if (e < E) atomicAdd(&cnt[edge_at(ei, (long long)E + e, g_is64)], 1);
}
__global__ void scan_kernel(const int* __restrict__ cnt, int* __restrict__ rowptr,
                            int* __restrict__ cur, int n) {
    __shared__ int part[1024];
    const int t = threadIdx.x;
    const int chunk = (n + 1023) >> 10;
    int b = t * chunk; if (b > n) b = n;
    int e = b + chunk; if (e > n) e = n;
    int s = 0;
    for (int i = b; i < e; i++) s += cnt[i];
    part[t] = s;
    __syncthreads();
    if (t == 0) {
        int a = 0;
        for (int i = 0; i < 1024; i++) { int v = part[i]; part[i] = a; a += v; }
    }
    __syncthreads();
    int off = part[t];
    for (int i = b; i < e; i++) { rowptr[i] = off; cur[i] = off; off += cnt[i]; }
    if (t == 1023) rowptr[n] = off;
}
__global__ void scatter_kernel(const void* __restrict__ ei, int* __restrict__ cur,
                               int* __restrict__ srcs, int E) {
    int e = blockIdx.x * blockDim.x + threadIdx.x;
    if (e < E) {
        const int is64 = g_is64;
        int d = edge_at(ei, (long long)E + e, is64);
        int p = atomicAdd(&cur[d], 1);
        srcs[p] = edge_at(ei, e, is64);
    }
}

// ======================= weight prep: transpose + fp16 hi/lo split =========
struct WDesc { const float* W; const float* b; int K; int M; int layer; int off; };
struct WTable { WDesc d[12]; };

__global__ void prep_weights_kernel(WTable t, int y0, __half* __restrict__ whi,
                                    __half* __restrict__ wlo, float* __restrict__ biasf) {
    const WDesc w = t.d[y0 + blockIdx.y];
    const size_t base = (size_t)w.layer * NTOTMAX * KMAX;
    const int stride = gridDim.x * blockDim.x;
    for (int i = blockIdx.x * blockDim.x + threadIdx.x; i < w.M; i += stride)
        biasf[w.layer * NTOTMAX + w.off + i] = w.b[i];
    const int total = w.K * w.M;
    for (int i = blockIdx.x * blockDim.x + threadIdx.x; i < total; i += stride) {
        int k = i / w.M, m = i % w.M;
        float v = w.W[i];
        __half hi = __float2half(v);
        float lo = v - __half2float(hi);
        size_t dst = base + (size_t)(w.off + m) * w.K + k;
        whi[dst] = hi;
        wlo[dst] = __float2half(lo);
    }
}

// ======================= activation fp16 hi/lo split (input x only) ========
__global__ void split_act_kernel(const float* __restrict__ x, __half* __restrict__ hi,
                                 __half* __restrict__ lo, int total) {
    int i = blockIdx.x * blockDim.x + threadIdx.x;
    if (i < total) {
        float v = x[i];
        __half h = __float2half(v);
        hi[i] = h;
        lo[i] = __float2half(v - __half2float(h));
    }
}

// ======================= HMMA GEMM: C[N, ntot] = A @ Wt^T + bias ===========
// fp16 split in register accumulators. Per-column-tile pass count:
//   3-pass: Ahi*Bhi + Alo*Bhi + Ahi*Blo   (skip / output tiles)
//   2-pass: Ahi*Bhi + Alo*Bhi             (lp2 tiles)
//   1-pass: Ahi*Bhi                       (lp1 tiles: q,k,v — logits / fp16-stored)
// Unneeded Alo/Blo tile loads are skipped per level.
// kc-outer / pass-inner, double-buffered 4-region SMEM, one wait+sync per kc.
// CTA tile 128x128, BK=32, 8 warps (2x4), warp tile 64x32.
#define STG_BYTES 10240                 /* 128 rows * 80B padded */
#define SMEM_TOT  (8 * STG_BYTES)       /* 4 tensors x 2 slots = 81920 */

struct OutSpec { void* out[4]; int half_mask; int cpo; };

__global__ void __launch_bounds__(256, 2)
gemm_mma_kernel(const __half* __restrict__ Ahi, const __half* __restrict__ Alo,
                const __half* __restrict__ Whi, const __half* __restrict__ Wlo,
                const float* __restrict__ biasf, OutSpec os, int Nrows, int K,
                uint32_t lp2_mask, uint32_t lp1_mask)
{
    extern __shared__ char smem[];
    const uint32_t sb = smem_u32(smem);
    const int tid = threadIdx.x, lane = tid & 31, wid = tid >> 5;
    const int wm = wid & 1, wn = wid >> 1;
    const int m0 = blockIdx.y * 128, n0 = blockIdx.x * 128;
    const int KT = K / 32;
    const int npass = ((lp1_mask >> blockIdx.x) & 1u) ? 1
                    : (((lp2_mask >> blockIdx.x) & 1u) ? 2 : 3);

    float acc[4][4][4];
#pragma unroll
    for (int a = 0; a < 4; a++)
#pragma unroll
        for (int b = 0; b < 4; b++)
#pragma unroll
            for (int c = 0; c < 4; c++) acc[a][b][c] = 0.f;

    const int r0 = tid >> 2, c0 = tid & 3;
    const int r1 = r0 + 64;

    // region(tensor, slot) base: tensor 0=Ahi 1=Alo 2=Bhi 3=Blo
    auto issueKC = [&](int kc) {
        const int slot = kc & 1;
        const int koff = kc * 32;
        int ar0 = m0 + r0; bool v0 = ar0 < Nrows; if (!v0) ar0 = 0;
        int ar1 = m0 + r1; bool v1 = ar1 < Nrows; if (!v1) ar1 = 0;
        const uint32_t sAhi = sb + (0 * 2 + slot) * STG_BYTES;
        const uint32_t sAlo = sb + (1 * 2 + slot) * STG_BYTES;
        const uint32_t sBhi = sb + (2 * 2 + slot) * STG_BYTES;
        const uint32_t sBlo = sb + (3 * 2 + slot) * STG_BYTES;
        const uint32_t ro0 = r0 * 80 + c0 * 16, ro1 = r1 * 80 + c0 * 16;
        cp16(sAhi + ro0, Ahi + (size_t)ar0 * K + koff + c0 * 8, v0 ? 16 : 0);
        cp16(sAhi + ro1, Ahi + (size_t)ar1 * K + koff + c0 * 8, v1 ? 16 : 0);
        if (npass >= 2) {
            cp16(sAlo + ro0, Alo + (size_t)ar0 * K + koff + c0 * 8, v0 ? 16 : 0);
            cp16(sAlo + ro1, Alo + (size_t)ar1 * K + koff + c0 * 8, v1 ? 16 : 0);
        }
        cp16(sBhi + ro0, Whi + (size_t)(n0 + r0) * K + koff + c0 * 8, 16);
        cp16(sBhi + ro1, Whi + (size_t)(n0 + r1) * K + koff + c0 * 8, 16);
        if (npass == 3) {
            cp16(sBlo + ro0, Wlo + (size_t)(n0 + r0) * K + koff + c0 * 8, 16);
            cp16(sBlo + ro1, Wlo + (size_t)(n0 + r1) * K + koff + c0 * 8, 16);
        }
    };

    // per-warp ldmatrix local offsets (within a region)
    const uint32_t aLoc = (uint32_t)((wm * 64 + (lane & 15)) * 80 + (lane >> 4) * 16);
    const uint32_t bLoc = (uint32_t)((wn * 32 + (lane & 7) + ((lane >> 4) << 3)) * 80
                                     + ((lane >> 3) & 1) * 16);

    issueKC(0);
    asm volatile("cp.async.commit_group;" ::: "memory");

    for (int kc = 0; kc < KT; kc++) {
        asm volatile("cp.async.wait_group 0;" ::: "memory");
        __syncthreads();
        if (kc + 1 < KT) {
            issueKC(kc + 1);
            asm volatile("cp.async.commit_group;" ::: "memory");
        }
        const int slot = kc & 1;
#pragma unroll
        for (int pass = 0; pass < 3; pass++) {
            if (pass >= npass) break;
            const int aR = (pass == 1) ? 1 : 0;   // Alo on pass 1
            const int bR = (pass == 2) ? 3 : 2;   // Blo on pass 2
            const uint32_t aBase = sb + (uint32_t)(aR * 2 + slot) * STG_BYTES + aLoc;
            const uint32_t bBase = sb + (uint32_t)(bR * 2 + slot) * STG_BYTES + bLoc;
#pragma unroll
            for (int ks = 0; ks < 2; ks++) {
                uint32_t a[4][4], b[2][4];
#pragma unroll
                for (int mi = 0; mi < 4; mi++)
                    ldm_x4(a[mi][0], a[mi][1], a[mi][2], a[mi][3],
                           aBase + mi * 16 * 80 + ks * 32);
#pragma unroll
                for (int nj = 0; nj < 2; nj++)
                    ldm_x4(b[nj][0], b[nj][1], b[nj][2], b[nj][3],
                           bBase + nj * 16 * 80 + ks * 32);
#pragma unroll
                for (int mi = 0; mi < 4; mi++)
#pragma unroll
                    for (int ni = 0; ni < 4; ni++)
                        mma16816(acc[mi][ni], a[mi], &b[ni >> 1][(ni & 1) * 2]);
            }
        }
    }

    const int erow = lane >> 2, ecol = (lane & 3) * 2;
#pragma unroll
    for (int mi = 0; mi < 4; mi++) {
#pragma unroll
        for (int half = 0; half < 2; half++) {
            const int gr = m0 + wm * 64 + mi * 16 + erow + half * 8;
            if (gr >= Nrows) continue;
#pragma unroll
            for (int ni = 0; ni < 4; ni++) {
                const int gc = n0 + wn * 32 + ni * 8 + ecol;
                const int slot = gc / os.cpo;
                const int loc  = gc % os.cpo;
                float ox = acc[mi][ni][half * 2 + 0] + biasf[gc + 0];
                float oy = acc[mi][ni][half * 2 + 1] + biasf[gc + 1];
                if (os.half_mask & (1 << slot)) {
                    __half2 h2 = __floats2half2_rn(ox, oy);
                    *reinterpret_cast<__half2*>((__half*)os.out[slot] + (size_t)gr * os.cpo + loc) = h2;
                } else {
                    float2 o = make_float2(ox, oy);
                    *reinterpret_cast<float2*>((float*)os.out[slot] + (size_t)gr * os.cpo + loc) = o;
                }
            }
        }
    }
}

// ======================= per-node attention aggregation =======================
template<int PER>
__device__ __forceinline__ void vloadf(float* r, const float* __restrict__ p) {
#pragma unroll
    for (int i = 0; i < PER / 2; i++) {
        float2 t = reinterpret_cast<const float2*>(p)[i];
        r[2 * i + 0] = t.x; r[2 * i + 1] = t.y;
    }
}
template<int PER>
__device__ __forceinline__ void vloadh(float* r, const __half* __restrict__ p) {
    if constexpr (PER % 8 == 0) {
#pragma unroll
        for (int i = 0; i < PER / 8; i++) {
            uint4 t = reinterpret_cast<const uint4*>(p)[i];
            const __half2* h = reinterpret_cast<const __half2*>(&t);
#pragma unroll
            for (int j = 0; j < 4; j++) {
                float2 f = __half22float2(h[j]);
                r[i * 8 + j * 2 + 0] = f.x;
                r[i * 8 + j * 2 + 1] = f.y;
            }
        }
    } else {
        float2 f = __half22float2(*reinterpret_cast<const __half2*>(p));
        r[0] = f.x; r[1] = f.y;
    }
}

// One warp per destination node; 4-edge batch with K AND V gathered upfront as
// raw uint4 (MLP=16/lane, no false dependency of v-loads on softmax), lazy
// conversion at use. Online softmax; optional fused fp16 hi/lo split epilogue.
template<int HEADS, int CH, bool RELU, bool SPLIT>
__global__ void __launch_bounds__(256)
gat_agg_kernel(const float* __restrict__ Q, const __half* __restrict__ Kf,
               const __half* __restrict__ V,
               const int* __restrict__ rowptr, const int* __restrict__ srcs,
               float* __restrict__ out,
               __half* __restrict__ hi, __half* __restrict__ lo, int n)
{
    constexpr int NCH = HEADS * CH;
    constexpr int PER = NCH / 32;
    constexpr int RW  = CH / PER;
    const int lane = threadIdx.x & 31;
    const int node = blockIdx.x * (blockDim.x >> 5) + (threadIdx.x >> 5);
    if (node >= n) return;

    const float scale = rsqrtf((float)CH);
    const size_t base = (size_t)node * NCH + lane * PER;

    float qv[PER], acc[PER];
    vloadf<PER>(qv, Q + base);
#pragma unroll
    for (int i = 0; i < PER; i++) acc[i] = 0.f;

    float m = __int_as_float(0xff800000);
    float s = 0.f;

    const int e0 = rowptr[node];
    const int e1 = rowptr[node + 1];
    int e = e0;

    if constexpr (PER % 8 == 0) {
        constexpr int NU = PER / 8;            // uint4s per row slice
        for (; e + 4 <= e1; e += 4) {
            size_t b[4];
#pragma unroll
            for (int j = 0; j < 4; j++)
                b[j] = (size_t)srcs[e + j] * NCH + lane * PER;

            // gather K and V for all 4 edges upfront (raw, no conversion)
            uint4 ku[4][NU], vu[4][NU];
#pragma unroll
            for (int j = 0; j < 4; j++) {
#pragma unroll
                for (int i = 0; i < NU; i++) {
                    ku[j][i] = reinterpret_cast<const uint4*>(Kf + b[j])[i];
                    vu[j][i] = reinterpret_cast<const uint4*>(V  + b[j])[i];
                }
            }

            float p[4];
#pragma unroll
            for (int j = 0; j < 4; j++) {
                float d = 0.f;
#pragma unroll
                for (int i = 0; i < NU; i++) {
                    const __half2* h = reinterpret_cast<const __half2*>(&ku[j][i]);
#pragma unroll
                    for (int t = 0; t < 4; t++) {
                        float2 f = __half22float2(h[t]);
                        d = fmaf(qv[i * 8 + t * 2 + 0], f.x, d);
                        d = fmaf(qv[i * 8 + t * 2 + 1], f.y, d);
                    }
                }
                p[j] = d;
            }
#pragma unroll
            for (int off = RW >> 1; off > 0; off >>= 1) {
#pragma unroll
                for (int j = 0; j < 4; j++)
                    p[j] += __shfl_xor_sync(0xffffffffu, p[j], off);
            }
            float w[4];
            const float a0 = p[0] * scale, a1 = p[1] * scale;
            const float a2 = p[2] * scale, a3 = p[3] * scale;
            const float mn = fmaxf(fmaxf(m, fmaxf(a0, a1)), fmaxf(a2, a3));
            const float corr = __expf(m - mn);
            w[0] = __expf(a0 - mn); w[1] = __expf(a1 - mn);
            w[2] = __expf(a2 - mn); w[3] = __expf(a3 - mn);
            s = s * corr + (w[0] + w[1]) + (w[2] + w[3]);

#pragma unroll
            for (int i = 0; i < PER; i++) acc[i] *= corr;
#pragma unroll
            for (int j = 0; j < 4; j++) {
                const float wj = w[j];
#pragma unroll
                for (int i = 0; i < NU; i++) {
                    const __half2* h = reinterpret_cast<const __half2*>(&vu[j][i]);
#pragma unroll
                    for (int t = 0; t < 4; t++) {
                        float2 f = __half22float2(h[t]);
                        acc[i * 8 + t * 2 + 0] = fmaf(wj, f.x, acc[i * 8 + t * 2 + 0]);
                        acc[i * 8 + t * 2 + 1] = fmaf(wj, f.y, acc[i * 8 + t * 2 + 1]);
                    }
                }
            }
            m = mn;
        }
    }
    for (; e < e1; e++) {
        const int sn = srcs[e];
        const size_t sbx = (size_t)sn * NCH + lane * PER;
        float kv[PER], vv[PER];
        vloadh<PER>(kv, Kf + sbx);
        vloadh<PER>(vv, V  + sbx);
        float part = 0.f;
#pragma unroll
        for (int i = 0; i < PER; i++) part = fmaf(qv[i], kv[i], part);
#pragma unroll
        for (int off = RW >> 1; off > 0; off >>= 1)
            part += __shfl_xor_sync(0xffffffffu, part, off);
        const float alpha = part * scale;
        const float mn = fmaxf(m, alpha);
        const float corr = __expf(m - mn);
        const float w = __expf(alpha - mn);
        s = s * corr + w;
#pragma unroll
        for (int i = 0; i < PER; i++) acc[i] = fmaf(acc[i], corr, w * vv[i]);
        m = mn;
    }

    const float inv = 1.f / (s + 1e-16f);
#pragma unroll
    for (int i = 0; i < PER; i++) {
        float o = out[base + i] + acc[i] * inv;
        if (RELU) o = fmaxf(o, 0.f);
        out[base + i] = o;
        if (SPLIT) {
            __half h = __float2half(o);
            hi[base + i] = h;
            lo[base + i] = __float2half(o - __half2float(h));
        }
    }
}

// ======================= host orchestration =======================
extern "C" void kernel_launch(void* const* d_in, const int* in_sizes, int n_in,
                              void* d_out, int out_size)
{
    const float* x  = (const float*)d_in[0];
    const void*  ei = d_in[1];
    const int N = in_sizes[0] / 128;
    const int E = in_sizes[1] / 2;

    const float* P[24];
    for (int i = 0; i < 24; i++) P[i] = (const float*)d_in[2 + i];

    float *q, *h0, *h1, *biasf;
    __half *kh, *vh;
    __half *ahi, *alo, *whi, *wlo;
    int *rowptr, *cnt, *cur, *srcs;
    cudaGetSymbolAddress((void**)&q,  g_q);
    cudaGetSymbolAddress((void**)&kh, g_kh);
    cudaGetSymbolAddress((void**)&vh, g_vh);
    cudaGetSymbolAddress((void**)&h0, g_h0);
    cudaGetSymbolAddress((void**)&h1, g_h1);
    cudaGetSymbolAddress((void**)&ahi, g_ahi);
    cudaGetSymbolAddress((void**)&alo, g_alo);
    cudaGetSymbolAddress((void**)&whi, g_whi);
    cudaGetSymbolAddress((void**)&wlo, g_wlo);
    cudaGetSymbolAddress((void**)&biasf, g_biasf);
    cudaGetSymbolAddress((void**)&rowptr, g_rowptr);
    cudaGetSymbolAddress((void**)&cnt, g_cnt);
    cudaGetSymbolAddress((void**)&cur, g_cur);
    cudaGetSymbolAddress((void**)&srcs, g_srcs);

    cudaFuncSetAttribute(gemm_mma_kernel, cudaFuncAttributeMaxDynamicSharedMemorySize, SMEM_TOT);

    // side stream + events (created once; never allocates device memory)
    static cudaStream_t s2 = nullptr;
    static cudaEvent_t evA = nullptr, evB = nullptr, evC = nullptr;
    if (!s2) {
        cudaStreamCreateWithFlags(&s2, cudaStreamNonBlocking);
        cudaEventCreateWithFlags(&evA, cudaEventDisableTiming);
        cudaEventCreateWithFlags(&evB, cudaEventDisableTiming);
        cudaEventCreateWithFlags(&evC, cudaEventDisableTiming);
    }

    const int TB = 256;
    float* out = (float*)d_out;

    WTable wt;
    const int Ks[3] = {128, 512, 512};
    const int Ms[3] = {512, 512, 64};
    for (int l = 0; l < 3; l++)
        for (int j = 0; j < 4; j++) {
            wt.d[l * 4 + j].W = P[l * 8 + j * 2];
            wt.d[l * 4 + j].b = P[l * 8 + j * 2 + 1];
            wt.d[l * 4 + j].K = Ks[l];
            wt.d[l * 4 + j].M = Ms[l];
            wt.d[l * 4 + j].layer = l;
            wt.d[l * 4 + j].off = j * Ms[l];
        }

    // layers 0/1 column tiles: q,k,v (0-11) 1-pass, skip (12-15) 3-pass
    const uint32_t LP2_01 = 0x0000u;
    const uint32_t LP1_01 = 0x0FFFu;

    // ---- fork: CSR build + layer-1/2 weight prep on s2 ----
    detect_kernel<<<1, 1>>>((const int*)ei);
    cudaEventRecord(evA, 0);
    cudaStreamWaitEvent(s2, evA, 0);
    zero_int_kernel<<<(N + TB - 1) / TB, TB, 0, s2>>>(cnt, N);
    hist_kernel<<<(E + TB - 1) / TB, TB, 0, s2>>>(ei, cnt, E);
    scan_kernel<<<1, 1024, 0, s2>>>(cnt, rowptr, cur, N);
    scatter_kernel<<<(E + TB - 1) / TB, TB, 0, s2>>>(ei, cur, srcs, E);
    cudaEventRecord(evB, s2);
    prep_weights_kernel<<<dim3(64, 8), TB, 0, s2>>>(wt, 4, whi, wlo, biasf);
    cudaEventRecord(evC, s2);

    // main stream: layer-0 prep + GEMM-0
    prep_weights_kernel<<<dim3(64, 4), TB>>>(wt, 0, whi, wlo, biasf);
    split_act_kernel<<<(N * 128 + TB - 1) / TB, TB>>>(x, ahi, alo, N * 128);

    const int mtiles = (N + 127) / 128;
    OutSpec os0;
    os0.out[0] = q; os0.out[1] = kh; os0.out[2] = vh; os0.out[3] = h0;
    os0.half_mask = 0b0110; os0.cpo = 512;
    gemm_mma_kernel<<<dim3(2048 / 128, mtiles), 256, SMEM_TOT>>>(
        ahi, alo, whi, wlo, biasf, os0, N, 128, LP2_01, LP1_01);

    cudaStreamWaitEvent(0, evB, 0);   // CSR ready before aggregation

    const int aggBlocks = (N + 7) / 8;
    gat_agg_kernel<8, 64, true, true><<<aggBlocks, 256>>>(
        q, kh, vh, rowptr, srcs, h0, ahi, alo, N);

    cudaStreamWaitEvent(0, evC, 0);   // layer-1/2 weights ready

    // ---- layer 1 ----
    OutSpec os1;
    os1.out[0] = q; os1.out[1] = kh; os1.out[2] = vh; os1.out[3] = h1;
    os1.half_mask = 0b0110; os1.cpo = 512;
    gemm_mma_kernel<<<dim3(2048 / 128, mtiles), 256, SMEM_TOT>>>(
        ahi, alo, whi + (size_t)1 * NTOTMAX * KMAX, wlo + (size_t)1 * NTOTMAX * KMAX,
        biasf + NTOTMAX, os1, N, 512, LP2_01, LP1_01);
    gat_agg_kernel<8, 64, true, true><<<aggBlocks, 256>>>(
        q, kh, vh, rowptr, srcs, h1, ahi, alo, N);

    // ---- layer 2 (heads=1, ch=64): full 3-pass everywhere ----
    OutSpec os2;
    os2.out[0] = q; os2.out[1] = kh; os2.out[2] = vh; os2.out[3] = out;
    os2.half_mask = 0b0110; os2.cpo = 64;
    gemm_mma_kernel<<<dim3(256 / 128, mtiles), 256, SMEM_TOT>>>(
        ahi, alo, whi + (size_t)2 * NTOTMAX * KMAX, wlo + (size_t)2 * NTOTMAX * KMAX,
        biasf + 2 * NTOTMAX, os2, N, 512, 0u, 0u);
    gat_agg_kernel<1, 64, false, false><<<aggBlocks, 256>>>(
        q, kh, vh, rowptr, srcs, out, nullptr, nullptr, N);
}